// round 6
// baseline (speedup 1.0000x reference)
#include <cuda_runtime.h>
#include <cuda_bf16.h>
#include <math.h>
#include <stdint.h>

// ---------------- problem constants ----------------
#define Nn   128
#define Vn   128
#define NV   16384          // N*V rows
#define Cdim 256
#define Hdim 512
#define G4H  2048           // 4*H
#define Tn   12
#define NCn  5
#define EHn  256
#define ODn  5
#define PRED_TOTAL (Nn*Tn*Vn*ODn)   // 983040

// SMEM tile geometry: block tile 128(M) x 256(N), k-chunk 32, 80B padded rows
#define KCH      32
#define TROW_B   80
#define OFF_AHI  0
#define OFF_ALO  10240                     // 128*80
#define OFF_BHI  20480
#define OFF_BLO  40960                     // + 256*80
#define STAGE_B  61440
#define SM_TOTAL 133120                    // >= 128*260*4 (LSTM epilogue staging)

// ---------------- device scratch (no allocations allowed) ----------------
__device__ float g_gx[NV * G4H];        // x @ W_ih^T + biases (gate-permuted cols)
__device__ float g_c[NV * Hdim];
__device__ float g_ehpre[NV * EHn];
__device__ float g_psum[128 * EHn];
__device__ float g_psumsq[128 * EHn];
__device__ float g_bnscale[EHn];
__device__ float g_bnshift[EHn];
__device__ float g_ncontrib[Nn * NCn];
__device__ float g_bias2[G4H];          // permuted b_ih + b_hh
__device__ float g_hmean0[Nn * Hdim];   // per-n column sums of h (double buffered)
__device__ float g_hmean1[Nn * Hdim];

// bf16 split operands (value = hi + lo); h is double buffered
__device__ __nv_bfloat16 g_h_hi0[NV * Hdim];
__device__ __nv_bfloat16 g_h_lo0[NV * Hdim];
__device__ __nv_bfloat16 g_h_hi1[NV * Hdim];
__device__ __nv_bfloat16 g_h_lo1[NV * Hdim];
__device__ __nv_bfloat16 g_x_hi[NV * Cdim];
__device__ __nv_bfloat16 g_x_lo[NV * Cdim];
__device__ __nv_bfloat16 g_Wih_hi[G4H * Cdim];   // gate-permuted rows
__device__ __nv_bfloat16 g_Wih_lo[G4H * Cdim];
__device__ __nv_bfloat16 g_Whh_hi[G4H * Hdim];   // gate-permuted rows
__device__ __nv_bfloat16 g_Whh_lo[G4H * Hdim];
__device__ __nv_bfloat16 g_Weh_hi[EHn * Hdim];
__device__ __nv_bfloat16 g_Weh_lo[EHn * Hdim];

// ---------------- mma.sync / ldmatrix / cp.async helpers -------------------
__device__ __forceinline__ uint32_t smem_u32(const void* p) {
    uint32_t a;
    asm("{ .reg .u64 t; cvta.to.shared.u64 t, %1; cvt.u32.u64 %0, t; }" : "=r"(a) : "l"(p));
    return a;
}
__device__ __forceinline__ void ldsm_x4(uint32_t& r0, uint32_t& r1, uint32_t& r2,
                                        uint32_t& r3, uint32_t addr) {
    asm volatile("ldmatrix.sync.aligned.m8n8.x4.shared.b16 {%0,%1,%2,%3}, [%4];"
                 : "=r"(r0), "=r"(r1), "=r"(r2), "=r"(r3) : "r"(addr));
}
__device__ __forceinline__ void mma_bf16(float* c, const uint32_t* a,
                                         uint32_t b0, uint32_t b1) {
    asm volatile(
        "mma.sync.aligned.m16n8k16.row.col.f32.bf16.bf16.f32 "
        "{%0,%1,%2,%3}, {%4,%5,%6,%7}, {%8,%9}, {%0,%1,%2,%3};"
        : "+f"(c[0]), "+f"(c[1]), "+f"(c[2]), "+f"(c[3])
        : "r"(a[0]), "r"(a[1]), "r"(a[2]), "r"(a[3]), "r"(b0), "r"(b1));
}
__device__ __forceinline__ void cp16(uint32_t dst, const void* src) {
    asm volatile("cp.async.cg.shared.global [%0], [%1], 16;" :: "r"(dst), "l"(src));
}
#define CP_COMMIT() asm volatile("cp.async.commit_group;" ::: "memory")
#define CP_WAIT1()  asm volatile("cp.async.wait_group 1;" ::: "memory")
#define CP_WAIT0()  asm volatile("cp.async.wait_group 0;" ::: "memory")

// issue one k-chunk (A: 128 rows, B: 256 rows; hi+lo) into a stage
__device__ __forceinline__ void load_chunk(
    uint32_t st, const __nv_bfloat16* A0, const __nv_bfloat16* A1,
    const __nv_bfloat16* B0, const __nv_bfloat16* B1, int K, int kk, int tid)
{
#pragma unroll
    for (int it = 0; it < 2; it++) {
        int f = tid + (it << 8);          // 0..511
        int r = f >> 2, c = f & 3;
        uint32_t off = (uint32_t)r * TROW_B + (uint32_t)c * 16;
        size_t src = (size_t)r * K + kk + (c << 3);
        cp16(st + OFF_AHI + off, A0 + src);
        cp16(st + OFF_ALO + off, A1 + src);
    }
#pragma unroll
    for (int it = 0; it < 4; it++) {
        int f = tid + (it << 8);          // 0..1023
        int r = f >> 2, c = f & 3;
        uint32_t off = (uint32_t)r * TROW_B + (uint32_t)c * 16;
        size_t src = (size_t)r * K + kk + (c << 3);
        cp16(st + OFF_BHI + off, B0 + src);
        cp16(st + OFF_BLO + off, B1 + src);
    }
}

// ---------------- core GEMM: C[M,Ntot] = (Ahi+Alo) @ (Bhi+Blo)^T ----------
// Block tile 128x256, warp tile 64x64 (2x4 warp grid), k-chunk 32.
// MODE 0: C = acc + bias (gx GEMM)
// MODE 1: fused LSTM epilogue (reads gx w/ biases), writes g_c + next h hi/lo
//         + per-(n, column) h sums into hmean_out.
// MODE 2: C = acc + bias (ehpre) + fused BN column stats into g_psum/g_psumsq.
template<int MODE>
__global__ __launch_bounds__(256, 1) void mma_gemm(
    const __nv_bfloat16* __restrict__ Ahi, const __nv_bfloat16* __restrict__ Alo,
    const __nv_bfloat16* __restrict__ Bhi, const __nv_bfloat16* __restrict__ Blo,
    float* __restrict__ C, const float* __restrict__ bias,
    const float* __restrict__ gx,
    __nv_bfloat16* __restrict__ whi, __nv_bfloat16* __restrict__ wlo,
    float* __restrict__ hmean_out,
    int Ntot, int K)
{
    extern __shared__ char smem[];
    const uint32_t sb = smem_u32(smem);
    const int tid  = threadIdx.x;
    const int wid  = tid >> 5;
    const int lane = tid & 31;
    const int row0 = blockIdx.y << 7;
    const int col0 = blockIdx.x << 8;

    const int am0 = (wid & 1) * 64;    // warp m-offset in tile
    const int bn0 = (wid >> 1) * 64;   // warp n-offset in tile

    const uint32_t lrow = lane & 15, lcol = lane >> 4;
    const int g  = lane >> 2;
    const int t2 = (lane & 3) << 1;

    const __nv_bfloat16* A0 = Ahi + (size_t)row0 * K;
    const __nv_bfloat16* A1 = Alo + (size_t)row0 * K;
    const __nv_bfloat16* B0 = Bhi + (size_t)col0 * K;
    const __nv_bfloat16* B1 = Blo + (size_t)col0 * K;

    float acc[4][8][4];
#pragma unroll
    for (int mf = 0; mf < 4; mf++)
#pragma unroll
        for (int nf = 0; nf < 8; nf++)
#pragma unroll
            for (int e = 0; e < 4; e++) acc[mf][nf][e] = 0.f;

    const int nch = K / KCH;

    load_chunk(sb, A0, A1, B0, B1, K, 0, tid);
    CP_COMMIT();

    for (int kc = 0; kc < nch; kc++) {
        if (kc + 1 < nch) {
            load_chunk(sb + (uint32_t)((kc + 1) & 1) * STAGE_B,
                       A0, A1, B0, B1, K, (kc + 1) * KCH, tid);
            CP_COMMIT();
            CP_WAIT1();
        } else {
            CP_WAIT0();
        }
        __syncthreads();

        const uint32_t st  = sb + (uint32_t)(kc & 1) * STAGE_B;
        const uint32_t sA0 = st + OFF_AHI;
        const uint32_t sA1 = st + OFF_ALO;
        const uint32_t sB0 = st + OFF_BHI;
        const uint32_t sB1 = st + OFF_BLO;

#pragma unroll
        for (int ks = 0; ks < 2; ks++) {
            uint32_t a[4][4], bh[4][4], bl[4][4];
            const uint32_t kb = (uint32_t)(ks * 32 + lcol * 16);
#pragma unroll
            for (int mf = 0; mf < 4; mf++) {
                uint32_t ad = sA0 + (uint32_t)(am0 + mf * 16 + lrow) * TROW_B + kb;
                ldsm_x4(a[mf][0], a[mf][1], a[mf][2], a[mf][3], ad);
            }
#pragma unroll
            for (int ng = 0; ng < 4; ng++) {
                uint32_t roff = (uint32_t)(bn0 + ng * 16 + lrow) * TROW_B + kb;
                ldsm_x4(bh[ng][0], bh[ng][1], bh[ng][2], bh[ng][3], sB0 + roff);
                ldsm_x4(bl[ng][0], bl[ng][1], bl[ng][2], bl[ng][3], sB1 + roff);
            }
            // hi*hi and hi*lo
#pragma unroll
            for (int mf = 0; mf < 4; mf++)
#pragma unroll
                for (int nf = 0; nf < 8; nf++) {
                    int ng = nf >> 1, hf = nf & 1;
                    mma_bf16(acc[mf][nf], a[mf], bh[ng][hf], bh[ng][hf + 2]);
                    mma_bf16(acc[mf][nf], a[mf], bl[ng][hf], bl[ng][hf + 2]);
                }
            // lo*hi (reload A-lo into the same regs)
#pragma unroll
            for (int mf = 0; mf < 4; mf++) {
                uint32_t ad = sA1 + (uint32_t)(am0 + mf * 16 + lrow) * TROW_B + kb;
                ldsm_x4(a[mf][0], a[mf][1], a[mf][2], a[mf][3], ad);
            }
#pragma unroll
            for (int mf = 0; mf < 4; mf++)
#pragma unroll
                for (int nf = 0; nf < 8; nf++) {
                    int ng = nf >> 1, hf = nf & 1;
                    mma_bf16(acc[mf][nf], a[mf], bh[ng][hf], bh[ng][hf + 2]);
                }
        }
        __syncthreads();
    }

    if (MODE != 1) {
        // ---- generic store: C = acc + bias; MODE 2 also collects BN stats ----
        float sc_[8][2], sq_[8][2];
        if (MODE == 2) {
#pragma unroll
            for (int nf = 0; nf < 8; nf++) { sc_[nf][0] = sc_[nf][1] = 0.f;
                                             sq_[nf][0] = sq_[nf][1] = 0.f; }
        }
#pragma unroll
        for (int mf = 0; mf < 4; mf++) {
            int rg = row0 + am0 + mf * 16 + g;
#pragma unroll
            for (int nf = 0; nf < 8; nf++) {
                int cg = col0 + bn0 + nf * 8 + t2;
                float b0 = bias[cg], b1 = bias[cg + 1];
                float v00 = acc[mf][nf][0] + b0, v01 = acc[mf][nf][1] + b1;
                float v10 = acc[mf][nf][2] + b0, v11 = acc[mf][nf][3] + b1;
                *(float2*)(C + (size_t)rg * Ntot + cg) = make_float2(v00, v01);
                *(float2*)(C + (size_t)(rg + 8) * Ntot + cg) = make_float2(v10, v11);
                if (MODE == 2) {
                    sc_[nf][0] += v00 + v10; sq_[nf][0] += v00 * v00 + v10 * v10;
                    sc_[nf][1] += v01 + v11; sq_[nf][1] += v01 * v01 + v11 * v11;
                }
            }
        }
        if (MODE == 2) {
            __syncthreads();
            float2* S2 = (float2*)smem;    // [256 cols][16 slots]
            int slot = ((wid & 1) << 3) + g;
#pragma unroll
            for (int nf = 0; nf < 8; nf++) {
                int cc0 = bn0 + nf * 8 + t2;
                S2[cc0 * 16 + slot]       = make_float2(sc_[nf][0], sq_[nf][0]);
                S2[(cc0 + 1) * 16 + slot] = make_float2(sc_[nf][1], sq_[nf][1]);
            }
            __syncthreads();
            {
                float s = 0.f, q = 0.f;
#pragma unroll
                for (int k2 = 0; k2 < 16; k2++) {
                    float2 v = S2[tid * 16 + k2];
                    s += v.x; q += v.y;
                }
                int rb = row0 >> 7;
                g_psum[rb * EHn + col0 + tid]   = s;
                g_psumsq[rb * EHn + col0 + tid] = q;
            }
        }
    } else {
        // ---- LSTM epilogue: stage acc tile in smem, then elementwise ----
        float* Sf = (float*)smem;   // [128][260]
#pragma unroll
        for (int mf = 0; mf < 4; mf++) {
            int rr = am0 + mf * 16 + g;
#pragma unroll
            for (int nf = 0; nf < 8; nf++) {
                int cc = bn0 + nf * 8 + t2;
                Sf[rr * 260 + cc]           = acc[mf][nf][0];
                Sf[rr * 260 + cc + 1]       = acc[mf][nf][1];
                Sf[(rr + 8) * 260 + cc]     = acc[mf][nf][2];
                Sf[(rr + 8) * 260 + cc + 1] = acc[mf][nf][3];
            }
        }
        __syncthreads();

        const int j0 = col0 >> 2;      // 64 gate-quadruples per tile
        float hsum = 0.f;
        const int qq = tid & 63;       // fixed h-column per thread
#pragma unroll
        for (int it = 0; it < 32; it++) {
            int item = tid + (it << 8);            // 0..8191
            int r = item >> 6;                     // 0..127
            int grow = row0 + r;
            float4 gv  = *(const float4*)(Sf + r * 260 + (qq << 2));
            float4 gxv = *(const float4*)(gx + (size_t)grow * G4H + col0 + (qq << 2));
            float gi = gv.x + gxv.x;
            float gf = gv.y + gxv.y;
            float gg = gv.z + gxv.z;
            float go = gv.w + gxv.w;
            float si = 1.f / (1.f + expf(-gi));
            float sf = 1.f / (1.f + expf(-gf));
            float so = 1.f / (1.f + expf(-go));
            size_t idx = (size_t)grow * Hdim + j0 + qq;
            float cn = sf * g_c[idx] + si * tanhf(gg);
            g_c[idx] = cn;
            float hv = so * tanhf(cn);
            hsum += hv;
            __nv_bfloat16 hb = __float2bfloat16(hv);
            whi[idx] = hb;
            wlo[idx] = __float2bfloat16(hv - __bfloat162float(hb));
        }
        // per-(n, column) h sums: this CTA's 128 rows are exactly one n
        __syncthreads();
        float* Sm = (float*)smem;      // [64 q][4 slots]
        Sm[qq * 4 + (tid >> 6)] = hsum;
        __syncthreads();
        if (tid < 64) {
            float s = Sm[tid * 4] + Sm[tid * 4 + 1] + Sm[tid * 4 + 2] + Sm[tid * 4 + 3];
            hmean_out[(row0 >> 7) * Hdim + j0 + tid] = s;   // raw sum; oc scales
        }
    }
}

// ---------------- splits / init -------------------------------------------
__global__ __launch_bounds__(256) void split_mat(
    const float* __restrict__ src, __nv_bfloat16* __restrict__ hi,
    __nv_bfloat16* __restrict__ lo, int n)
{
    int i = blockIdx.x * blockDim.x + threadIdx.x;
    if (i < n) {
        float v = src[i];
        __nv_bfloat16 h = __float2bfloat16(v);
        hi[i] = h;
        lo[i] = __float2bfloat16(v - __bfloat162float(h));
    }
}

// gate-permuted split for W [2048][K]: new_row = (r%512)*4 + r/512
__global__ __launch_bounds__(256) void split_perm(
    const float* __restrict__ src, __nv_bfloat16* __restrict__ hi,
    __nv_bfloat16* __restrict__ lo, int K)
{
    int i = blockIdx.x * blockDim.x + threadIdx.x;   // over 2048*K
    int r = i / K, c = i - r * K;
    int nr = ((r & 511) << 2) + (r >> 9);
    float v = src[i];
    __nv_bfloat16 h = __float2bfloat16(v);
    hi[nr * K + c] = h;
    lo[nr * K + c] = __float2bfloat16(v - __bfloat162float(h));
}

__global__ void bias_combine(const float* __restrict__ b_ih,
                             const float* __restrict__ b_hh)
{
    int i = blockIdx.x * blockDim.x + threadIdx.x;   // < 2048
    int p = ((i & 511) << 2) + (i >> 9);
    g_bias2[p] = b_ih[i] + b_hh[i];
}

__global__ void init_state(const float* __restrict__ h0, const float* __restrict__ c0)
{
    int i = blockIdx.x * blockDim.x + threadIdx.x;   // NV*Hdim grid
    float hv = h0[i];
    g_c[i] = c0[i];
    __nv_bfloat16 hb = __float2bfloat16(hv);
    g_h_hi0[i] = hb;
    g_h_lo0[i] = __float2bfloat16(hv - __bfloat162float(hb));
}

// ---------------- finalize: eh BN params + full ec branch ------------------
__global__ __launch_bounds__(256) void finalize_step(
    const float* __restrict__ gamma_eh, const float* __restrict__ beta_eh,
    const float* __restrict__ oneh_t,
    const float* __restrict__ W_ec, const float* __restrict__ b_ec,
    const float* __restrict__ gamma_ec, const float* __restrict__ beta_ec,
    const float* __restrict__ W_out)
{
    __shared__ float s_cnt[NCn];
    __shared__ int   s_cls[Nn];
    __shared__ float s_ec[NCn][EHn];
    __shared__ float s_contrib[NCn * ODn];

    int tid = threadIdx.x;
    {
        float s = 0.f, sq = 0.f;
        for (int b = 0; b < 128; b++) {
            s  += g_psum[b * EHn + tid];
            sq += g_psumsq[b * EHn + tid];
        }
        float m   = s * (1.f / (float)NV);
        float var = sq * (1.f / (float)NV) - m * m;
        float sc  = gamma_eh[tid] * rsqrtf(var + 1e-5f);
        g_bnscale[tid] = sc;
        g_bnshift[tid] = beta_eh[tid] - sc * m;
    }
    if (tid < NCn) {
        float cv = 0.f;
        for (int n = 0; n < Nn; n++) cv += oneh_t[n * NCn + tid];
        s_cnt[tid] = cv;
    }
    if (tid < Nn) {
        const float* r = oneh_t + tid * NCn;
        int cl = 0; float best = r[0];
#pragma unroll
        for (int k = 1; k < NCn; k++) if (r[k] > best) { best = r[k]; cl = k; }
        s_cls[tid] = cl;
    }
    __syncthreads();
    {
        int j = tid;
        float pre[NCn];
        float m = 0.f, sq = 0.f;
#pragma unroll
        for (int cl = 0; cl < NCn; cl++) {
            pre[cl] = W_ec[j * NCn + cl] + b_ec[j];
            float w = s_cnt[cl] * (1.f / (float)Nn);
            m  += w * pre[cl];
            sq += w * pre[cl] * pre[cl];
        }
        float var = sq - m * m;
        float sc  = gamma_ec[j] * rsqrtf(var + 1e-5f);
        float sh  = beta_ec[j] - sc * m;
#pragma unroll
        for (int cl = 0; cl < NCn; cl++)
            s_ec[cl][j] = fmaxf(sc * pre[cl] + sh, 0.f);
    }
    __syncthreads();
    int warp = tid >> 5, lane = tid & 31;
    for (int p = warp; p < NCn * ODn; p += 8) {
        int cl = p / ODn, od = p % ODn;
        float a = 0.f;
#pragma unroll
        for (int u = 0; u < 8; u++) {
            int j = lane + (u << 5);
            a = fmaf(s_ec[cl][j], W_out[od * (EHn + EHn) + EHn + j], a);
        }
        for (int off = 16; off; off >>= 1) a += __shfl_xor_sync(0xffffffffu, a, off);
        if (lane == 0) s_contrib[p] = a;
    }
    __syncthreads();
    if (tid < Nn) {
        int cl = s_cls[tid];
#pragma unroll
        for (int od = 0; od < ODn; od++)
            g_ncontrib[tid * ODn + od] = s_contrib[cl * ODn + od];
    }
}

// ---------------- op: bn+relu(eh) . W_out[:, :256] + ec + b_out + act ------
__global__ __launch_bounds__(256) void op_kernel(
    const float* __restrict__ W_out, const float* __restrict__ b_out,
    float* __restrict__ out, int t)
{
    int warp = threadIdx.x >> 5, lane = threadIdx.x & 31;
    int row  = (blockIdx.x << 3) + warp;
    const float* er = g_ehpre + (size_t)row * EHn;

    float a0 = 0.f, a1 = 0.f, a2 = 0.f, a3 = 0.f, a4 = 0.f;
#pragma unroll
    for (int u = 0; u < 8; u++) {
        int j = lane + (u << 5);
        float xv = fmaxf(fmaf(g_bnscale[j], er[j], g_bnshift[j]), 0.f);
        a0 = fmaf(xv, W_out[j],            a0);
        a1 = fmaf(xv, W_out[512  + j],     a1);
        a2 = fmaf(xv, W_out[1024 + j],     a2);
        a3 = fmaf(xv, W_out[1536 + j],     a3);
        a4 = fmaf(xv, W_out[2048 + j],     a4);
    }
    for (int off = 16; off; off >>= 1) {
        a0 += __shfl_xor_sync(0xffffffffu, a0, off);
        a1 += __shfl_xor_sync(0xffffffffu, a1, off);
        a2 += __shfl_xor_sync(0xffffffffu, a2, off);
        a3 += __shfl_xor_sync(0xffffffffu, a3, off);
        a4 += __shfl_xor_sync(0xffffffffu, a4, off);
    }
    if (lane < ODn) {
        int n = row >> 7, v = row & 127;
        float a = (lane == 0) ? a0 : (lane == 1) ? a1 : (lane == 2) ? a2
                : (lane == 3) ? a3 : a4;
        a += g_ncontrib[n * ODn + lane] + b_out[lane];
        if (lane == 2 || lane == 3) a = expf(a);
        else if (lane == 4)         a = tanhf(a);
        out[(((size_t)n * Tn + t) * Vn + v) * ODn + lane] = a;
    }
}

// ---------------- oc: (sum_V h / V) @ W_cls^T + b_cls ----------------------
__global__ __launch_bounds__(192) void oc_kernel(
    const float* __restrict__ hmean, const float* __restrict__ W_cls,
    const float* __restrict__ b_cls, float* __restrict__ out, int t)
{
    int n = blockIdx.x;
    int warp = threadIdx.x >> 5, lane = threadIdx.x & 31;
    if (warp < ODn) {
        float a = 0.f;
#pragma unroll
        for (int u = 0; u < 16; u++) {
            int k = lane + (u << 5);
            a = fmaf(hmean[n * Hdim + k], W_cls[warp * Hdim + k], a);
        }
        for (int off = 16; off; off >>= 1) a += __shfl_xor_sync(0xffffffffu, a, off);
        if (lane == 0)
            out[PRED_TOTAL + ((size_t)t * Nn + n) * ODn + warp] =
                a * (1.f / (float)Vn) + b_cls[warp];
    }
}

// ---------------- streams/events (created at load, before harness checkpoints)
struct StreamRes {
    cudaStream_t s2 = nullptr;
    cudaEvent_t  eG[2] = {nullptr, nullptr};
    cudaEvent_t  eH[2] = {nullptr, nullptr};
    bool ok = false;
    StreamRes() {
        if (cudaStreamCreateWithFlags(&s2, cudaStreamNonBlocking) != cudaSuccess) return;
        for (int i = 0; i < 2; i++) {
            if (cudaEventCreateWithFlags(&eG[i], cudaEventDisableTiming) != cudaSuccess) return;
            if (cudaEventCreateWithFlags(&eH[i], cudaEventDisableTiming) != cudaSuccess) return;
        }
        ok = true;
    }
};
static StreamRes g_sr;

// ---------------- host launcher --------------------------------------------
extern "C" void kernel_launch(void* const* d_in, const int* in_sizes, int n_in,
                              void* d_out, int out_size)
{
    const float* x     = (const float*)d_in[0];
    const float* h0    = (const float*)d_in[1];
    const float* c0    = (const float*)d_in[2];
    const float* oneh  = (const float*)d_in[3];
    const float* W_ih  = (const float*)d_in[4];
    const float* W_hh  = (const float*)d_in[5];
    const float* b_ih  = (const float*)d_in[6];
    const float* b_hh  = (const float*)d_in[7];
    const float* W_cls = (const float*)d_in[8];
    const float* b_cls = (const float*)d_in[9];
    const float* W_eh  = (const float*)d_in[10];
    const float* b_eh  = (const float*)d_in[11];
    const float* ga_eh = (const float*)d_in[12];
    const float* be_eh = (const float*)d_in[13];
    const float* W_ec  = (const float*)d_in[14];
    const float* b_ec  = (const float*)d_in[15];
    const float* ga_ec = (const float*)d_in[16];
    const float* be_ec = (const float*)d_in[17];
    const float* W_out = (const float*)d_in[18];
    const float* b_out = (const float*)d_in[19];
    float* out = (float*)d_out;

    cudaFuncSetAttribute(mma_gemm<0>, cudaFuncAttributeMaxDynamicSharedMemorySize, SM_TOTAL);
    cudaFuncSetAttribute(mma_gemm<1>, cudaFuncAttributeMaxDynamicSharedMemorySize, SM_TOTAL);
    cudaFuncSetAttribute(mma_gemm<2>, cudaFuncAttributeMaxDynamicSharedMemorySize, SM_TOTAL);

    float *gx, *ehpre, *bias2;
    float *hmean[2];
    __nv_bfloat16 *xh, *xl, *Wihh, *Wihl, *Whhh, *Whhl, *Wehh, *Wehl;
    __nv_bfloat16 *hbuf_hi[2], *hbuf_lo[2];
    cudaGetSymbolAddress((void**)&gx,    g_gx);
    cudaGetSymbolAddress((void**)&ehpre, g_ehpre);
    cudaGetSymbolAddress((void**)&bias2, g_bias2);
    cudaGetSymbolAddress((void**)&xh,    g_x_hi);
    cudaGetSymbolAddress((void**)&xl,    g_x_lo);
    cudaGetSymbolAddress((void**)&Wihh,  g_Wih_hi);
    cudaGetSymbolAddress((void**)&Wihl,  g_Wih_lo);
    cudaGetSymbolAddress((void**)&Whhh,  g_Whh_hi);
    cudaGetSymbolAddress((void**)&Whhl,  g_Whh_lo);
    cudaGetSymbolAddress((void**)&Wehh,  g_Weh_hi);
    cudaGetSymbolAddress((void**)&Wehl,  g_Weh_lo);
    cudaGetSymbolAddress((void**)&hbuf_hi[0], g_h_hi0);
    cudaGetSymbolAddress((void**)&hbuf_lo[0], g_h_lo0);
    cudaGetSymbolAddress((void**)&hbuf_hi[1], g_h_hi1);
    cudaGetSymbolAddress((void**)&hbuf_lo[1], g_h_lo1);
    cudaGetSymbolAddress((void**)&hmean[0], g_hmean0);
    cudaGetSymbolAddress((void**)&hmean[1], g_hmean1);

    // init + operand splits (stream 0)
    init_state<<<(NV * Hdim) / 256, 256>>>(h0, c0);
    split_mat<<<(NV * Cdim) / 256, 256>>>(x, xh, xl, NV * Cdim);
    split_perm<<<(G4H * Cdim) / 256, 256>>>(W_ih, Wihh, Wihl, Cdim);
    split_perm<<<(G4H * Hdim) / 256, 256>>>(W_hh, Whhh, Whhl, Hdim);
    split_mat<<<(EHn * Hdim) / 256, 256>>>(W_eh, Wehh, Wehl, EHn * Hdim);
    bias_combine<<<G4H / 256, 256>>>(b_ih, b_hh);

    // gx = x @ Wih_perm^T + (b_ih + b_hh)_perm   (step-invariant)
    mma_gemm<0><<<dim3(G4H / 256, NV / 128), 256, SM_TOTAL>>>(
        xh, xl, Wihh, Wihl, gx, bias2, nullptr, nullptr, nullptr, nullptr,
        G4H, Cdim);

    const bool dual = g_sr.ok;
    cudaStream_t sH = dual ? g_sr.s2 : (cudaStream_t)0;

    for (int t = 0; t < Tn; t++) {
        const int rb = t & 1, wb = rb ^ 1;

        if (dual && t >= 2) cudaStreamWaitEvent(0, g_sr.eH[t & 1], 0);

        // fused: gates = gx + h @ Whh_perm^T -> LSTM update -> h,c (+ split, hmean)
        mma_gemm<1><<<dim3(G4H / 256, NV / 128), 256, SM_TOTAL>>>(
            hbuf_hi[rb], hbuf_lo[rb], Whhh, Whhl, nullptr, nullptr, gx,
            hbuf_hi[wb], hbuf_lo[wb], hmean[wb], G4H, Hdim);

        if (dual) {
            cudaEventRecord(g_sr.eG[t & 1], 0);
            cudaStreamWaitEvent(sH, g_sr.eG[t & 1], 0);
        }

        // head chain (second stream when available)
        oc_kernel<<<Nn, 192, 0, sH>>>(hmean[wb], W_cls, b_cls, out, t);
        mma_gemm<2><<<dim3(EHn / 256, NV / 128), 256, SM_TOTAL, sH>>>(
            hbuf_hi[wb], hbuf_lo[wb], Wehh, Wehl, ehpre, b_eh,
            nullptr, nullptr, nullptr, nullptr, EHn, Hdim);
        finalize_step<<<1, 256, 0, sH>>>(ga_eh, be_eh, oneh + (size_t)t * Nn * NCn,
                                         W_ec, b_ec, ga_ec, be_ec, W_out);
        op_kernel<<<NV / 8, 256, 0, sH>>>(W_out, b_out, out, t);

        if (dual) cudaEventRecord(g_sr.eH[t & 1], sH);
    }

    if (dual) {
        cudaStreamWaitEvent(0, g_sr.eH[0], 0);
        cudaStreamWaitEvent(0, g_sr.eH[1], 0);
    }
}

// round 7
// speedup vs baseline: 1.1500x; 1.1500x over previous
#include <cuda_runtime.h>
#include <cuda_bf16.h>
#include <math.h>
#include <stdint.h>

// ---------------- problem constants ----------------
#define Nn   128
#define Vn   128
#define NV   16384          // N*V rows
#define Cdim 256
#define Hdim 512
#define G4H  2048           // 4*H
#define Tn   12
#define NCn  5
#define EHn  256
#define ODn  5
#define PRED_TOTAL (Nn*Tn*Vn*ODn)   // 983040

// SMEM tile geometry: 4-stage pipeline, k-chunk 16, 48B padded rows
#define KCH      16
#define TROW_B   48
#define TILE_B   (128 * TROW_B)           // 6144 bytes
#define OFF_AHI  0
#define OFF_ALO  6144
#define OFF_BHI  12288
#define OFF_BLO  18432
#define STAGE_B  24576
#define NSTAGE   4
#define SM_TOTAL (NSTAGE * STAGE_B)       // 98304 (>= 128*132*4 + hmean scratch)

// ---------------- device scratch (no allocations allowed) ----------------
__device__ float g_gx[NV * G4H];        // x @ W_ih^T + biases (gate-permuted cols)
__device__ float g_c[NV * Hdim];
__device__ float g_ehpre[NV * EHn];
__device__ float g_psum[128 * EHn];
__device__ float g_psumsq[128 * EHn];
__device__ float g_bnscale[EHn];
__device__ float g_bnshift[EHn];
__device__ float g_ncontrib[Nn * NCn];
__device__ float g_bias2[G4H];          // permuted b_ih + b_hh
__device__ float g_hmean0[Nn * Hdim];   // per-n column sums of h (double buffered)
__device__ float g_hmean1[Nn * Hdim];

// bf16 split operands (value = hi + lo); h is double buffered
__device__ __nv_bfloat16 g_h_hi0[NV * Hdim];
__device__ __nv_bfloat16 g_h_lo0[NV * Hdim];
__device__ __nv_bfloat16 g_h_hi1[NV * Hdim];
__device__ __nv_bfloat16 g_h_lo1[NV * Hdim];
__device__ __nv_bfloat16 g_x_hi[NV * Cdim];
__device__ __nv_bfloat16 g_x_lo[NV * Cdim];
__device__ __nv_bfloat16 g_Wih_hi[G4H * Cdim];   // gate-permuted rows
__device__ __nv_bfloat16 g_Wih_lo[G4H * Cdim];
__device__ __nv_bfloat16 g_Whh_hi[G4H * Hdim];   // gate-permuted rows
__device__ __nv_bfloat16 g_Whh_lo[G4H * Hdim];
__device__ __nv_bfloat16 g_Weh_hi[EHn * Hdim];
__device__ __nv_bfloat16 g_Weh_lo[EHn * Hdim];

// ---------------- mma.sync / ldmatrix / cp.async helpers -------------------
__device__ __forceinline__ uint32_t smem_u32(const void* p) {
    uint32_t a;
    asm("{ .reg .u64 t; cvta.to.shared.u64 t, %1; cvt.u32.u64 %0, t; }" : "=r"(a) : "l"(p));
    return a;
}
__device__ __forceinline__ void ldsm_x4(uint32_t& r0, uint32_t& r1, uint32_t& r2,
                                        uint32_t& r3, uint32_t addr) {
    asm volatile("ldmatrix.sync.aligned.m8n8.x4.shared.b16 {%0,%1,%2,%3}, [%4];"
                 : "=r"(r0), "=r"(r1), "=r"(r2), "=r"(r3) : "r"(addr));
}
__device__ __forceinline__ void mma_bf16(float* c, const uint32_t* a,
                                         uint32_t b0, uint32_t b1) {
    asm volatile(
        "mma.sync.aligned.m16n8k16.row.col.f32.bf16.bf16.f32 "
        "{%0,%1,%2,%3}, {%4,%5,%6,%7}, {%8,%9}, {%0,%1,%2,%3};"
        : "+f"(c[0]), "+f"(c[1]), "+f"(c[2]), "+f"(c[3])
        : "r"(a[0]), "r"(a[1]), "r"(a[2]), "r"(a[3]), "r"(b0), "r"(b1));
}
__device__ __forceinline__ void cp16(uint32_t dst, const void* src) {
    asm volatile("cp.async.cg.shared.global [%0], [%1], 16;" :: "r"(dst), "l"(src));
}
#define CP_COMMIT() asm volatile("cp.async.commit_group;" ::: "memory")
#define CP_WAIT2()  asm volatile("cp.async.wait_group 2;" ::: "memory")
#define CP_WAIT1()  asm volatile("cp.async.wait_group 1;" ::: "memory")
#define CP_WAIT0()  asm volatile("cp.async.wait_group 0;" ::: "memory")

// issue one k-chunk's 4 tiles (A-hi, A-lo, B-hi, B-lo); 1 cp16/thread/tile
__device__ __forceinline__ void load_chunk(
    uint32_t st, const __nv_bfloat16* A0, const __nv_bfloat16* A1,
    const __nv_bfloat16* B0, const __nv_bfloat16* B1, int K, int kk, int tid)
{
    int r = tid >> 1, c = tid & 1;
    uint32_t off = (uint32_t)r * TROW_B + (uint32_t)c * 16;
    size_t src = (size_t)r * K + kk + (c << 3);
    cp16(st + OFF_AHI + off, A0 + src);
    cp16(st + OFF_ALO + off, A1 + src);
    cp16(st + OFF_BHI + off, B0 + src);
    cp16(st + OFF_BLO + off, B1 + src);
}

// ---------------- core GEMM: C[M,Ntot] = (Ahi+Alo) @ (Bhi+Blo)^T ----------
// Block tile 128x128, warp tile 64x32 (2x4 warp grid), 4-stage k16 pipeline.
// MODE 0: C = acc + bias (gx GEMM)
// MODE 1: fused LSTM epilogue (reads gx w/ biases), writes g_c + next h hi/lo
//         + per-(n, column) h sums into hmean_out.
// MODE 2: C = acc + bias (ehpre) + fused BN column stats into g_psum/g_psumsq.
template<int MODE>
__global__ __launch_bounds__(256, 2) void mma_gemm(
    const __nv_bfloat16* __restrict__ Ahi, const __nv_bfloat16* __restrict__ Alo,
    const __nv_bfloat16* __restrict__ Bhi, const __nv_bfloat16* __restrict__ Blo,
    float* __restrict__ C, const float* __restrict__ bias,
    const float* __restrict__ gx,
    __nv_bfloat16* __restrict__ whi, __nv_bfloat16* __restrict__ wlo,
    float* __restrict__ hmean_out,
    int Ntot, int K)
{
    extern __shared__ char smem[];
    const uint32_t sb = smem_u32(smem);
    const int tid  = threadIdx.x;
    const int wid  = tid >> 5;
    const int lane = tid & 31;
    const int row0 = blockIdx.y << 7;
    const int col0 = blockIdx.x << 7;

    const int am0 = (wid & 1) * 64;    // warp m-offset in tile
    const int bn0 = (wid >> 1) * 32;   // warp n-offset in tile

    const uint32_t lrow = lane & 15, lcol = lane >> 4;
    const int g  = lane >> 2;
    const int t2 = (lane & 3) << 1;

    const __nv_bfloat16* A0 = Ahi + (size_t)row0 * K;
    const __nv_bfloat16* A1 = Alo + (size_t)row0 * K;
    const __nv_bfloat16* B0 = Bhi + (size_t)col0 * K;
    const __nv_bfloat16* B1 = Blo + (size_t)col0 * K;

    float acc[4][4][4];
#pragma unroll
    for (int mf = 0; mf < 4; mf++)
#pragma unroll
        for (int nf = 0; nf < 4; nf++)
#pragma unroll
            for (int e = 0; e < 4; e++) acc[mf][nf][e] = 0.f;

    const int nch = K / KCH;            // 16 (K=256) or 32 (K=512), both %4==0

    // prologue: fill 3 stages
#pragma unroll
    for (int p = 0; p < NSTAGE - 1; p++) {
        load_chunk(sb + (uint32_t)p * STAGE_B, A0, A1, B0, B1, K, p * KCH, tid);
        CP_COMMIT();
    }

    for (int kc = 0; kc < nch; kc++) {
        const int rem = nch - 1 - kc;
        if (rem >= 2)      CP_WAIT2();
        else if (rem == 1) CP_WAIT1();
        else               CP_WAIT0();
        __syncthreads();

        if (kc + NSTAGE - 1 < nch) {
            load_chunk(sb + (uint32_t)((kc + NSTAGE - 1) & (NSTAGE - 1)) * STAGE_B,
                       A0, A1, B0, B1, K, (kc + NSTAGE - 1) * KCH, tid);
            CP_COMMIT();
        }

        const uint32_t st  = sb + (uint32_t)(kc & (NSTAGE - 1)) * STAGE_B;
        const uint32_t sA0 = st + OFF_AHI;
        const uint32_t sA1 = st + OFF_ALO;
        const uint32_t sB0 = st + OFF_BHI;
        const uint32_t sB1 = st + OFF_BLO;

        uint32_t a[4][4], bh[2][4], bl[2][4];
        const uint32_t kb = lcol * 16;
#pragma unroll
        for (int mf = 0; mf < 4; mf++) {
            uint32_t ad = sA0 + (uint32_t)(am0 + mf * 16 + lrow) * TROW_B + kb;
            ldsm_x4(a[mf][0], a[mf][1], a[mf][2], a[mf][3], ad);
        }
#pragma unroll
        for (int ng = 0; ng < 2; ng++) {
            uint32_t roff = (uint32_t)(bn0 + ng * 16 + lrow) * TROW_B + kb;
            ldsm_x4(bh[ng][0], bh[ng][1], bh[ng][2], bh[ng][3], sB0 + roff);
            ldsm_x4(bl[ng][0], bl[ng][1], bl[ng][2], bl[ng][3], sB1 + roff);
        }
        // hi*hi and hi*lo
#pragma unroll
        for (int mf = 0; mf < 4; mf++)
#pragma unroll
            for (int nf = 0; nf < 4; nf++) {
                int ng = nf >> 1, hf = nf & 1;
                mma_bf16(acc[mf][nf], a[mf], bh[ng][hf], bh[ng][hf + 2]);
                mma_bf16(acc[mf][nf], a[mf], bl[ng][hf], bl[ng][hf + 2]);
            }
        // lo*hi (reload A-lo into the same regs)
#pragma unroll
        for (int mf = 0; mf < 4; mf++) {
            uint32_t ad = sA1 + (uint32_t)(am0 + mf * 16 + lrow) * TROW_B + kb;
            ldsm_x4(a[mf][0], a[mf][1], a[mf][2], a[mf][3], ad);
        }
#pragma unroll
        for (int mf = 0; mf < 4; mf++)
#pragma unroll
            for (int nf = 0; nf < 4; nf++) {
                int ng = nf >> 1, hf = nf & 1;
                mma_bf16(acc[mf][nf], a[mf], bh[ng][hf], bh[ng][hf + 2]);
            }
    }
    // NOTE: nch % 4 == 0, so the last computed stage is stage 3
    // (offset 73728..98304); epilogue smem below only touches [0, 68608).

    if (MODE != 1) {
        // ---- generic store: C = acc + bias; MODE 2 also collects BN stats ----
        float sc_[4][2], sq_[4][2];
        if (MODE == 2) {
#pragma unroll
            for (int nf = 0; nf < 4; nf++) { sc_[nf][0] = sc_[nf][1] = 0.f;
                                             sq_[nf][0] = sq_[nf][1] = 0.f; }
        }
#pragma unroll
        for (int mf = 0; mf < 4; mf++) {
            int rg = row0 + am0 + mf * 16 + g;
#pragma unroll
            for (int nf = 0; nf < 4; nf++) {
                int cg = col0 + bn0 + nf * 8 + t2;
                float b0 = bias[cg], b1 = bias[cg + 1];
                float v00 = acc[mf][nf][0] + b0, v01 = acc[mf][nf][1] + b1;
                float v10 = acc[mf][nf][2] + b0, v11 = acc[mf][nf][3] + b1;
                *(float2*)(C + (size_t)rg * Ntot + cg) = make_float2(v00, v01);
                *(float2*)(C + (size_t)(rg + 8) * Ntot + cg) = make_float2(v10, v11);
                if (MODE == 2) {
                    sc_[nf][0] += v00 + v10; sq_[nf][0] += v00 * v00 + v10 * v10;
                    sc_[nf][1] += v01 + v11; sq_[nf][1] += v01 * v01 + v11 * v11;
                }
            }
        }
        if (MODE == 2) {
            float2* S2 = (float2*)smem;    // [128 cols][16 slots] = 16KB
            int slot = ((wid & 1) << 3) + g;
#pragma unroll
            for (int nf = 0; nf < 4; nf++) {
                int cc0 = bn0 + nf * 8 + t2;
                S2[cc0 * 16 + slot]       = make_float2(sc_[nf][0], sq_[nf][0]);
                S2[(cc0 + 1) * 16 + slot] = make_float2(sc_[nf][1], sq_[nf][1]);
            }
            __syncthreads();
            if (tid < 128) {
                float s = 0.f, q = 0.f;
#pragma unroll
                for (int k2 = 0; k2 < 16; k2++) {
                    float2 v = S2[tid * 16 + k2];
                    s += v.x; q += v.y;
                }
                int rb = row0 >> 7;
                g_psum[rb * EHn + col0 + tid]   = s;
                g_psumsq[rb * EHn + col0 + tid] = q;
            }
        }
    } else {
        // ---- LSTM epilogue: stage acc tile in smem, then elementwise ----
        float* Sf = (float*)smem;   // [128][132] = 67584 B
#pragma unroll
        for (int mf = 0; mf < 4; mf++) {
            int rr = am0 + mf * 16 + g;
#pragma unroll
            for (int nf = 0; nf < 4; nf++) {
                int cc = bn0 + nf * 8 + t2;
                Sf[rr * 132 + cc]           = acc[mf][nf][0];
                Sf[rr * 132 + cc + 1]       = acc[mf][nf][1];
                Sf[(rr + 8) * 132 + cc]     = acc[mf][nf][2];
                Sf[(rr + 8) * 132 + cc + 1] = acc[mf][nf][3];
            }
        }
        __syncthreads();

        const int j0 = col0 >> 2;      // 32 gate-quadruples per tile
        float hsum = 0.f;
#pragma unroll
        for (int it = 0; it < 16; it++) {
            int item = tid + (it << 8);            // 0..4095
            int r = item >> 5, q = item & 31;
            int grow = row0 + r;
            float4 gv  = *(const float4*)(Sf + r * 132 + (q << 2));
            float4 gxv = *(const float4*)(gx + (size_t)grow * G4H + col0 + (q << 2));
            float gi = gv.x + gxv.x;
            float gf = gv.y + gxv.y;
            float gg = gv.z + gxv.z;
            float go = gv.w + gxv.w;
            float si = 1.f / (1.f + expf(-gi));
            float sf = 1.f / (1.f + expf(-gf));
            float so = 1.f / (1.f + expf(-go));
            size_t idx = (size_t)grow * Hdim + j0 + q;
            float cn = sf * g_c[idx] + si * tanhf(gg);
            g_c[idx] = cn;
            float hv = so * tanhf(cn);
            hsum += hv;
            __nv_bfloat16 hb = __float2bfloat16(hv);
            whi[idx] = hb;
            wlo[idx] = __float2bfloat16(hv - __bfloat162float(hb));
        }
        // per-(n, column) h sums: this CTA's 128 rows are exactly one n
        float* Sm = (float*)(smem + 67584);   // [32 q][8 warp-slots] = 1KB
        Sm[(tid & 31) * 8 + (tid >> 5)] = hsum;
        __syncthreads();
        if (tid < 32) {
            float s = 0.f;
#pragma unroll
            for (int k2 = 0; k2 < 8; k2++) s += Sm[tid * 8 + k2];
            hmean_out[(row0 >> 7) * Hdim + j0 + tid] = s;   // raw sum; oc scales
        }
    }
}

// ---------------- splits / init -------------------------------------------
__global__ __launch_bounds__(256) void split_mat(
    const float* __restrict__ src, __nv_bfloat16* __restrict__ hi,
    __nv_bfloat16* __restrict__ lo, int n)
{
    int i = blockIdx.x * blockDim.x + threadIdx.x;
    if (i < n) {
        float v = src[i];
        __nv_bfloat16 h = __float2bfloat16(v);
        hi[i] = h;
        lo[i] = __float2bfloat16(v - __bfloat162float(h));
    }
}

// gate-permuted split for W [2048][K]: new_row = (r%512)*4 + r/512
__global__ __launch_bounds__(256) void split_perm(
    const float* __restrict__ src, __nv_bfloat16* __restrict__ hi,
    __nv_bfloat16* __restrict__ lo, int K)
{
    int i = blockIdx.x * blockDim.x + threadIdx.x;   // over 2048*K
    int r = i / K, c = i - r * K;
    int nr = ((r & 511) << 2) + (r >> 9);
    float v = src[i];
    __nv_bfloat16 h = __float2bfloat16(v);
    hi[nr * K + c] = h;
    lo[nr * K + c] = __float2bfloat16(v - __bfloat162float(h));
}

__global__ void bias_combine(const float* __restrict__ b_ih,
                             const float* __restrict__ b_hh)
{
    int i = blockIdx.x * blockDim.x + threadIdx.x;   // < 2048
    int p = ((i & 511) << 2) + (i >> 9);
    g_bias2[p] = b_ih[i] + b_hh[i];
}

__global__ void init_state(const float* __restrict__ h0, const float* __restrict__ c0)
{
    int i = blockIdx.x * blockDim.x + threadIdx.x;   // NV*Hdim grid
    float hv = h0[i];
    g_c[i] = c0[i];
    __nv_bfloat16 hb = __float2bfloat16(hv);
    g_h_hi0[i] = hb;
    g_h_lo0[i] = __float2bfloat16(hv - __bfloat162float(hb));
}

// ---------------- finalize: eh BN params + full ec branch ------------------
__global__ __launch_bounds__(256) void finalize_step(
    const float* __restrict__ gamma_eh, const float* __restrict__ beta_eh,
    const float* __restrict__ oneh_t,
    const float* __restrict__ W_ec, const float* __restrict__ b_ec,
    const float* __restrict__ gamma_ec, const float* __restrict__ beta_ec,
    const float* __restrict__ W_out)
{
    __shared__ float s_cnt[NCn];
    __shared__ int   s_cls[Nn];
    __shared__ float s_ec[NCn][EHn];
    __shared__ float s_contrib[NCn * ODn];

    int tid = threadIdx.x;
    {
        float s = 0.f, sq = 0.f;
        for (int b = 0; b < 128; b++) {
            s  += g_psum[b * EHn + tid];
            sq += g_psumsq[b * EHn + tid];
        }
        float m   = s * (1.f / (float)NV);
        float var = sq * (1.f / (float)NV) - m * m;
        float sc  = gamma_eh[tid] * rsqrtf(var + 1e-5f);
        g_bnscale[tid] = sc;
        g_bnshift[tid] = beta_eh[tid] - sc * m;
    }
    if (tid < NCn) {
        float cv = 0.f;
        for (int n = 0; n < Nn; n++) cv += oneh_t[n * NCn + tid];
        s_cnt[tid] = cv;
    }
    if (tid < Nn) {
        const float* r = oneh_t + tid * NCn;
        int cl = 0; float best = r[0];
#pragma unroll
        for (int k = 1; k < NCn; k++) if (r[k] > best) { best = r[k]; cl = k; }
        s_cls[tid] = cl;
    }
    __syncthreads();
    {
        int j = tid;
        float pre[NCn];
        float m = 0.f, sq = 0.f;
#pragma unroll
        for (int cl = 0; cl < NCn; cl++) {
            pre[cl] = W_ec[j * NCn + cl] + b_ec[j];
            float w = s_cnt[cl] * (1.f / (float)Nn);
            m  += w * pre[cl];
            sq += w * pre[cl] * pre[cl];
        }
        float var = sq - m * m;
        float sc  = gamma_ec[j] * rsqrtf(var + 1e-5f);
        float sh  = beta_ec[j] - sc * m;
#pragma unroll
        for (int cl = 0; cl < NCn; cl++)
            s_ec[cl][j] = fmaxf(sc * pre[cl] + sh, 0.f);
    }
    __syncthreads();
    int warp = tid >> 5, lane = tid & 31;
    for (int p = warp; p < NCn * ODn; p += 8) {
        int cl = p / ODn, od = p % ODn;
        float a = 0.f;
#pragma unroll
        for (int u = 0; u < 8; u++) {
            int j = lane + (u << 5);
            a = fmaf(s_ec[cl][j], W_out[od * (EHn + EHn) + EHn + j], a);
        }
        for (int off = 16; off; off >>= 1) a += __shfl_xor_sync(0xffffffffu, a, off);
        if (lane == 0) s_contrib[p] = a;
    }
    __syncthreads();
    if (tid < Nn) {
        int cl = s_cls[tid];
#pragma unroll
        for (int od = 0; od < ODn; od++)
            g_ncontrib[tid * ODn + od] = s_contrib[cl * ODn + od];
    }
}

// ---------------- op: bn+relu(eh) . W_out[:, :256] + ec + b_out + act ------
__global__ __launch_bounds__(256) void op_kernel(
    const float* __restrict__ W_out, const float* __restrict__ b_out,
    float* __restrict__ out, int t)
{
    int warp = threadIdx.x >> 5, lane = threadIdx.x & 31;
    int row  = (blockIdx.x << 3) + warp;
    const float* er = g_ehpre + (size_t)row * EHn;

    float a0 = 0.f, a1 = 0.f, a2 = 0.f, a3 = 0.f, a4 = 0.f;
#pragma unroll
    for (int u = 0; u < 8; u++) {
        int j = lane + (u << 5);
        float xv = fmaxf(fmaf(g_bnscale[j], er[j], g_bnshift[j]), 0.f);
        a0 = fmaf(xv, W_out[j],            a0);
        a1 = fmaf(xv, W_out[512  + j],     a1);
        a2 = fmaf(xv, W_out[1024 + j],     a2);
        a3 = fmaf(xv, W_out[1536 + j],     a3);
        a4 = fmaf(xv, W_out[2048 + j],     a4);
    }
    for (int off = 16; off; off >>= 1) {
        a0 += __shfl_xor_sync(0xffffffffu, a0, off);
        a1 += __shfl_xor_sync(0xffffffffu, a1, off);
        a2 += __shfl_xor_sync(0xffffffffu, a2, off);
        a3 += __shfl_xor_sync(0xffffffffu, a3, off);
        a4 += __shfl_xor_sync(0xffffffffu, a4, off);
    }
    if (lane < ODn) {
        int n = row >> 7, v = row & 127;
        float a = (lane == 0) ? a0 : (lane == 1) ? a1 : (lane == 2) ? a2
                : (lane == 3) ? a3 : a4;
        a += g_ncontrib[n * ODn + lane] + b_out[lane];
        if (lane == 2 || lane == 3) a = expf(a);
        else if (lane == 4)         a = tanhf(a);
        out[(((size_t)n * Tn + t) * Vn + v) * ODn + lane] = a;
    }
}

// ---------------- oc: (sum_V h / V) @ W_cls^T + b_cls ----------------------
__global__ __launch_bounds__(192) void oc_kernel(
    const float* __restrict__ hmean, const float* __restrict__ W_cls,
    const float* __restrict__ b_cls, float* __restrict__ out, int t)
{
    int n = blockIdx.x;
    int warp = threadIdx.x >> 5, lane = threadIdx.x & 31;
    if (warp < ODn) {
        float a = 0.f;
#pragma unroll
        for (int u = 0; u < 16; u++) {
            int k = lane + (u << 5);
            a = fmaf(hmean[n * Hdim + k], W_cls[warp * Hdim + k], a);
        }
        for (int off = 16; off; off >>= 1) a += __shfl_xor_sync(0xffffffffu, a, off);
        if (lane == 0)
            out[PRED_TOTAL + ((size_t)t * Nn + n) * ODn + warp] =
                a * (1.f / (float)Vn) + b_cls[warp];
    }
}

// ---------------- streams/events (created at load, before harness checkpoints)
struct StreamRes {
    cudaStream_t s2 = nullptr;
    cudaEvent_t  eG[2] = {nullptr, nullptr};
    cudaEvent_t  eH[2] = {nullptr, nullptr};
    bool ok = false;
    StreamRes() {
        if (cudaStreamCreateWithFlags(&s2, cudaStreamNonBlocking) != cudaSuccess) return;
        for (int i = 0; i < 2; i++) {
            if (cudaEventCreateWithFlags(&eG[i], cudaEventDisableTiming) != cudaSuccess) return;
            if (cudaEventCreateWithFlags(&eH[i], cudaEventDisableTiming) != cudaSuccess) return;
        }
        ok = true;
    }
};
static StreamRes g_sr;

// ---------------- host launcher --------------------------------------------
extern "C" void kernel_launch(void* const* d_in, const int* in_sizes, int n_in,
                              void* d_out, int out_size)
{
    const float* x     = (const float*)d_in[0];
    const float* h0    = (const float*)d_in[1];
    const float* c0    = (const float*)d_in[2];
    const float* oneh  = (const float*)d_in[3];
    const float* W_ih  = (const float*)d_in[4];
    const float* W_hh  = (const float*)d_in[5];
    const float* b_ih  = (const float*)d_in[6];
    const float* b_hh  = (const float*)d_in[7];
    const float* W_cls = (const float*)d_in[8];
    const float* b_cls = (const float*)d_in[9];
    const float* W_eh  = (const float*)d_in[10];
    const float* b_eh  = (const float*)d_in[11];
    const float* ga_eh = (const float*)d_in[12];
    const float* be_eh = (const float*)d_in[13];
    const float* W_ec  = (const float*)d_in[14];
    const float* b_ec  = (const float*)d_in[15];
    const float* ga_ec = (const float*)d_in[16];
    const float* be_ec = (const float*)d_in[17];
    const float* W_out = (const float*)d_in[18];
    const float* b_out = (const float*)d_in[19];
    float* out = (float*)d_out;

    cudaFuncSetAttribute(mma_gemm<0>, cudaFuncAttributeMaxDynamicSharedMemorySize, SM_TOTAL);
    cudaFuncSetAttribute(mma_gemm<1>, cudaFuncAttributeMaxDynamicSharedMemorySize, SM_TOTAL);
    cudaFuncSetAttribute(mma_gemm<2>, cudaFuncAttributeMaxDynamicSharedMemorySize, SM_TOTAL);

    float *gx, *ehpre, *bias2;
    float *hmean[2];
    __nv_bfloat16 *xh, *xl, *Wihh, *Wihl, *Whhh, *Whhl, *Wehh, *Wehl;
    __nv_bfloat16 *hbuf_hi[2], *hbuf_lo[2];
    cudaGetSymbolAddress((void**)&gx,    g_gx);
    cudaGetSymbolAddress((void**)&ehpre, g_ehpre);
    cudaGetSymbolAddress((void**)&bias2, g_bias2);
    cudaGetSymbolAddress((void**)&xh,    g_x_hi);
    cudaGetSymbolAddress((void**)&xl,    g_x_lo);
    cudaGetSymbolAddress((void**)&Wihh,  g_Wih_hi);
    cudaGetSymbolAddress((void**)&Wihl,  g_Wih_lo);
    cudaGetSymbolAddress((void**)&Whhh,  g_Whh_hi);
    cudaGetSymbolAddress((void**)&Whhl,  g_Whh_lo);
    cudaGetSymbolAddress((void**)&Wehh,  g_Weh_hi);
    cudaGetSymbolAddress((void**)&Wehl,  g_Weh_lo);
    cudaGetSymbolAddress((void**)&hbuf_hi[0], g_h_hi0);
    cudaGetSymbolAddress((void**)&hbuf_lo[0], g_h_lo0);
    cudaGetSymbolAddress((void**)&hbuf_hi[1], g_h_hi1);
    cudaGetSymbolAddress((void**)&hbuf_lo[1], g_h_lo1);
    cudaGetSymbolAddress((void**)&hmean[0], g_hmean0);
    cudaGetSymbolAddress((void**)&hmean[1], g_hmean1);

    // init + operand splits (stream 0)
    init_state<<<(NV * Hdim) / 256, 256>>>(h0, c0);
    split_mat<<<(NV * Cdim) / 256, 256>>>(x, xh, xl, NV * Cdim);
    split_perm<<<(G4H * Cdim) / 256, 256>>>(W_ih, Wihh, Wihl, Cdim);
    split_perm<<<(G4H * Hdim) / 256, 256>>>(W_hh, Whhh, Whhl, Hdim);
    split_mat<<<(EHn * Hdim) / 256, 256>>>(W_eh, Wehh, Wehl, EHn * Hdim);
    bias_combine<<<G4H / 256, 256>>>(b_ih, b_hh);

    // gx = x @ Wih_perm^T + (b_ih + b_hh)_perm   (step-invariant)
    mma_gemm<0><<<dim3(G4H / 128, NV / 128), 256, SM_TOTAL>>>(
        xh, xl, Wihh, Wihl, gx, bias2, nullptr, nullptr, nullptr, nullptr,
        G4H, Cdim);

    const bool dual = g_sr.ok;
    cudaStream_t sH = dual ? g_sr.s2 : (cudaStream_t)0;

    for (int t = 0; t < Tn; t++) {
        const int rb = t & 1, wb = rb ^ 1;

        if (dual && t >= 2) cudaStreamWaitEvent(0, g_sr.eH[t & 1], 0);

        // fused: gates = gx + h @ Whh_perm^T -> LSTM update -> h,c (+ split, hmean)
        mma_gemm<1><<<dim3(G4H / 128, NV / 128), 256, SM_TOTAL>>>(
            hbuf_hi[rb], hbuf_lo[rb], Whhh, Whhl, nullptr, nullptr, gx,
            hbuf_hi[wb], hbuf_lo[wb], hmean[wb], G4H, Hdim);

        if (dual) {
            cudaEventRecord(g_sr.eG[t & 1], 0);
            cudaStreamWaitEvent(sH, g_sr.eG[t & 1], 0);
        }

        // head chain (second stream when available)
        oc_kernel<<<Nn, 192, 0, sH>>>(hmean[wb], W_cls, b_cls, out, t);
        mma_gemm<2><<<dim3(EHn / 128, NV / 128), 256, SM_TOTAL, sH>>>(
            hbuf_hi[wb], hbuf_lo[wb], Wehh, Wehl, ehpre, b_eh,
            nullptr, nullptr, nullptr, nullptr, EHn, Hdim);
        finalize_step<<<1, 256, 0, sH>>>(ga_eh, be_eh, oneh + (size_t)t * Nn * NCn,
                                         W_ec, b_ec, ga_ec, be_ec, W_out);
        op_kernel<<<NV / 8, 256, 0, sH>>>(W_out, b_out, out, t);

        if (dual) cudaEventRecord(g_sr.eH[t & 1], sH);
    }

    if (dual) {
        cudaStreamWaitEvent(0, g_sr.eH[0], 0);
        cudaStreamWaitEvent(0, g_sr.eH[1], 0);
    }
}

// round 8
// speedup vs baseline: 1.7259x; 1.5009x over previous
#include <cuda_runtime.h>
#include <cuda_fp16.h>
#include <math.h>
#include <stdint.h>

// ---------------- problem constants ----------------
#define Nn   128
#define Vn   128
#define NV   16384          // N*V rows
#define Cdim 256
#define Hdim 512
#define G4H  2048           // 4*H
#define Tn   12
#define NCn  5
#define EHn  256
#define ODn  5
#define PRED_TOTAL (Nn*Tn*Vn*ODn)   // 983040

// SMEM tile geometry: tiles of 128 rows x 32 fp16, 80B padded rows
#define KCH      32
#define TROW_B   80
#define TILE_B   (128 * TROW_B)           // 10240 bytes
#define OFF_A    0
#define OFF_BHI  10240
#define OFF_BLO  20480
#define OFF_ALO  30720                    // only when ASPLIT
#define SMEM_M0  81920                    // 2 stages x 4 tiles
#define SMEM_M1  68608                    // max(2x3 tiles, LSTM staging 67584+1024)
#define SMEM_M2  61440                    // 2 stages x 3 tiles

// ---------------- device scratch (no allocations allowed) ----------------
__device__ float g_gx[NV * G4H];        // x @ W_ih^T + biases (gate-permuted cols)
__device__ float g_c[NV * Hdim];
__device__ float g_ehpre[NV * EHn];
__device__ float g_psum[128 * EHn];
__device__ float g_psumsq[128 * EHn];
__device__ float g_bnscale[EHn];
__device__ float g_bnshift[EHn];
__device__ float g_ncontrib[Nn * NCn];
__device__ float g_bias2[G4H];          // permuted b_ih + b_hh
__device__ float g_hmean0[Nn * Hdim];   // per-n column sums of h (double buffered)
__device__ float g_hmean1[Nn * Hdim];

// fp16 operands; weights are 2-term split (hi+lo), h is single fp16
__device__ __half g_h0[NV * Hdim];      // h state, double buffered
__device__ __half g_h1[NV * Hdim];
__device__ __half g_x_hi[NV * Cdim];
__device__ __half g_x_lo[NV * Cdim];
__device__ __half g_Wih_hi[G4H * Cdim];   // gate-permuted rows
__device__ __half g_Wih_lo[G4H * Cdim];
__device__ __half g_Whh_hi[G4H * Hdim];   // gate-permuted rows
__device__ __half g_Whh_lo[G4H * Hdim];
__device__ __half g_Weh_hi[EHn * Hdim];
__device__ __half g_Weh_lo[EHn * Hdim];

// ---------------- mma.sync / ldmatrix / cp.async helpers -------------------
__device__ __forceinline__ uint32_t smem_u32(const void* p) {
    uint32_t a;
    asm("{ .reg .u64 t; cvta.to.shared.u64 t, %1; cvt.u32.u64 %0, t; }" : "=r"(a) : "l"(p));
    return a;
}
__device__ __forceinline__ void ldsm_x4(uint32_t& r0, uint32_t& r1, uint32_t& r2,
                                        uint32_t& r3, uint32_t addr) {
    asm volatile("ldmatrix.sync.aligned.m8n8.x4.shared.b16 {%0,%1,%2,%3}, [%4];"
                 : "=r"(r0), "=r"(r1), "=r"(r2), "=r"(r3) : "r"(addr));
}
__device__ __forceinline__ void mma_f16(float* c, const uint32_t* a,
                                        uint32_t b0, uint32_t b1) {
    asm volatile(
        "mma.sync.aligned.m16n8k16.row.col.f32.f16.f16.f32 "
        "{%0,%1,%2,%3}, {%4,%5,%6,%7}, {%8,%9}, {%0,%1,%2,%3};"
        : "+f"(c[0]), "+f"(c[1]), "+f"(c[2]), "+f"(c[3])
        : "r"(a[0]), "r"(a[1]), "r"(a[2]), "r"(a[3]), "r"(b0), "r"(b1));
}
__device__ __forceinline__ void cp16(uint32_t dst, const void* src) {
    asm volatile("cp.async.cg.shared.global [%0], [%1], 16;" :: "r"(dst), "l"(src));
}
#define CP_COMMIT() asm volatile("cp.async.commit_group;" ::: "memory")
#define CP_WAIT1()  asm volatile("cp.async.wait_group 1;" ::: "memory")
#define CP_WAIT0()  asm volatile("cp.async.wait_group 0;" ::: "memory")

// issue one k-chunk (A single; B hi+lo; optional A-lo) into a stage
template<int ASPLIT>
__device__ __forceinline__ void load_chunk(
    uint32_t st, const __half* A0, const __half* A1,
    const __half* B0, const __half* B1, int K, int kk, int tid)
{
#pragma unroll
    for (int it = 0; it < 2; it++) {
        int f = tid + (it << 8);          // 0..511
        int r = f >> 2, c = f & 3;
        uint32_t off = (uint32_t)r * TROW_B + (uint32_t)c * 16;
        size_t src = (size_t)r * K + kk + (c << 3);
        cp16(st + OFF_A   + off, A0 + src);
        cp16(st + OFF_BHI + off, B0 + src);
        cp16(st + OFF_BLO + off, B1 + src);
        if (ASPLIT) cp16(st + OFF_ALO + off, A1 + src);
    }
}

// ---------------- core GEMM: C[M,Ntot] = A @ (Bhi+Blo)^T (+ Alo @ Bhi^T) --
// Block tile 128x128, warp tile 64x32 (2x4 warp grid), 2-stage k32 pipeline.
// MODE 0: C = acc + bias (gx GEMM; ASPLIT=1 gives 3-term precision)
// MODE 1: fused LSTM epilogue (reads gx w/ biases), writes g_c + next h (fp16)
//         + per-(n, column) h sums into hmean_out.
// MODE 2: C = acc + bias (ehpre) + fused BN column stats into g_psum/g_psumsq.
template<int MODE, int ASPLIT>
__global__ __launch_bounds__(256, 2) void mma_gemm(
    const __half* __restrict__ Ahi, const __half* __restrict__ Alo,
    const __half* __restrict__ Bhi, const __half* __restrict__ Blo,
    float* __restrict__ C, const float* __restrict__ bias,
    const float* __restrict__ gx,
    __half* __restrict__ whi,
    float* __restrict__ hmean_out,
    int Ntot, int K)
{
    constexpr uint32_t STAGE_B = (ASPLIT ? 4 : 3) * TILE_B;
    extern __shared__ char smem[];
    const uint32_t sb = smem_u32(smem);
    const int tid  = threadIdx.x;
    const int wid  = tid >> 5;
    const int lane = tid & 31;
    const int row0 = blockIdx.y << 7;
    const int col0 = blockIdx.x << 7;

    const int am0 = (wid & 1) * 64;    // warp m-offset in tile
    const int bn0 = (wid >> 1) * 32;   // warp n-offset in tile

    const uint32_t lrow = lane & 15, lcol = lane >> 4;
    const int g  = lane >> 2;
    const int t2 = (lane & 3) << 1;

    const __half* A0 = Ahi + (size_t)row0 * K;
    const __half* A1 = ASPLIT ? (Alo + (size_t)row0 * K) : nullptr;
    const __half* B0 = Bhi + (size_t)col0 * K;
    const __half* B1 = Blo + (size_t)col0 * K;

    float acc[4][4][4];
#pragma unroll
    for (int mf = 0; mf < 4; mf++)
#pragma unroll
        for (int nf = 0; nf < 4; nf++)
#pragma unroll
            for (int e = 0; e < 4; e++) acc[mf][nf][e] = 0.f;

    const int nch = K / KCH;

    // prologue: stage 0 <- chunk 0
    load_chunk<ASPLIT>(sb, A0, A1, B0, B1, K, 0, tid);
    CP_COMMIT();

    for (int kc = 0; kc < nch; kc++) {
        if (kc + 1 < nch) {
            load_chunk<ASPLIT>(sb + (uint32_t)((kc + 1) & 1) * STAGE_B,
                               A0, A1, B0, B1, K, (kc + 1) * KCH, tid);
            CP_COMMIT();
            CP_WAIT1();
        } else {
            CP_WAIT0();
        }
        __syncthreads();

        const uint32_t st  = sb + (uint32_t)(kc & 1) * STAGE_B;
        const uint32_t sA  = st + OFF_A;
        const uint32_t sB0 = st + OFF_BHI;
        const uint32_t sB1 = st + OFF_BLO;

#pragma unroll
        for (int ks = 0; ks < 2; ks++) {
            uint32_t a[4][4], bh[2][4], bl[2][4];
            const uint32_t kb = (uint32_t)(ks * 32 + lcol * 16);
#pragma unroll
            for (int mf = 0; mf < 4; mf++) {
                uint32_t ad = sA + (uint32_t)(am0 + mf * 16 + lrow) * TROW_B + kb;
                ldsm_x4(a[mf][0], a[mf][1], a[mf][2], a[mf][3], ad);
            }
#pragma unroll
            for (int ng = 0; ng < 2; ng++) {
                uint32_t roff = (uint32_t)(bn0 + ng * 16 + lrow) * TROW_B + kb;
                ldsm_x4(bh[ng][0], bh[ng][1], bh[ng][2], bh[ng][3], sB0 + roff);
                ldsm_x4(bl[ng][0], bl[ng][1], bl[ng][2], bl[ng][3], sB1 + roff);
            }
            // A * (B_hi + B_lo): A fragments reused for both terms
#pragma unroll
            for (int mf = 0; mf < 4; mf++)
#pragma unroll
                for (int nf = 0; nf < 4; nf++) {
                    int ng = nf >> 1, hf = nf & 1;
                    mma_f16(acc[mf][nf], a[mf], bh[ng][hf], bh[ng][hf + 2]);
                    mma_f16(acc[mf][nf], a[mf], bl[ng][hf], bl[ng][hf + 2]);
                }
            if (ASPLIT) {
                // + A_lo * B_hi (3rd term, gx GEMM only)
#pragma unroll
                for (int mf = 0; mf < 4; mf++) {
                    uint32_t ad = st + OFF_ALO
                                + (uint32_t)(am0 + mf * 16 + lrow) * TROW_B + kb;
                    ldsm_x4(a[mf][0], a[mf][1], a[mf][2], a[mf][3], ad);
                }
#pragma unroll
                for (int mf = 0; mf < 4; mf++)
#pragma unroll
                    for (int nf = 0; nf < 4; nf++) {
                        int ng = nf >> 1, hf = nf & 1;
                        mma_f16(acc[mf][nf], a[mf], bh[ng][hf], bh[ng][hf + 2]);
                    }
            }
        }
        __syncthreads();
    }

    if (MODE != 1) {
        // ---- generic store: C = acc + bias; MODE 2 also collects BN stats ----
        float sc_[4][2], sq_[4][2];
        if (MODE == 2) {
#pragma unroll
            for (int nf = 0; nf < 4; nf++) { sc_[nf][0] = sc_[nf][1] = 0.f;
                                             sq_[nf][0] = sq_[nf][1] = 0.f; }
        }
#pragma unroll
        for (int mf = 0; mf < 4; mf++) {
            int rg = row0 + am0 + mf * 16 + g;
#pragma unroll
            for (int nf = 0; nf < 4; nf++) {
                int cg = col0 + bn0 + nf * 8 + t2;
                float b0 = bias[cg], b1 = bias[cg + 1];
                float v00 = acc[mf][nf][0] + b0, v01 = acc[mf][nf][1] + b1;
                float v10 = acc[mf][nf][2] + b0, v11 = acc[mf][nf][3] + b1;
                *(float2*)(C + (size_t)rg * Ntot + cg) = make_float2(v00, v01);
                *(float2*)(C + (size_t)(rg + 8) * Ntot + cg) = make_float2(v10, v11);
                if (MODE == 2) {
                    sc_[nf][0] += v00 + v10; sq_[nf][0] += v00 * v00 + v10 * v10;
                    sc_[nf][1] += v01 + v11; sq_[nf][1] += v01 * v01 + v11 * v11;
                }
            }
        }
        if (MODE == 2) {
            float2* S2 = (float2*)smem;    // [128 cols][16 slots] = 16KB
            int slot = ((wid & 1) << 3) + g;
#pragma unroll
            for (int nf = 0; nf < 4; nf++) {
                int cc0 = bn0 + nf * 8 + t2;
                S2[cc0 * 16 + slot]       = make_float2(sc_[nf][0], sq_[nf][0]);
                S2[(cc0 + 1) * 16 + slot] = make_float2(sc_[nf][1], sq_[nf][1]);
            }
            __syncthreads();
            if (tid < 128) {
                float s = 0.f, q = 0.f;
#pragma unroll
                for (int k2 = 0; k2 < 16; k2++) {
                    float2 v = S2[tid * 16 + k2];
                    s += v.x; q += v.y;
                }
                int rb = row0 >> 7;
                g_psum[rb * EHn + col0 + tid]   = s;
                g_psumsq[rb * EHn + col0 + tid] = q;
            }
        }
    } else {
        // ---- LSTM epilogue: stage acc tile in smem, then elementwise ----
        float* Sf = (float*)smem;   // [128][132] = 67584 B
#pragma unroll
        for (int mf = 0; mf < 4; mf++) {
            int rr = am0 + mf * 16 + g;
#pragma unroll
            for (int nf = 0; nf < 4; nf++) {
                int cc = bn0 + nf * 8 + t2;
                Sf[rr * 132 + cc]           = acc[mf][nf][0];
                Sf[rr * 132 + cc + 1]       = acc[mf][nf][1];
                Sf[(rr + 8) * 132 + cc]     = acc[mf][nf][2];
                Sf[(rr + 8) * 132 + cc + 1] = acc[mf][nf][3];
            }
        }
        __syncthreads();

        const int j0 = col0 >> 2;      // 32 gate-quadruples per tile
        float hsum = 0.f;
#pragma unroll
        for (int it = 0; it < 16; it++) {
            int item = tid + (it << 8);            // 0..4095
            int r = item >> 5, q = item & 31;
            int grow = row0 + r;
            float4 gv  = *(const float4*)(Sf + r * 132 + (q << 2));
            float4 gxv = *(const float4*)(gx + (size_t)grow * G4H + col0 + (q << 2));
            float gi = gv.x + gxv.x;
            float gf = gv.y + gxv.y;
            float gg = gv.z + gxv.z;
            float go = gv.w + gxv.w;
            float si = 1.f / (1.f + expf(-gi));
            float sf = 1.f / (1.f + expf(-gf));
            float so = 1.f / (1.f + expf(-go));
            size_t idx = (size_t)grow * Hdim + j0 + q;
            float cn = sf * g_c[idx] + si * tanhf(gg);
            g_c[idx] = cn;
            float hv = so * tanhf(cn);
            hsum += hv;
            whi[idx] = __float2half_rn(hv);
        }
        // per-(n, column) h sums: this CTA's 128 rows are exactly one n
        float* Sm = (float*)(smem + 67584);   // [32 q][8 warp-slots] = 1KB
        Sm[(tid & 31) * 8 + (tid >> 5)] = hsum;
        __syncthreads();
        if (tid < 32) {
            float s = 0.f;
#pragma unroll
            for (int k2 = 0; k2 < 8; k2++) s += Sm[tid * 8 + k2];
            hmean_out[(row0 >> 7) * Hdim + j0 + tid] = s;   // raw sum; oc scales
        }
    }
}

// ---------------- splits / init -------------------------------------------
__global__ __launch_bounds__(256) void split_mat(
    const float* __restrict__ src, __half* __restrict__ hi,
    __half* __restrict__ lo, int n)
{
    int i = blockIdx.x * blockDim.x + threadIdx.x;
    if (i < n) {
        float v = src[i];
        __half h = __float2half_rn(v);
        hi[i] = h;
        lo[i] = __float2half_rn(v - __half2float(h));
    }
}

// gate-permuted split for W [2048][K]: new_row = (r%512)*4 + r/512
__global__ __launch_bounds__(256) void split_perm(
    const float* __restrict__ src, __half* __restrict__ hi,
    __half* __restrict__ lo, int K)
{
    int i = blockIdx.x * blockDim.x + threadIdx.x;   // over 2048*K
    int r = i / K, c = i - r * K;
    int nr = ((r & 511) << 2) + (r >> 9);
    float v = src[i];
    __half h = __float2half_rn(v);
    hi[nr * K + c] = h;
    lo[nr * K + c] = __float2half_rn(v - __half2float(h));
}

__global__ void bias_combine(const float* __restrict__ b_ih,
                             const float* __restrict__ b_hh)
{
    int i = blockIdx.x * blockDim.x + threadIdx.x;   // < 2048
    int p = ((i & 511) << 2) + (i >> 9);
    g_bias2[p] = b_ih[i] + b_hh[i];
}

__global__ void init_state(const float* __restrict__ h0, const float* __restrict__ c0)
{
    int i = blockIdx.x * blockDim.x + threadIdx.x;   // NV*Hdim grid
    g_c[i] = c0[i];
    g_h0[i] = __float2half_rn(h0[i]);
}

// ---------------- finalize: eh BN params + full ec branch ------------------
__global__ __launch_bounds__(256) void finalize_step(
    const float* __restrict__ gamma_eh, const float* __restrict__ beta_eh,
    const float* __restrict__ oneh_t,
    const float* __restrict__ W_ec, const float* __restrict__ b_ec,
    const float* __restrict__ gamma_ec, const float* __restrict__ beta_ec,
    const float* __restrict__ W_out)
{
    __shared__ float s_cnt[NCn];
    __shared__ int   s_cls[Nn];
    __shared__ float s_ec[NCn][EHn];
    __shared__ float s_contrib[NCn * ODn];

    int tid = threadIdx.x;
    {
        float s = 0.f, sq = 0.f;
        for (int b = 0; b < 128; b++) {
            s  += g_psum[b * EHn + tid];
            sq += g_psumsq[b * EHn + tid];
        }
        float m   = s * (1.f / (float)NV);
        float var = sq * (1.f / (float)NV) - m * m;
        float sc  = gamma_eh[tid] * rsqrtf(var + 1e-5f);
        g_bnscale[tid] = sc;
        g_bnshift[tid] = beta_eh[tid] - sc * m;
    }
    if (tid < NCn) {
        float cv = 0.f;
        for (int n = 0; n < Nn; n++) cv += oneh_t[n * NCn + tid];
        s_cnt[tid] = cv;
    }
    if (tid < Nn) {
        const float* r = oneh_t + tid * NCn;
        int cl = 0; float best = r[0];
#pragma unroll
        for (int k = 1; k < NCn; k++) if (r[k] > best) { best = r[k]; cl = k; }
        s_cls[tid] = cl;
    }
    __syncthreads();
    {
        int j = tid;
        float pre[NCn];
        float m = 0.f, sq = 0.f;
#pragma unroll
        for (int cl = 0; cl < NCn; cl++) {
            pre[cl] = W_ec[j * NCn + cl] + b_ec[j];
            float w = s_cnt[cl] * (1.f / (float)Nn);
            m  += w * pre[cl];
            sq += w * pre[cl] * pre[cl];
        }
        float var = sq - m * m;
        float sc  = gamma_ec[j] * rsqrtf(var + 1e-5f);
        float sh  = beta_ec[j] - sc * m;
#pragma unroll
        for (int cl = 0; cl < NCn; cl++)
            s_ec[cl][j] = fmaxf(sc * pre[cl] + sh, 0.f);
    }
    __syncthreads();
    int warp = tid >> 5, lane = tid & 31;
    for (int p = warp; p < NCn * ODn; p += 8) {
        int cl = p / ODn, od = p % ODn;
        float a = 0.f;
#pragma unroll
        for (int u = 0; u < 8; u++) {
            int j = lane + (u << 5);
            a = fmaf(s_ec[cl][j], W_out[od * (EHn + EHn) + EHn + j], a);
        }
        for (int off = 16; off; off >>= 1) a += __shfl_xor_sync(0xffffffffu, a, off);
        if (lane == 0) s_contrib[p] = a;
    }
    __syncthreads();
    if (tid < Nn) {
        int cl = s_cls[tid];
#pragma unroll
        for (int od = 0; od < ODn; od++)
            g_ncontrib[tid * ODn + od] = s_contrib[cl * ODn + od];
    }
}

// ---------------- op: bn+relu(eh) . W_out[:, :256] + ec + b_out + act ------
__global__ __launch_bounds__(256) void op_kernel(
    const float* __restrict__ W_out, const float* __restrict__ b_out,
    float* __restrict__ out, int t)
{
    int warp = threadIdx.x >> 5, lane = threadIdx.x & 31;
    int row  = (blockIdx.x << 3) + warp;
    const float* er = g_ehpre + (size_t)row * EHn;

    float a0 = 0.f, a1 = 0.f, a2 = 0.f, a3 = 0.f, a4 = 0.f;
#pragma unroll
    for (int u = 0; u < 8; u++) {
        int j = lane + (u << 5);
        float xv = fmaxf(fmaf(g_bnscale[j], er[j], g_bnshift[j]), 0.f);
        a0 = fmaf(xv, W_out[j],            a0);
        a1 = fmaf(xv, W_out[512  + j],     a1);
        a2 = fmaf(xv, W_out[1024 + j],     a2);
        a3 = fmaf(xv, W_out[1536 + j],     a3);
        a4 = fmaf(xv, W_out[2048 + j],     a4);
    }
    for (int off = 16; off; off >>= 1) {
        a0 += __shfl_xor_sync(0xffffffffu, a0, off);
        a1 += __shfl_xor_sync(0xffffffffu, a1, off);
        a2 += __shfl_xor_sync(0xffffffffu, a2, off);
        a3 += __shfl_xor_sync(0xffffffffu, a3, off);
        a4 += __shfl_xor_sync(0xffffffffu, a4, off);
    }
    if (lane < ODn) {
        int n = row >> 7, v = row & 127;
        float a = (lane == 0) ? a0 : (lane == 1) ? a1 : (lane == 2) ? a2
                : (lane == 3) ? a3 : a4;
        a += g_ncontrib[n * ODn + lane] + b_out[lane];
        if (lane == 2 || lane == 3) a = expf(a);
        else if (lane == 4)         a = tanhf(a);
        out[(((size_t)n * Tn + t) * Vn + v) * ODn + lane] = a;
    }
}

// ---------------- oc: (sum_V h / V) @ W_cls^T + b_cls ----------------------
__global__ __launch_bounds__(192) void oc_kernel(
    const float* __restrict__ hmean, const float* __restrict__ W_cls,
    const float* __restrict__ b_cls, float* __restrict__ out, int t)
{
    int n = blockIdx.x;
    int warp = threadIdx.x >> 5, lane = threadIdx.x & 31;
    if (warp < ODn) {
        float a = 0.f;
#pragma unroll
        for (int u = 0; u < 16; u++) {
            int k = lane + (u << 5);
            a = fmaf(hmean[n * Hdim + k], W_cls[warp * Hdim + k], a);
        }
        for (int off = 16; off; off >>= 1) a += __shfl_xor_sync(0xffffffffu, a, off);
        if (lane == 0)
            out[PRED_TOTAL + ((size_t)t * Nn + n) * ODn + warp] =
                a * (1.f / (float)Vn) + b_cls[warp];
    }
}

// ---------------- streams/events (created at load, before harness checkpoints)
struct StreamRes {
    cudaStream_t s2 = nullptr;
    cudaEvent_t  eG[2] = {nullptr, nullptr};
    cudaEvent_t  eH[2] = {nullptr, nullptr};
    bool ok = false;
    StreamRes() {
        if (cudaStreamCreateWithFlags(&s2, cudaStreamNonBlocking) != cudaSuccess) return;
        for (int i = 0; i < 2; i++) {
            if (cudaEventCreateWithFlags(&eG[i], cudaEventDisableTiming) != cudaSuccess) return;
            if (cudaEventCreateWithFlags(&eH[i], cudaEventDisableTiming) != cudaSuccess) return;
        }
        ok = true;
    }
};
static StreamRes g_sr;

// ---------------- host launcher --------------------------------------------
extern "C" void kernel_launch(void* const* d_in, const int* in_sizes, int n_in,
                              void* d_out, int out_size)
{
    const float* x     = (const float*)d_in[0];
    const float* h0    = (const float*)d_in[1];
    const float* c0    = (const float*)d_in[2];
    const float* oneh  = (const float*)d_in[3];
    const float* W_ih  = (const float*)d_in[4];
    const float* W_hh  = (const float*)d_in[5];
    const float* b_ih  = (const float*)d_in[6];
    const float* b_hh  = (const float*)d_in[7];
    const float* W_cls = (const float*)d_in[8];
    const float* b_cls = (const float*)d_in[9];
    const float* W_eh  = (const float*)d_in[10];
    const float* b_eh  = (const float*)d_in[11];
    const float* ga_eh = (const float*)d_in[12];
    const float* be_eh = (const float*)d_in[13];
    const float* W_ec  = (const float*)d_in[14];
    const float* b_ec  = (const float*)d_in[15];
    const float* ga_ec = (const float*)d_in[16];
    const float* be_ec = (const float*)d_in[17];
    const float* W_out = (const float*)d_in[18];
    const float* b_out = (const float*)d_in[19];
    float* out = (float*)d_out;

    cudaFuncSetAttribute(mma_gemm<0,1>, cudaFuncAttributeMaxDynamicSharedMemorySize, SMEM_M0);
    cudaFuncSetAttribute(mma_gemm<1,0>, cudaFuncAttributeMaxDynamicSharedMemorySize, SMEM_M1);
    cudaFuncSetAttribute(mma_gemm<2,0>, cudaFuncAttributeMaxDynamicSharedMemorySize, SMEM_M2);

    float *gx, *ehpre, *bias2;
    float *hmean[2];
    __half *xh, *xl, *Wihh, *Wihl, *Whhh, *Whhl, *Wehh, *Wehl;
    __half *hbuf[2];
    cudaGetSymbolAddress((void**)&gx,    g_gx);
    cudaGetSymbolAddress((void**)&ehpre, g_ehpre);
    cudaGetSymbolAddress((void**)&bias2, g_bias2);
    cudaGetSymbolAddress((void**)&xh,    g_x_hi);
    cudaGetSymbolAddress((void**)&xl,    g_x_lo);
    cudaGetSymbolAddress((void**)&Wihh,  g_Wih_hi);
    cudaGetSymbolAddress((void**)&Wihl,  g_Wih_lo);
    cudaGetSymbolAddress((void**)&Whhh,  g_Whh_hi);
    cudaGetSymbolAddress((void**)&Whhl,  g_Whh_lo);
    cudaGetSymbolAddress((void**)&Wehh,  g_Weh_hi);
    cudaGetSymbolAddress((void**)&Wehl,  g_Weh_lo);
    cudaGetSymbolAddress((void**)&hbuf[0], g_h0);
    cudaGetSymbolAddress((void**)&hbuf[1], g_h1);
    cudaGetSymbolAddress((void**)&hmean[0], g_hmean0);
    cudaGetSymbolAddress((void**)&hmean[1], g_hmean1);

    // init + operand splits (stream 0)
    init_state<<<(NV * Hdim) / 256, 256>>>(h0, c0);
    split_mat<<<(NV * Cdim) / 256, 256>>>(x, xh, xl, NV * Cdim);
    split_perm<<<(G4H * Cdim) / 256, 256>>>(W_ih, Wihh, Wihl, Cdim);
    split_perm<<<(G4H * Hdim) / 256, 256>>>(W_hh, Whhh, Whhl, Hdim);
    split_mat<<<(EHn * Hdim) / 256, 256>>>(W_eh, Wehh, Wehl, EHn * Hdim);
    bias_combine<<<G4H / 256, 256>>>(b_ih, b_hh);

    // gx = x @ Wih_perm^T + (b_ih + b_hh)_perm   (step-invariant, 3-term)
    mma_gemm<0,1><<<dim3(G4H / 128, NV / 128), 256, SMEM_M0>>>(
        xh, xl, Wihh, Wihl, gx, bias2, nullptr, nullptr, nullptr,
        G4H, Cdim);

    const bool dual = g_sr.ok;
    cudaStream_t sH = dual ? g_sr.s2 : (cudaStream_t)0;

    for (int t = 0; t < Tn; t++) {
        const int rb = t & 1, wb = rb ^ 1;

        if (dual && t >= 2) cudaStreamWaitEvent(0, g_sr.eH[t & 1], 0);

        // fused: gates = gx + h @ Whh_perm^T -> LSTM update -> h,c (+ hmean)
        mma_gemm<1,0><<<dim3(G4H / 128, NV / 128), 256, SMEM_M1>>>(
            hbuf[rb], nullptr, Whhh, Whhl, nullptr, nullptr, gx,
            hbuf[wb], hmean[wb], G4H, Hdim);

        if (dual) {
            cudaEventRecord(g_sr.eG[t & 1], 0);
            cudaStreamWaitEvent(sH, g_sr.eG[t & 1], 0);
        }

        // head chain (second stream when available)
        oc_kernel<<<Nn, 192, 0, sH>>>(hmean[wb], W_cls, b_cls, out, t);
        mma_gemm<2,0><<<dim3(EHn / 128, NV / 128), 256, SMEM_M2, sH>>>(
            hbuf[wb], nullptr, Wehh, Wehl, ehpre, b_eh,
            nullptr, nullptr, nullptr, EHn, Hdim);
        finalize_step<<<1, 256, 0, sH>>>(ga_eh, be_eh, oneh + (size_t)t * Nn * NCn,
                                         W_ec, b_ec, ga_ec, be_ec, W_out);
        op_kernel<<<NV / 8, 256, 0, sH>>>(W_out, b_out, out, t);

        if (dual) cudaEventRecord(g_sr.eH[t & 1], sH);
    }

    if (dual) {
        cudaStreamWaitEvent(0, g_sr.eH[0], 0);
        cudaStreamWaitEvent(0, g_sr.eH[1], 0);
    }
}

// round 9
// speedup vs baseline: 2.1483x; 1.2447x over previous
#include <cuda_runtime.h>
#include <cuda_fp16.h>
#include <math.h>
#include <stdint.h>

// ---------------- problem constants ----------------
#define Nn   128
#define Vn   128
#define NV   16384          // N*V rows
#define Cdim 256
#define Hdim 512
#define G4H  2048           // 4*H
#define Tn   12
#define NCn  5
#define EHn  256
#define ODn  5
#define PRED_TOTAL (Nn*Tn*Vn*ODn)   // 983040

// SMEM tile geometry: tiles of 128 rows x 32 fp16, 80B padded rows
#define KCH      32
#define TROW_B   80
#define TILE_B   (128 * TROW_B)           // 10240 bytes
#define OFF_A    0
#define OFF_BHI  10240
#define OFF_BLO  20480
#define OFF_ALO  30720
#define SMEM_M0  81920                    // 2 stages x 4 tiles (3-term)
#define SMEM_M1  68608                    // max(2x2 tiles, LSTM staging 67584+1024)
#define SMEM_M2  61440                    // 2 stages x 3 tiles (2-term)

// ---------------- device scratch (no allocations allowed) ----------------
__device__ float g_gx[NV * G4H];        // x @ W_ih^T + biases (gate-permuted cols)
__device__ float g_c[NV * Hdim];
__device__ float g_ehpre[NV * EHn];
__device__ float g_psum[128 * EHn];
__device__ float g_psumsq[128 * EHn];
__device__ float g_bnscale[EHn];
__device__ float g_bnshift[EHn];
__device__ float g_ncontrib[Nn * NCn];
__device__ float g_bias2[G4H];          // permuted b_ih + b_hh
__device__ float g_hmean0[Nn * Hdim];   // per-n column sums of h (double buffered)
__device__ float g_hmean1[Nn * Hdim];

// fp16 operands; h is single fp16 (double buffered)
__device__ __half g_h0[NV * Hdim];
__device__ __half g_h1[NV * Hdim];
__device__ __half g_x_hi[NV * Cdim];
__device__ __half g_x_lo[NV * Cdim];
__device__ __half g_Wih_hi[G4H * Cdim];   // gate-permuted rows
__device__ __half g_Wih_lo[G4H * Cdim];
__device__ __half g_Whh_hi[G4H * Hdim];   // gate-permuted rows (single term)
__device__ __half g_Weh_hi[EHn * Hdim];
__device__ __half g_Weh_lo[EHn * Hdim];

// ---------------- mma.sync / ldmatrix / cp.async helpers -------------------
__device__ __forceinline__ uint32_t smem_u32(const void* p) {
    uint32_t a;
    asm("{ .reg .u64 t; cvta.to.shared.u64 t, %1; cvt.u32.u64 %0, t; }" : "=r"(a) : "l"(p));
    return a;
}
__device__ __forceinline__ void ldsm_x4(uint32_t& r0, uint32_t& r1, uint32_t& r2,
                                        uint32_t& r3, uint32_t addr) {
    asm volatile("ldmatrix.sync.aligned.m8n8.x4.shared.b16 {%0,%1,%2,%3}, [%4];"
                 : "=r"(r0), "=r"(r1), "=r"(r2), "=r"(r3) : "r"(addr));
}
__device__ __forceinline__ void mma_f16(float* c, const uint32_t* a,
                                        uint32_t b0, uint32_t b1) {
    asm volatile(
        "mma.sync.aligned.m16n8k16.row.col.f32.f16.f16.f32 "
        "{%0,%1,%2,%3}, {%4,%5,%6,%7}, {%8,%9}, {%0,%1,%2,%3};"
        : "+f"(c[0]), "+f"(c[1]), "+f"(c[2]), "+f"(c[3])
        : "r"(a[0]), "r"(a[1]), "r"(a[2]), "r"(a[3]), "r"(b0), "r"(b1));
}
__device__ __forceinline__ void cp16(uint32_t dst, const void* src) {
    asm volatile("cp.async.cg.shared.global [%0], [%1], 16;" :: "r"(dst), "l"(src));
}
#define CP_COMMIT() asm volatile("cp.async.commit_group;" ::: "memory")
#define CP_WAIT1()  asm volatile("cp.async.wait_group 1;" ::: "memory")
#define CP_WAIT0()  asm volatile("cp.async.wait_group 0;" ::: "memory")

// issue one k-chunk into a stage: A + B_hi always, B_lo if NT>=2, A_lo if NT==3
template<int NT>
__device__ __forceinline__ void load_chunk(
    uint32_t st, const __half* A0, const __half* A1,
    const __half* B0, const __half* B1, int K, int kk, int tid)
{
#pragma unroll
    for (int it = 0; it < 2; it++) {
        int f = tid + (it << 8);          // 0..511
        int r = f >> 2, c = f & 3;
        uint32_t off = (uint32_t)r * TROW_B + (uint32_t)c * 16;
        size_t src = (size_t)r * K + kk + (c << 3);
        cp16(st + OFF_A   + off, A0 + src);
        cp16(st + OFF_BHI + off, B0 + src);
        if (NT >= 2) cp16(st + OFF_BLO + off, B1 + src);
        if (NT == 3) cp16(st + OFF_ALO + off, A1 + src);
    }
}

// ---------------- core GEMM: C[M,Ntot] = A @ B^T (1..3 precision terms) ----
// Block tile 128x128, warp tile 64x32 (2x4 warp grid), 2-stage k32 pipeline.
// MODE 0: C = acc + bias (gx GEMM, NT=3: A@Bhi + A@Blo + Alo@Bhi)
// MODE 1: fused LSTM epilogue (reads gx w/ biases), writes g_c + next h (fp16)
//         + per-(n, column) h sums into hmean_out. NT=1: single A@Bhi.
// MODE 2: C = acc + bias (ehpre, NT=2) + fused BN stats into g_psum/g_psumsq.
template<int MODE, int NT>
__global__ __launch_bounds__(256, 2) void mma_gemm(
    const __half* __restrict__ Ahi, const __half* __restrict__ Alo,
    const __half* __restrict__ Bhi, const __half* __restrict__ Blo,
    float* __restrict__ C, const float* __restrict__ bias,
    const float* __restrict__ gx,
    __half* __restrict__ whi,
    float* __restrict__ hmean_out,
    int Ntot, int K)
{
    constexpr uint32_t STAGE_B = (NT == 1 ? 2 : (NT == 2 ? 3 : 4)) * TILE_B;
    extern __shared__ char smem[];
    const uint32_t sb = smem_u32(smem);
    const int tid  = threadIdx.x;
    const int wid  = tid >> 5;
    const int lane = tid & 31;
    const int row0 = blockIdx.y << 7;
    const int col0 = blockIdx.x << 7;

    const int am0 = (wid & 1) * 64;    // warp m-offset in tile
    const int bn0 = (wid >> 1) * 32;   // warp n-offset in tile

    const uint32_t lrow = lane & 15, lcol = lane >> 4;
    const int g  = lane >> 2;
    const int t2 = (lane & 3) << 1;

    const __half* A0 = Ahi + (size_t)row0 * K;
    const __half* A1 = (NT == 3) ? (Alo + (size_t)row0 * K) : nullptr;
    const __half* B0 = Bhi + (size_t)col0 * K;
    const __half* B1 = (NT >= 2) ? (Blo + (size_t)col0 * K) : nullptr;

    float acc[4][4][4];
#pragma unroll
    for (int mf = 0; mf < 4; mf++)
#pragma unroll
        for (int nf = 0; nf < 4; nf++)
#pragma unroll
            for (int e = 0; e < 4; e++) acc[mf][nf][e] = 0.f;

    const int nch = K / KCH;

    // prologue: stage 0 <- chunk 0
    load_chunk<NT>(sb, A0, A1, B0, B1, K, 0, tid);
    CP_COMMIT();

    for (int kc = 0; kc < nch; kc++) {
        if (kc + 1 < nch) {
            load_chunk<NT>(sb + (uint32_t)((kc + 1) & 1) * STAGE_B,
                           A0, A1, B0, B1, K, (kc + 1) * KCH, tid);
            CP_COMMIT();
            CP_WAIT1();
        } else {
            CP_WAIT0();
        }
        __syncthreads();

        const uint32_t st  = sb + (uint32_t)(kc & 1) * STAGE_B;
        const uint32_t sA  = st + OFF_A;
        const uint32_t sB0 = st + OFF_BHI;
        const uint32_t sB1 = st + OFF_BLO;

#pragma unroll
        for (int ks = 0; ks < 2; ks++) {
            uint32_t a[4][4], bh[2][4], bl[2][4];
            const uint32_t kb = (uint32_t)(ks * 32 + lcol * 16);
#pragma unroll
            for (int mf = 0; mf < 4; mf++) {
                uint32_t ad = sA + (uint32_t)(am0 + mf * 16 + lrow) * TROW_B + kb;
                ldsm_x4(a[mf][0], a[mf][1], a[mf][2], a[mf][3], ad);
            }
#pragma unroll
            for (int ng = 0; ng < 2; ng++) {
                uint32_t roff = (uint32_t)(bn0 + ng * 16 + lrow) * TROW_B + kb;
                ldsm_x4(bh[ng][0], bh[ng][1], bh[ng][2], bh[ng][3], sB0 + roff);
                if (NT >= 2)
                    ldsm_x4(bl[ng][0], bl[ng][1], bl[ng][2], bl[ng][3], sB1 + roff);
            }
#pragma unroll
            for (int mf = 0; mf < 4; mf++)
#pragma unroll
                for (int nf = 0; nf < 4; nf++) {
                    int ng = nf >> 1, hf = nf & 1;
                    mma_f16(acc[mf][nf], a[mf], bh[ng][hf], bh[ng][hf + 2]);
                    if (NT >= 2)
                        mma_f16(acc[mf][nf], a[mf], bl[ng][hf], bl[ng][hf + 2]);
                }
            if (NT == 3) {
#pragma unroll
                for (int mf = 0; mf < 4; mf++) {
                    uint32_t ad = st + OFF_ALO
                                + (uint32_t)(am0 + mf * 16 + lrow) * TROW_B + kb;
                    ldsm_x4(a[mf][0], a[mf][1], a[mf][2], a[mf][3], ad);
                }
#pragma unroll
                for (int mf = 0; mf < 4; mf++)
#pragma unroll
                    for (int nf = 0; nf < 4; nf++) {
                        int ng = nf >> 1, hf = nf & 1;
                        mma_f16(acc[mf][nf], a[mf], bh[ng][hf], bh[ng][hf + 2]);
                    }
            }
        }
        __syncthreads();
    }

    if (MODE != 1) {
        // ---- generic store: C = acc + bias; MODE 2 also collects BN stats ----
        float sc_[4][2], sq_[4][2];
        if (MODE == 2) {
#pragma unroll
            for (int nf = 0; nf < 4; nf++) { sc_[nf][0] = sc_[nf][1] = 0.f;
                                             sq_[nf][0] = sq_[nf][1] = 0.f; }
        }
#pragma unroll
        for (int mf = 0; mf < 4; mf++) {
            int rg = row0 + am0 + mf * 16 + g;
#pragma unroll
            for (int nf = 0; nf < 4; nf++) {
                int cg = col0 + bn0 + nf * 8 + t2;
                float b0 = bias[cg], b1 = bias[cg + 1];
                float v00 = acc[mf][nf][0] + b0, v01 = acc[mf][nf][1] + b1;
                float v10 = acc[mf][nf][2] + b0, v11 = acc[mf][nf][3] + b1;
                *(float2*)(C + (size_t)rg * Ntot + cg) = make_float2(v00, v01);
                *(float2*)(C + (size_t)(rg + 8) * Ntot + cg) = make_float2(v10, v11);
                if (MODE == 2) {
                    sc_[nf][0] += v00 + v10; sq_[nf][0] += v00 * v00 + v10 * v10;
                    sc_[nf][1] += v01 + v11; sq_[nf][1] += v01 * v01 + v11 * v11;
                }
            }
        }
        if (MODE == 2) {
            float2* S2 = (float2*)smem;    // [128 cols][16 slots] = 16KB
            int slot = ((wid & 1) << 3) + g;
#pragma unroll
            for (int nf = 0; nf < 4; nf++) {
                int cc0 = bn0 + nf * 8 + t2;
                S2[cc0 * 16 + slot]       = make_float2(sc_[nf][0], sq_[nf][0]);
                S2[(cc0 + 1) * 16 + slot] = make_float2(sc_[nf][1], sq_[nf][1]);
            }
            __syncthreads();
            if (tid < 128) {
                float s = 0.f, q = 0.f;
#pragma unroll
                for (int k2 = 0; k2 < 16; k2++) {
                    float2 v = S2[tid * 16 + k2];
                    s += v.x; q += v.y;
                }
                int rb = row0 >> 7;
                g_psum[rb * EHn + col0 + tid]   = s;
                g_psumsq[rb * EHn + col0 + tid] = q;
            }
        }
    } else {
        // ---- LSTM epilogue: stage acc tile in smem, then elementwise ----
        float* Sf = (float*)smem;   // [128][132] = 67584 B
#pragma unroll
        for (int mf = 0; mf < 4; mf++) {
            int rr = am0 + mf * 16 + g;
#pragma unroll
            for (int nf = 0; nf < 4; nf++) {
                int cc = bn0 + nf * 8 + t2;
                Sf[rr * 132 + cc]           = acc[mf][nf][0];
                Sf[rr * 132 + cc + 1]       = acc[mf][nf][1];
                Sf[(rr + 8) * 132 + cc]     = acc[mf][nf][2];
                Sf[(rr + 8) * 132 + cc + 1] = acc[mf][nf][3];
            }
        }
        __syncthreads();

        const int j0 = col0 >> 2;      // 32 gate-quadruples per tile
        float hsum = 0.f;
#pragma unroll
        for (int it = 0; it < 16; it++) {
            int item = tid + (it << 8);            // 0..4095
            int r = item >> 5, q = item & 31;
            int grow = row0 + r;
            float4 gv  = *(const float4*)(Sf + r * 132 + (q << 2));
            float4 gxv = *(const float4*)(gx + (size_t)grow * G4H + col0 + (q << 2));
            float gi = gv.x + gxv.x;
            float gf = gv.y + gxv.y;
            float gg = gv.z + gxv.z;
            float go = gv.w + gxv.w;
            float si = 1.f / (1.f + expf(-gi));
            float sf = 1.f / (1.f + expf(-gf));
            float so = 1.f / (1.f + expf(-go));
            size_t idx = (size_t)grow * Hdim + j0 + q;
            float cn = sf * g_c[idx] + si * tanhf(gg);
            g_c[idx] = cn;
            float hv = so * tanhf(cn);
            hsum += hv;
            whi[idx] = __float2half_rn(hv);
        }
        // per-(n, column) h sums: this CTA's 128 rows are exactly one n
        float* Sm = (float*)(smem + 67584);   // [32 q][8 warp-slots] = 1KB
        Sm[(tid & 31) * 8 + (tid >> 5)] = hsum;
        __syncthreads();
        if (tid < 32) {
            float s = 0.f;
#pragma unroll
            for (int k2 = 0; k2 < 8; k2++) s += Sm[tid * 8 + k2];
            hmean_out[(row0 >> 7) * Hdim + j0 + tid] = s;   // raw sum; oc scales
        }
    }
}

// ---------------- splits / init -------------------------------------------
__global__ __launch_bounds__(256) void split_mat(
    const float* __restrict__ src, __half* __restrict__ hi,
    __half* __restrict__ lo, int n)
{
    int i = blockIdx.x * blockDim.x + threadIdx.x;
    if (i < n) {
        float v = src[i];
        __half h = __float2half_rn(v);
        hi[i] = h;
        if (lo) lo[i] = __float2half_rn(v - __half2float(h));
    }
}

// gate-permuted split for W [2048][K]: new_row = (r%512)*4 + r/512
__global__ __launch_bounds__(256) void split_perm(
    const float* __restrict__ src, __half* __restrict__ hi,
    __half* __restrict__ lo, int K)
{
    int i = blockIdx.x * blockDim.x + threadIdx.x;   // over 2048*K
    int r = i / K, c = i - r * K;
    int nr = ((r & 511) << 2) + (r >> 9);
    float v = src[i];
    __half h = __float2half_rn(v);
    hi[nr * K + c] = h;
    if (lo) lo[nr * K + c] = __float2half_rn(v - __half2float(h));
}

__global__ void bias_combine(const float* __restrict__ b_ih,
                             const float* __restrict__ b_hh)
{
    int i = blockIdx.x * blockDim.x + threadIdx.x;   // < 2048
    int p = ((i & 511) << 2) + (i >> 9);
    g_bias2[p] = b_ih[i] + b_hh[i];
}

__global__ void init_state(const float* __restrict__ h0, const float* __restrict__ c0)
{
    int i = blockIdx.x * blockDim.x + threadIdx.x;   // NV*Hdim grid
    g_c[i] = c0[i];
    g_h0[i] = __float2half_rn(h0[i]);
}

// ---------------- finalize: eh BN params + full ec branch ------------------
__global__ __launch_bounds__(256) void finalize_step(
    const float* __restrict__ gamma_eh, const float* __restrict__ beta_eh,
    const float* __restrict__ oneh_t,
    const float* __restrict__ W_ec, const float* __restrict__ b_ec,
    const float* __restrict__ gamma_ec, const float* __restrict__ beta_ec,
    const float* __restrict__ W_out)
{
    __shared__ float s_cnt[NCn];
    __shared__ int   s_cls[Nn];
    __shared__ float s_ec[NCn][EHn];
    __shared__ float s_contrib[NCn * ODn];

    int tid = threadIdx.x;
    {
        float s = 0.f, sq = 0.f;
        for (int b = 0; b < 128; b++) {
            s  += g_psum[b * EHn + tid];
            sq += g_psumsq[b * EHn + tid];
        }
        float m   = s * (1.f / (float)NV);
        float var = sq * (1.f / (float)NV) - m * m;
        float sc  = gamma_eh[tid] * rsqrtf(var + 1e-5f);
        g_bnscale[tid] = sc;
        g_bnshift[tid] = beta_eh[tid] - sc * m;
    }
    if (tid < NCn) {
        float cv = 0.f;
        for (int n = 0; n < Nn; n++) cv += oneh_t[n * NCn + tid];
        s_cnt[tid] = cv;
    }
    if (tid < Nn) {
        const float* r = oneh_t + tid * NCn;
        int cl = 0; float best = r[0];
#pragma unroll
        for (int k = 1; k < NCn; k++) if (r[k] > best) { best = r[k]; cl = k; }
        s_cls[tid] = cl;
    }
    __syncthreads();
    {
        int j = tid;
        float pre[NCn];
        float m = 0.f, sq = 0.f;
#pragma unroll
        for (int cl = 0; cl < NCn; cl++) {
            pre[cl] = W_ec[j * NCn + cl] + b_ec[j];
            float w = s_cnt[cl] * (1.f / (float)Nn);
            m  += w * pre[cl];
            sq += w * pre[cl] * pre[cl];
        }
        float var = sq - m * m;
        float sc  = gamma_ec[j] * rsqrtf(var + 1e-5f);
        float sh  = beta_ec[j] - sc * m;
#pragma unroll
        for (int cl = 0; cl < NCn; cl++)
            s_ec[cl][j] = fmaxf(sc * pre[cl] + sh, 0.f);
    }
    __syncthreads();
    int warp = tid >> 5, lane = tid & 31;
    for (int p = warp; p < NCn * ODn; p += 8) {
        int cl = p / ODn, od = p % ODn;
        float a = 0.f;
#pragma unroll
        for (int u = 0; u < 8; u++) {
            int j = lane + (u << 5);
            a = fmaf(s_ec[cl][j], W_out[od * (EHn + EHn) + EHn + j], a);
        }
        for (int off = 16; off; off >>= 1) a += __shfl_xor_sync(0xffffffffu, a, off);
        if (lane == 0) s_contrib[p] = a;
    }
    __syncthreads();
    if (tid < Nn) {
        int cl = s_cls[tid];
#pragma unroll
        for (int od = 0; od < ODn; od++)
            g_ncontrib[tid * ODn + od] = s_contrib[cl * ODn + od];
    }
}

// ---------------- op: bn+relu(eh) . W_out[:, :256] + ec + b_out + act ------
__global__ __launch_bounds__(256) void op_kernel(
    const float* __restrict__ W_out, const float* __restrict__ b_out,
    float* __restrict__ out, int t)
{
    int warp = threadIdx.x >> 5, lane = threadIdx.x & 31;
    int row  = (blockIdx.x << 3) + warp;
    const float* er = g_ehpre + (size_t)row * EHn;

    float a0 = 0.f, a1 = 0.f, a2 = 0.f, a3 = 0.f, a4 = 0.f;
#pragma unroll
    for (int u = 0; u < 8; u++) {
        int j = lane + (u << 5);
        float xv = fmaxf(fmaf(g_bnscale[j], er[j], g_bnshift[j]), 0.f);
        a0 = fmaf(xv, W_out[j],            a0);
        a1 = fmaf(xv, W_out[512  + j],     a1);
        a2 = fmaf(xv, W_out[1024 + j],     a2);
        a3 = fmaf(xv, W_out[1536 + j],     a3);
        a4 = fmaf(xv, W_out[2048 + j],     a4);
    }
    for (int off = 16; off; off >>= 1) {
        a0 += __shfl_xor_sync(0xffffffffu, a0, off);
        a1 += __shfl_xor_sync(0xffffffffu, a1, off);
        a2 += __shfl_xor_sync(0xffffffffu, a2, off);
        a3 += __shfl_xor_sync(0xffffffffu, a3, off);
        a4 += __shfl_xor_sync(0xffffffffu, a4, off);
    }
    if (lane < ODn) {
        int n = row >> 7, v = row & 127;
        float a = (lane == 0) ? a0 : (lane == 1) ? a1 : (lane == 2) ? a2
                : (lane == 3) ? a3 : a4;
        a += g_ncontrib[n * ODn + lane] + b_out[lane];
        if (lane == 2 || lane == 3) a = expf(a);
        else if (lane == 4)         a = tanhf(a);
        out[(((size_t)n * Tn + t) * Vn + v) * ODn + lane] = a;
    }
}

// ---------------- oc: (sum_V h / V) @ W_cls^T + b_cls ----------------------
__global__ __launch_bounds__(192) void oc_kernel(
    const float* __restrict__ hmean, const float* __restrict__ W_cls,
    const float* __restrict__ b_cls, float* __restrict__ out, int t)
{
    int n = blockIdx.x;
    int warp = threadIdx.x >> 5, lane = threadIdx.x & 31;
    if (warp < ODn) {
        float a = 0.f;
#pragma unroll
        for (int u = 0; u < 16; u++) {
            int k = lane + (u << 5);
            a = fmaf(hmean[n * Hdim + k], W_cls[warp * Hdim + k], a);
        }
        for (int off = 16; off; off >>= 1) a += __shfl_xor_sync(0xffffffffu, a, off);
        if (lane == 0)
            out[PRED_TOTAL + ((size_t)t * Nn + n) * ODn + warp] =
                a * (1.f / (float)Vn) + b_cls[warp];
    }
}

// ---------------- streams/events (created at load, before harness checkpoints)
struct StreamRes {
    cudaStream_t s2 = nullptr;
    cudaEvent_t  eG[2] = {nullptr, nullptr};
    cudaEvent_t  eH[2] = {nullptr, nullptr};
    bool ok = false;
    StreamRes() {
        if (cudaStreamCreateWithFlags(&s2, cudaStreamNonBlocking) != cudaSuccess) return;
        for (int i = 0; i < 2; i++) {
            if (cudaEventCreateWithFlags(&eG[i], cudaEventDisableTiming) != cudaSuccess) return;
            if (cudaEventCreateWithFlags(&eH[i], cudaEventDisableTiming) != cudaSuccess) return;
        }
        ok = true;
    }
};
static StreamRes g_sr;

// ---------------- host launcher --------------------------------------------
extern "C" void kernel_launch(void* const* d_in, const int* in_sizes, int n_in,
                              void* d_out, int out_size)
{
    const float* x     = (const float*)d_in[0];
    const float* h0    = (const float*)d_in[1];
    const float* c0    = (const float*)d_in[2];
    const float* oneh  = (const float*)d_in[3];
    const float* W_ih  = (const float*)d_in[4];
    const float* W_hh  = (const float*)d_in[5];
    const float* b_ih  = (const float*)d_in[6];
    const float* b_hh  = (const float*)d_in[7];
    const float* W_cls = (const float*)d_in[8];
    const float* b_cls = (const float*)d_in[9];
    const float* W_eh  = (const float*)d_in[10];
    const float* b_eh  = (const float*)d_in[11];
    const float* ga_eh = (const float*)d_in[12];
    const float* be_eh = (const float*)d_in[13];
    const float* W_ec  = (const float*)d_in[14];
    const float* b_ec  = (const float*)d_in[15];
    const float* ga_ec = (const float*)d_in[16];
    const float* be_ec = (const float*)d_in[17];
    const float* W_out = (const float*)d_in[18];
    const float* b_out = (const float*)d_in[19];
    float* out = (float*)d_out;

    cudaFuncSetAttribute(mma_gemm<0,3>, cudaFuncAttributeMaxDynamicSharedMemorySize, SMEM_M0);
    cudaFuncSetAttribute(mma_gemm<1,1>, cudaFuncAttributeMaxDynamicSharedMemorySize, SMEM_M1);
    cudaFuncSetAttribute(mma_gemm<2,2>, cudaFuncAttributeMaxDynamicSharedMemorySize, SMEM_M2);

    float *gx, *ehpre, *bias2;
    float *hmean[2];
    __half *xh, *xl, *Wihh, *Wihl, *Whhh, *Wehh, *Wehl;
    __half *hbuf[2];
    cudaGetSymbolAddress((void**)&gx,    g_gx);
    cudaGetSymbolAddress((void**)&ehpre, g_ehpre);
    cudaGetSymbolAddress((void**)&bias2, g_bias2);
    cudaGetSymbolAddress((void**)&xh,    g_x_hi);
    cudaGetSymbolAddress((void**)&xl,    g_x_lo);
    cudaGetSymbolAddress((void**)&Wihh,  g_Wih_hi);
    cudaGetSymbolAddress((void**)&Wihl,  g_Wih_lo);
    cudaGetSymbolAddress((void**)&Whhh,  g_Whh_hi);
    cudaGetSymbolAddress((void**)&Wehh,  g_Weh_hi);
    cudaGetSymbolAddress((void**)&Wehl,  g_Weh_lo);
    cudaGetSymbolAddress((void**)&hbuf[0], g_h0);
    cudaGetSymbolAddress((void**)&hbuf[1], g_h1);
    cudaGetSymbolAddress((void**)&hmean[0], g_hmean0);
    cudaGetSymbolAddress((void**)&hmean[1], g_hmean1);

    // init + operand splits (stream 0)
    init_state<<<(NV * Hdim) / 256, 256>>>(h0, c0);
    split_mat<<<(NV * Cdim) / 256, 256>>>(x, xh, xl, NV * Cdim);
    split_perm<<<(G4H * Cdim) / 256, 256>>>(W_ih, Wihh, Wihl, Cdim);
    split_perm<<<(G4H * Hdim) / 256, 256>>>(W_hh, Whhh, nullptr, Hdim);
    split_mat<<<(EHn * Hdim) / 256, 256>>>(W_eh, Wehh, Wehl, EHn * Hdim);
    bias_combine<<<G4H / 256, 256>>>(b_ih, b_hh);

    // gx = x @ Wih_perm^T + (b_ih + b_hh)_perm   (step-invariant, 3-term)
    mma_gemm<0,3><<<dim3(G4H / 128, NV / 128), 256, SMEM_M0>>>(
        xh, xl, Wihh, Wihl, gx, bias2, nullptr, nullptr, nullptr,
        G4H, Cdim);

    const bool dual = g_sr.ok;
    cudaStream_t sH = dual ? g_sr.s2 : (cudaStream_t)0;

    for (int t = 0; t < Tn; t++) {
        const int rb = t & 1, wb = rb ^ 1;

        if (dual && t >= 2) cudaStreamWaitEvent(0, g_sr.eH[t & 1], 0);

        // fused: gates = gx + h @ Whh_perm^T -> LSTM update -> h,c (+ hmean)
        mma_gemm<1,1><<<dim3(G4H / 128, NV / 128), 256, SMEM_M1>>>(
            hbuf[rb], nullptr, Whhh, nullptr, nullptr, nullptr, gx,
            hbuf[wb], hmean[wb], G4H, Hdim);

        if (dual) {
            cudaEventRecord(g_sr.eG[t & 1], 0);
            cudaStreamWaitEvent(sH, g_sr.eG[t & 1], 0);
        }

        // head chain (second stream when available)
        oc_kernel<<<Nn, 192, 0, sH>>>(hmean[wb], W_cls, b_cls, out, t);
        mma_gemm<2,2><<<dim3(EHn / 128, NV / 128), 256, SMEM_M2, sH>>>(
            hbuf[wb], nullptr, Wehh, Wehl, ehpre, b_eh,
            nullptr, nullptr, nullptr, EHn, Hdim);
        finalize_step<<<1, 256, 0, sH>>>(ga_eh, be_eh, oneh + (size_t)t * Nn * NCn,
                                         W_ec, b_ec, ga_ec, be_ec, W_out);
        op_kernel<<<NV / 8, 256, 0, sH>>>(W_out, b_out, out, t);

        if (dual) cudaEventRecord(g_sr.eH[t & 1], sH);
    }

    if (dual) {
        cudaStreamWaitEvent(0, g_sr.eH[0], 0);
        cudaStreamWaitEvent(0, g_sr.eH[1], 0);
    }
}

// round 10
// speedup vs baseline: 2.3137x; 1.0770x over previous
#include <cuda_runtime.h>
#include <cuda_fp16.h>
#include <math.h>
#include <stdint.h>

// ---------------- problem constants ----------------
#define Nn   128
#define Vn   128
#define NV   16384          // N*V rows
#define Cdim 256
#define Hdim 512
#define G4H  2048           // 4*H
#define Tn   12
#define NCn  5
#define EHn  256
#define ODn  5
#define PRED_TOTAL (Nn*Tn*Vn*ODn)   // 983040

// SMEM tile geometry: tiles of 128 rows x 32 fp16, 80B padded rows
#define KCH      32
#define TROW_B   80
#define TILE_B   (128 * TROW_B)           // 10240 bytes
#define OFF_A    0
#define OFF_BHI  10240
#define OFF_BLO  20480
#define OFF_ALO  30720
#define SMEM_M0  81920                    // 2 stages x 4 tiles (3-term)
#define SMEM_M1  68608                    // max(2x2 tiles, LSTM staging 67584+1024)
#define SMEM_M2  40960                    // 2 stages x 2 tiles (1-term)

// ---------------- device scratch (no allocations allowed) ----------------
__device__ __half g_gx[NV * G4H];       // fp16: x @ W_ih^T + biases (gate-permuted)
__device__ float g_c[NV * Hdim];
__device__ float g_ehpre[NV * EHn];
__device__ float g_psum[128 * EHn];
__device__ float g_psumsq[128 * EHn];
__device__ float g_bnscale[EHn];
__device__ float g_bnshift[EHn];
__device__ float g_ncontrib[Nn * NCn];
__device__ float g_bias2[G4H];          // permuted b_ih + b_hh
__device__ float g_hmean0[Nn * Hdim];   // per-n column sums of h (double buffered)
__device__ float g_hmean1[Nn * Hdim];

// fp16 operands; h is single fp16 (double buffered)
__device__ __half g_h0[NV * Hdim];
__device__ __half g_h1[NV * Hdim];
__device__ __half g_x_hi[NV * Cdim];
__device__ __half g_x_lo[NV * Cdim];
__device__ __half g_Wih_hi[G4H * Cdim];   // gate-permuted rows
__device__ __half g_Wih_lo[G4H * Cdim];
__device__ __half g_Whh_hi[G4H * Hdim];   // gate-permuted rows (single term)
__device__ __half g_Weh_hi[EHn * Hdim];

// ---------------- mma.sync / ldmatrix / cp.async helpers -------------------
__device__ __forceinline__ uint32_t smem_u32(const void* p) {
    uint32_t a;
    asm("{ .reg .u64 t; cvta.to.shared.u64 t, %1; cvt.u32.u64 %0, t; }" : "=r"(a) : "l"(p));
    return a;
}
__device__ __forceinline__ void ldsm_x4(uint32_t& r0, uint32_t& r1, uint32_t& r2,
                                        uint32_t& r3, uint32_t addr) {
    asm volatile("ldmatrix.sync.aligned.m8n8.x4.shared.b16 {%0,%1,%2,%3}, [%4];"
                 : "=r"(r0), "=r"(r1), "=r"(r2), "=r"(r3) : "r"(addr));
}
__device__ __forceinline__ void mma_f16(float* c, const uint32_t* a,
                                        uint32_t b0, uint32_t b1) {
    asm volatile(
        "mma.sync.aligned.m16n8k16.row.col.f32.f16.f16.f32 "
        "{%0,%1,%2,%3}, {%4,%5,%6,%7}, {%8,%9}, {%0,%1,%2,%3};"
        : "+f"(c[0]), "+f"(c[1]), "+f"(c[2]), "+f"(c[3])
        : "r"(a[0]), "r"(a[1]), "r"(a[2]), "r"(a[3]), "r"(b0), "r"(b1));
}
__device__ __forceinline__ void cp16(uint32_t dst, const void* src) {
    asm volatile("cp.async.cg.shared.global [%0], [%1], 16;" :: "r"(dst), "l"(src));
}
#define CP_COMMIT() asm volatile("cp.async.commit_group;" ::: "memory")
#define CP_WAIT1()  asm volatile("cp.async.wait_group 1;" ::: "memory")
#define CP_WAIT0()  asm volatile("cp.async.wait_group 0;" ::: "memory")

// issue one k-chunk into a stage: A + B_hi always, B_lo if NT>=2, A_lo if NT==3
template<int NT>
__device__ __forceinline__ void load_chunk(
    uint32_t st, const __half* A0, const __half* A1,
    const __half* B0, const __half* B1, int K, int kk, int tid)
{
#pragma unroll
    for (int it = 0; it < 2; it++) {
        int f = tid + (it << 8);          // 0..511
        int r = f >> 2, c = f & 3;
        uint32_t off = (uint32_t)r * TROW_B + (uint32_t)c * 16;
        size_t src = (size_t)r * K + kk + (c << 3);
        cp16(st + OFF_A   + off, A0 + src);
        cp16(st + OFF_BHI + off, B0 + src);
        if (NT >= 2) cp16(st + OFF_BLO + off, B1 + src);
        if (NT == 3) cp16(st + OFF_ALO + off, A1 + src);
    }
}

// ---------------- core GEMM: C[M,Ntot] = A @ B^T (1..3 precision terms) ----
// Block tile 128x128, warp tile 64x32 (2x4 warp grid), 2-stage k32 pipeline.
// MODE 0: Ch(half) = acc + bias (gx GEMM, NT=3)
// MODE 1: fused LSTM epilogue (reads fp16 gx w/ biases), writes g_c + next h
//         + per-(n, column) h sums into hmean_out. NT=1.
// MODE 2: C(float) = acc + bias (ehpre, NT=1) + fused BN stats.
template<int MODE, int NT>
__global__ __launch_bounds__(256, 2) void mma_gemm(
    const __half* __restrict__ Ahi, const __half* __restrict__ Alo,
    const __half* __restrict__ Bhi, const __half* __restrict__ Blo,
    float* __restrict__ C, __half* __restrict__ Ch,
    const float* __restrict__ bias,
    const __half* __restrict__ gx,
    __half* __restrict__ whi,
    float* __restrict__ hmean_out,
    int Ntot, int K)
{
    constexpr uint32_t STAGE_B = (NT == 1 ? 2 : (NT == 2 ? 3 : 4)) * TILE_B;
    extern __shared__ char smem[];
    const uint32_t sb = smem_u32(smem);
    const int tid  = threadIdx.x;
    const int wid  = tid >> 5;
    const int lane = tid & 31;
    const int row0 = blockIdx.y << 7;
    const int col0 = blockIdx.x << 7;

    const int am0 = (wid & 1) * 64;    // warp m-offset in tile
    const int bn0 = (wid >> 1) * 32;   // warp n-offset in tile

    const uint32_t lrow = lane & 15, lcol = lane >> 4;
    const int g  = lane >> 2;
    const int t2 = (lane & 3) << 1;

    const __half* A0 = Ahi + (size_t)row0 * K;
    const __half* A1 = (NT == 3) ? (Alo + (size_t)row0 * K) : nullptr;
    const __half* B0 = Bhi + (size_t)col0 * K;
    const __half* B1 = (NT >= 2) ? (Blo + (size_t)col0 * K) : nullptr;

    float acc[4][4][4];
#pragma unroll
    for (int mf = 0; mf < 4; mf++)
#pragma unroll
        for (int nf = 0; nf < 4; nf++)
#pragma unroll
            for (int e = 0; e < 4; e++) acc[mf][nf][e] = 0.f;

    const int nch = K / KCH;

    // prologue: stage 0 <- chunk 0
    load_chunk<NT>(sb, A0, A1, B0, B1, K, 0, tid);
    CP_COMMIT();

    for (int kc = 0; kc < nch; kc++) {
        if (kc + 1 < nch) {
            load_chunk<NT>(sb + (uint32_t)((kc + 1) & 1) * STAGE_B,
                           A0, A1, B0, B1, K, (kc + 1) * KCH, tid);
            CP_COMMIT();
            CP_WAIT1();
        } else {
            CP_WAIT0();
        }
        __syncthreads();

        const uint32_t st  = sb + (uint32_t)(kc & 1) * STAGE_B;
        const uint32_t sA  = st + OFF_A;
        const uint32_t sB0 = st + OFF_BHI;
        const uint32_t sB1 = st + OFF_BLO;

#pragma unroll
        for (int ks = 0; ks < 2; ks++) {
            uint32_t a[4][4], bh[2][4], bl[2][4];
            const uint32_t kb = (uint32_t)(ks * 32 + lcol * 16);
#pragma unroll
            for (int mf = 0; mf < 4; mf++) {
                uint32_t ad = sA + (uint32_t)(am0 + mf * 16 + lrow) * TROW_B + kb;
                ldsm_x4(a[mf][0], a[mf][1], a[mf][2], a[mf][3], ad);
            }
#pragma unroll
            for (int ng = 0; ng < 2; ng++) {
                uint32_t roff = (uint32_t)(bn0 + ng * 16 + lrow) * TROW_B + kb;
                ldsm_x4(bh[ng][0], bh[ng][1], bh[ng][2], bh[ng][3], sB0 + roff);
                if (NT >= 2)
                    ldsm_x4(bl[ng][0], bl[ng][1], bl[ng][2], bl[ng][3], sB1 + roff);
            }
#pragma unroll
            for (int mf = 0; mf < 4; mf++)
#pragma unroll
                for (int nf = 0; nf < 4; nf++) {
                    int ng = nf >> 1, hf = nf & 1;
                    mma_f16(acc[mf][nf], a[mf], bh[ng][hf], bh[ng][hf + 2]);
                    if (NT >= 2)
                        mma_f16(acc[mf][nf], a[mf], bl[ng][hf], bl[ng][hf + 2]);
                }
            if (NT == 3) {
#pragma unroll
                for (int mf = 0; mf < 4; mf++) {
                    uint32_t ad = st + OFF_ALO
                                + (uint32_t)(am0 + mf * 16 + lrow) * TROW_B + kb;
                    ldsm_x4(a[mf][0], a[mf][1], a[mf][2], a[mf][3], ad);
                }
#pragma unroll
                for (int mf = 0; mf < 4; mf++)
#pragma unroll
                    for (int nf = 0; nf < 4; nf++) {
                        int ng = nf >> 1, hf = nf & 1;
                        mma_f16(acc[mf][nf], a[mf], bh[ng][hf], bh[ng][hf + 2]);
                    }
            }
        }
        __syncthreads();
    }

    if (MODE == 0) {
        // ---- gx store: Ch(half) = acc + bias ----
#pragma unroll
        for (int mf = 0; mf < 4; mf++) {
            int rg = row0 + am0 + mf * 16 + g;
#pragma unroll
            for (int nf = 0; nf < 4; nf++) {
                int cg = col0 + bn0 + nf * 8 + t2;
                float b0 = bias[cg], b1 = bias[cg + 1];
                __half2 v0 = __floats2half2_rn(acc[mf][nf][0] + b0, acc[mf][nf][1] + b1);
                __half2 v1 = __floats2half2_rn(acc[mf][nf][2] + b0, acc[mf][nf][3] + b1);
                *(__half2*)(Ch + (size_t)rg * Ntot + cg) = v0;
                *(__half2*)(Ch + (size_t)(rg + 8) * Ntot + cg) = v1;
            }
        }
    } else if (MODE == 2) {
        // ---- ehpre store + BN column stats ----
        float sc_[4][2], sq_[4][2];
#pragma unroll
        for (int nf = 0; nf < 4; nf++) { sc_[nf][0] = sc_[nf][1] = 0.f;
                                         sq_[nf][0] = sq_[nf][1] = 0.f; }
#pragma unroll
        for (int mf = 0; mf < 4; mf++) {
            int rg = row0 + am0 + mf * 16 + g;
#pragma unroll
            for (int nf = 0; nf < 4; nf++) {
                int cg = col0 + bn0 + nf * 8 + t2;
                float b0 = bias[cg], b1 = bias[cg + 1];
                float v00 = acc[mf][nf][0] + b0, v01 = acc[mf][nf][1] + b1;
                float v10 = acc[mf][nf][2] + b0, v11 = acc[mf][nf][3] + b1;
                *(float2*)(C + (size_t)rg * Ntot + cg) = make_float2(v00, v01);
                *(float2*)(C + (size_t)(rg + 8) * Ntot + cg) = make_float2(v10, v11);
                sc_[nf][0] += v00 + v10; sq_[nf][0] += v00 * v00 + v10 * v10;
                sc_[nf][1] += v01 + v11; sq_[nf][1] += v01 * v01 + v11 * v11;
            }
        }
        float2* S2 = (float2*)smem;    // [128 cols][16 slots] = 16KB
        int slot = ((wid & 1) << 3) + g;
#pragma unroll
        for (int nf = 0; nf < 4; nf++) {
            int cc0 = bn0 + nf * 8 + t2;
            S2[cc0 * 16 + slot]       = make_float2(sc_[nf][0], sq_[nf][0]);
            S2[(cc0 + 1) * 16 + slot] = make_float2(sc_[nf][1], sq_[nf][1]);
        }
        __syncthreads();
        if (tid < 128) {
            float s = 0.f, q = 0.f;
#pragma unroll
            for (int k2 = 0; k2 < 16; k2++) {
                float2 v = S2[tid * 16 + k2];
                s += v.x; q += v.y;
            }
            int rb = row0 >> 7;
            g_psum[rb * EHn + col0 + tid]   = s;
            g_psumsq[rb * EHn + col0 + tid] = q;
        }
    } else {
        // ---- LSTM epilogue: stage acc tile in smem, then elementwise ----
        float* Sf = (float*)smem;   // [128][132] = 67584 B
#pragma unroll
        for (int mf = 0; mf < 4; mf++) {
            int rr = am0 + mf * 16 + g;
#pragma unroll
            for (int nf = 0; nf < 4; nf++) {
                int cc = bn0 + nf * 8 + t2;
                Sf[rr * 132 + cc]           = acc[mf][nf][0];
                Sf[rr * 132 + cc + 1]       = acc[mf][nf][1];
                Sf[(rr + 8) * 132 + cc]     = acc[mf][nf][2];
                Sf[(rr + 8) * 132 + cc + 1] = acc[mf][nf][3];
            }
        }
        __syncthreads();

        const int j0 = col0 >> 2;      // 32 gate-quadruples per tile
        float hsum = 0.f;
#pragma unroll
        for (int it = 0; it < 16; it++) {
            int item = tid + (it << 8);            // 0..4095
            int r = item >> 5, q = item & 31;
            int grow = row0 + r;
            float4 gv = *(const float4*)(Sf + r * 132 + (q << 2));
            // gx is fp16: load 4 halves (8 bytes)
            uint2 gxraw = *(const uint2*)(gx + (size_t)grow * G4H + col0 + (q << 2));
            float2 gx01 = __half22float2(*(const __half2*)&gxraw.x);
            float2 gx23 = __half22float2(*(const __half2*)&gxraw.y);
            float gi = gv.x + gx01.x;
            float gf = gv.y + gx01.y;
            float gg = gv.z + gx23.x;
            float go = gv.w + gx23.y;
            float si = 1.f / (1.f + expf(-gi));
            float sf = 1.f / (1.f + expf(-gf));
            float so = 1.f / (1.f + expf(-go));
            size_t idx = (size_t)grow * Hdim + j0 + q;
            float cn = sf * g_c[idx] + si * tanhf(gg);
            g_c[idx] = cn;
            float hv = so * tanhf(cn);
            hsum += hv;
            whi[idx] = __float2half_rn(hv);
        }
        // per-(n, column) h sums: this CTA's 128 rows are exactly one n
        float* Sm = (float*)(smem + 67584);   // [32 q][8 warp-slots] = 1KB
        Sm[(tid & 31) * 8 + (tid >> 5)] = hsum;
        __syncthreads();
        if (tid < 32) {
            float s = 0.f;
#pragma unroll
            for (int k2 = 0; k2 < 8; k2++) s += Sm[tid * 8 + k2];
            hmean_out[(row0 >> 7) * Hdim + j0 + tid] = s;   // raw sum; oc scales
        }
    }
}

// ---------------- splits / init -------------------------------------------
__global__ __launch_bounds__(256) void split_mat(
    const float* __restrict__ src, __half* __restrict__ hi,
    __half* __restrict__ lo, int n)
{
    int i = blockIdx.x * blockDim.x + threadIdx.x;
    if (i < n) {
        float v = src[i];
        __half h = __float2half_rn(v);
        hi[i] = h;
        if (lo) lo[i] = __float2half_rn(v - __half2float(h));
    }
}

// gate-permuted split for W [2048][K]: new_row = (r%512)*4 + r/512
__global__ __launch_bounds__(256) void split_perm(
    const float* __restrict__ src, __half* __restrict__ hi,
    __half* __restrict__ lo, int K)
{
    int i = blockIdx.x * blockDim.x + threadIdx.x;   // over 2048*K
    int r = i / K, c = i - r * K;
    int nr = ((r & 511) << 2) + (r >> 9);
    float v = src[i];
    __half h = __float2half_rn(v);
    hi[nr * K + c] = h;
    if (lo) lo[nr * K + c] = __float2half_rn(v - __half2float(h));
}

__global__ void bias_combine(const float* __restrict__ b_ih,
                             const float* __restrict__ b_hh)
{
    int i = blockIdx.x * blockDim.x + threadIdx.x;   // < 2048
    int p = ((i & 511) << 2) + (i >> 9);
    g_bias2[p] = b_ih[i] + b_hh[i];
}

__global__ void init_state(const float* __restrict__ h0, const float* __restrict__ c0)
{
    int i = blockIdx.x * blockDim.x + threadIdx.x;   // NV*Hdim grid
    g_c[i] = c0[i];
    g_h0[i] = __float2half_rn(h0[i]);
}

// ---------------- finalize: eh BN params + full ec branch ------------------
__global__ __launch_bounds__(256) void finalize_step(
    const float* __restrict__ gamma_eh, const float* __restrict__ beta_eh,
    const float* __restrict__ oneh_t,
    const float* __restrict__ W_ec, const float* __restrict__ b_ec,
    const float* __restrict__ gamma_ec, const float* __restrict__ beta_ec,
    const float* __restrict__ W_out)
{
    __shared__ float s_cnt[NCn];
    __shared__ int   s_cls[Nn];
    __shared__ float s_ec[NCn][EHn];
    __shared__ float s_contrib[NCn * ODn];

    int tid = threadIdx.x;
    {
        float s = 0.f, sq = 0.f;
        for (int b = 0; b < 128; b++) {
            s  += g_psum[b * EHn + tid];
            sq += g_psumsq[b * EHn + tid];
        }
        float m   = s * (1.f / (float)NV);
        float var = sq * (1.f / (float)NV) - m * m;
        float sc  = gamma_eh[tid] * rsqrtf(var + 1e-5f);
        g_bnscale[tid] = sc;
        g_bnshift[tid] = beta_eh[tid] - sc * m;
    }
    if (tid < NCn) {
        float cv = 0.f;
        for (int n = 0; n < Nn; n++) cv += oneh_t[n * NCn + tid];
        s_cnt[tid] = cv;
    }
    if (tid < Nn) {
        const float* r = oneh_t + tid * NCn;
        int cl = 0; float best = r[0];
#pragma unroll
        for (int k = 1; k < NCn; k++) if (r[k] > best) { best = r[k]; cl = k; }
        s_cls[tid] = cl;
    }
    __syncthreads();
    {
        int j = tid;
        float pre[NCn];
        float m = 0.f, sq = 0.f;
#pragma unroll
        for (int cl = 0; cl < NCn; cl++) {
            pre[cl] = W_ec[j * NCn + cl] + b_ec[j];
            float w = s_cnt[cl] * (1.f / (float)Nn);
            m  += w * pre[cl];
            sq += w * pre[cl] * pre[cl];
        }
        float var = sq - m * m;
        float sc  = gamma_ec[j] * rsqrtf(var + 1e-5f);
        float sh  = beta_ec[j] - sc * m;
#pragma unroll
        for (int cl = 0; cl < NCn; cl++)
            s_ec[cl][j] = fmaxf(sc * pre[cl] + sh, 0.f);
    }
    __syncthreads();
    int warp = tid >> 5, lane = tid & 31;
    for (int p = warp; p < NCn * ODn; p += 8) {
        int cl = p / ODn, od = p % ODn;
        float a = 0.f;
#pragma unroll
        for (int u = 0; u < 8; u++) {
            int j = lane + (u << 5);
            a = fmaf(s_ec[cl][j], W_out[od * (EHn + EHn) + EHn + j], a);
        }
        for (int off = 16; off; off >>= 1) a += __shfl_xor_sync(0xffffffffu, a, off);
        if (lane == 0) s_contrib[p] = a;
    }
    __syncthreads();
    if (tid < Nn) {
        int cl = s_cls[tid];
#pragma unroll
        for (int od = 0; od < ODn; od++)
            g_ncontrib[tid * ODn + od] = s_contrib[cl * ODn + od];
    }
}

// ---------------- op: bn+relu(eh) . W_out[:, :256] + ec + b_out + act ------
__global__ __launch_bounds__(256) void op_kernel(
    const float* __restrict__ W_out, const float* __restrict__ b_out,
    float* __restrict__ out, int t)
{
    int warp = threadIdx.x >> 5, lane = threadIdx.x & 31;
    int row  = (blockIdx.x << 3) + warp;
    const float* er = g_ehpre + (size_t)row * EHn;

    float a0 = 0.f, a1 = 0.f, a2 = 0.f, a3 = 0.f, a4 = 0.f;
#pragma unroll
    for (int u = 0; u < 8; u++) {
        int j = lane + (u << 5);
        float xv = fmaxf(fmaf(g_bnscale[j], er[j], g_bnshift[j]), 0.f);
        a0 = fmaf(xv, W_out[j],            a0);
        a1 = fmaf(xv, W_out[512  + j],     a1);
        a2 = fmaf(xv, W_out[1024 + j],     a2);
        a3 = fmaf(xv, W_out[1536 + j],     a3);
        a4 = fmaf(xv, W_out[2048 + j],     a4);
    }
    for (int off = 16; off; off >>= 1) {
        a0 += __shfl_xor_sync(0xffffffffu, a0, off);
        a1 += __shfl_xor_sync(0xffffffffu, a1, off);
        a2 += __shfl_xor_sync(0xffffffffu, a2, off);
        a3 += __shfl_xor_sync(0xffffffffu, a3, off);
        a4 += __shfl_xor_sync(0xffffffffu, a4, off);
    }
    if (lane < ODn) {
        int n = row >> 7, v = row & 127;
        float a = (lane == 0) ? a0 : (lane == 1) ? a1 : (lane == 2) ? a2
                : (lane == 3) ? a3 : a4;
        a += g_ncontrib[n * ODn + lane] + b_out[lane];
        if (lane == 2 || lane == 3) a = expf(a);
        else if (lane == 4)         a = tanhf(a);
        out[(((size_t)n * Tn + t) * Vn + v) * ODn + lane] = a;
    }
}

// ---------------- oc: (sum_V h / V) @ W_cls^T + b_cls ----------------------
__global__ __launch_bounds__(192) void oc_kernel(
    const float* __restrict__ hmean, const float* __restrict__ W_cls,
    const float* __restrict__ b_cls, float* __restrict__ out, int t)
{
    int n = blockIdx.x;
    int warp = threadIdx.x >> 5, lane = threadIdx.x & 31;
    if (warp < ODn) {
        float a = 0.f;
#pragma unroll
        for (int u = 0; u < 16; u++) {
            int k = lane + (u << 5);
            a = fmaf(hmean[n * Hdim + k], W_cls[warp * Hdim + k], a);
        }
        for (int off = 16; off; off >>= 1) a += __shfl_xor_sync(0xffffffffu, a, off);
        if (lane == 0)
            out[PRED_TOTAL + ((size_t)t * Nn + n) * ODn + warp] =
                a * (1.f / (float)Vn) + b_cls[warp];
    }
}

// ---------------- streams/events (created at load, before harness checkpoints)
struct StreamRes {
    cudaStream_t s2 = nullptr;
    cudaEvent_t  eG[2] = {nullptr, nullptr};
    cudaEvent_t  eH[2] = {nullptr, nullptr};
    bool ok = false;
    StreamRes() {
        if (cudaStreamCreateWithFlags(&s2, cudaStreamNonBlocking) != cudaSuccess) return;
        for (int i = 0; i < 2; i++) {
            if (cudaEventCreateWithFlags(&eG[i], cudaEventDisableTiming) != cudaSuccess) return;
            if (cudaEventCreateWithFlags(&eH[i], cudaEventDisableTiming) != cudaSuccess) return;
        }
        ok = true;
    }
};
static StreamRes g_sr;

// ---------------- host launcher --------------------------------------------
extern "C" void kernel_launch(void* const* d_in, const int* in_sizes, int n_in,
                              void* d_out, int out_size)
{
    const float* x     = (const float*)d_in[0];
    const float* h0    = (const float*)d_in[1];
    const float* c0    = (const float*)d_in[2];
    const float* oneh  = (const float*)d_in[3];
    const float* W_ih  = (const float*)d_in[4];
    const float* W_hh  = (const float*)d_in[5];
    const float* b_ih  = (const float*)d_in[6];
    const float* b_hh  = (const float*)d_in[7];
    const float* W_cls = (const float*)d_in[8];
    const float* b_cls = (const float*)d_in[9];
    const float* W_eh  = (const float*)d_in[10];
    const float* b_eh  = (const float*)d_in[11];
    const float* ga_eh = (const float*)d_in[12];
    const float* be_eh = (const float*)d_in[13];
    const float* W_ec  = (const float*)d_in[14];
    const float* b_ec  = (const float*)d_in[15];
    const float* ga_ec = (const float*)d_in[16];
    const float* be_ec = (const float*)d_in[17];
    const float* W_out = (const float*)d_in[18];
    const float* b_out = (const float*)d_in[19];
    float* out = (float*)d_out;

    cudaFuncSetAttribute(mma_gemm<0,3>, cudaFuncAttributeMaxDynamicSharedMemorySize, SMEM_M0);
    cudaFuncSetAttribute(mma_gemm<1,1>, cudaFuncAttributeMaxDynamicSharedMemorySize, SMEM_M1);
    cudaFuncSetAttribute(mma_gemm<2,1>, cudaFuncAttributeMaxDynamicSharedMemorySize, SMEM_M2);

    float *ehpre, *bias2;
    float *hmean[2];
    __half *gx;
    __half *xh, *xl, *Wihh, *Wihl, *Whhh, *Wehh;
    __half *hbuf[2];
    cudaGetSymbolAddress((void**)&gx,    g_gx);
    cudaGetSymbolAddress((void**)&ehpre, g_ehpre);
    cudaGetSymbolAddress((void**)&bias2, g_bias2);
    cudaGetSymbolAddress((void**)&xh,    g_x_hi);
    cudaGetSymbolAddress((void**)&xl,    g_x_lo);
    cudaGetSymbolAddress((void**)&Wihh,  g_Wih_hi);
    cudaGetSymbolAddress((void**)&Wihl,  g_Wih_lo);
    cudaGetSymbolAddress((void**)&Whhh,  g_Whh_hi);
    cudaGetSymbolAddress((void**)&Wehh,  g_Weh_hi);
    cudaGetSymbolAddress((void**)&hbuf[0], g_h0);
    cudaGetSymbolAddress((void**)&hbuf[1], g_h1);
    cudaGetSymbolAddress((void**)&hmean[0], g_hmean0);
    cudaGetSymbolAddress((void**)&hmean[1], g_hmean1);

    // init + operand splits (stream 0)
    init_state<<<(NV * Hdim) / 256, 256>>>(h0, c0);
    split_mat<<<(NV * Cdim) / 256, 256>>>(x, xh, xl, NV * Cdim);
    split_perm<<<(G4H * Cdim) / 256, 256>>>(W_ih, Wihh, Wihl, Cdim);
    split_perm<<<(G4H * Hdim) / 256, 256>>>(W_hh, Whhh, nullptr, Hdim);
    split_mat<<<(EHn * Hdim) / 256, 256>>>(W_eh, Wehh, nullptr, EHn * Hdim);
    bias_combine<<<G4H / 256, 256>>>(b_ih, b_hh);

    // gx = x @ Wih_perm^T + (b_ih + b_hh)_perm   (step-invariant, 3-term, fp16 out)
    mma_gemm<0,3><<<dim3(G4H / 128, NV / 128), 256, SMEM_M0>>>(
        xh, xl, Wihh, Wihl, nullptr, gx, bias2, nullptr, nullptr, nullptr,
        G4H, Cdim);

    const bool dual = g_sr.ok;
    cudaStream_t sH = dual ? g_sr.s2 : (cudaStream_t)0;

    for (int t = 0; t < Tn; t++) {
        const int rb = t & 1, wb = rb ^ 1;

        if (dual && t >= 2) cudaStreamWaitEvent(0, g_sr.eH[t & 1], 0);

        // fused: gates = gx + h @ Whh_perm^T -> LSTM update -> h,c (+ hmean)
        mma_gemm<1,1><<<dim3(G4H / 128, NV / 128), 256, SMEM_M1>>>(
            hbuf[rb], nullptr, Whhh, nullptr, nullptr, nullptr, nullptr, gx,
            hbuf[wb], hmean[wb], G4H, Hdim);

        if (dual) {
            cudaEventRecord(g_sr.eG[t & 1], 0);
            cudaStreamWaitEvent(sH, g_sr.eG[t & 1], 0);
        }

        // head chain (second stream when available)
        oc_kernel<<<Nn, 192, 0, sH>>>(hmean[wb], W_cls, b_cls, out, t);
        mma_gemm<2,1><<<dim3(EHn / 128, NV / 128), 256, SMEM_M2, sH>>>(
            hbuf[wb], nullptr, Wehh, nullptr, ehpre, nullptr, b_eh,
            nullptr, nullptr, nullptr, EHn, Hdim);
        finalize_step<<<1, 256, 0, sH>>>(ga_eh, be_eh, oneh + (size_t)t * Nn * NCn,
                                         W_ec, b_ec, ga_ec, be_ec, W_out);
        op_kernel<<<NV / 8, 256, 0, sH>>>(W_out, b_out, out, t);

        if (dual) cudaEventRecord(g_sr.eH[t & 1], sH);
    }

    if (dual) {
        cudaStreamWaitEvent(0, g_sr.eH[0], 0);
        cudaStreamWaitEvent(0, g_sr.eH[1], 0);
    }
}

// round 11
// speedup vs baseline: 2.6197x; 1.1323x over previous
#include <cuda_runtime.h>
#include <cuda_fp16.h>
#include <math.h>
#include <stdint.h>

// ---------------- problem constants ----------------
#define Nn   128
#define Vn   128
#define NV   16384          // N*V rows
#define Cdim 256
#define Hdim 512
#define G4H  2048           // 4*H
#define Tn   12
#define NCn  5
#define EHn  256
#define ODn  5
#define PRED_TOTAL (Nn*Tn*Vn*ODn)   // 983040

// SMEM tile geometry: tiles of 128 rows x 32 fp16, 80B padded rows
#define KCH      32
#define TROW_B   80
#define TILE_B   (128 * TROW_B)           // 10240 bytes
#define OFF_A    0
#define OFF_BHI  10240
#define OFF_BLO  20480
#define OFF_ALO  30720
#define SMEM_M0  81920                    // 2 stages x 4 tiles (3-term)
#define SMEM_M1  68608                    // max(2x2 tiles, LSTM staging 67584+1024)
#define SMEM_M2  40960                    // 2 stages x 2 tiles (1-term)

// ---------------- device scratch (no allocations allowed) ----------------
__device__ __half g_gx[NV * G4H];       // fp16: x @ W_ih^T + biases (gate-permuted)
__device__ float g_c[NV * Hdim];
__device__ float g_ehpre[NV * EHn];
__device__ float g_psum[128 * EHn];
__device__ float g_psumsq[128 * EHn];
__device__ float g_bnscale[EHn];
__device__ float g_bnshift[EHn];
__device__ float g_ncontrib[Nn * NCn];
__device__ float g_bias2[G4H];          // permuted b_ih + b_hh
__device__ float g_hmean0[Nn * Hdim];   // per-n column sums of h (double buffered)
__device__ float g_hmean1[Nn * Hdim];

// fp16 operands; h is single fp16 (double buffered)
__device__ __half g_h0[NV * Hdim];
__device__ __half g_h1[NV * Hdim];
__device__ __half g_x_hi[NV * Cdim];
__device__ __half g_x_lo[NV * Cdim];
__device__ __half g_Wih_hi[G4H * Cdim];   // gate-permuted rows
__device__ __half g_Wih_lo[G4H * Cdim];
__device__ __half g_Whh_hi[G4H * Hdim];   // gate-permuted rows (single term)
__device__ __half g_Weh_hi[EHn * Hdim];

// ---------------- mma.sync / ldmatrix / cp.async helpers -------------------
__device__ __forceinline__ uint32_t smem_u32(const void* p) {
    uint32_t a;
    asm("{ .reg .u64 t; cvta.to.shared.u64 t, %1; cvt.u32.u64 %0, t; }" : "=r"(a) : "l"(p));
    return a;
}
__device__ __forceinline__ void ldsm_x4(uint32_t& r0, uint32_t& r1, uint32_t& r2,
                                        uint32_t& r3, uint32_t addr) {
    asm volatile("ldmatrix.sync.aligned.m8n8.x4.shared.b16 {%0,%1,%2,%3}, [%4];"
                 : "=r"(r0), "=r"(r1), "=r"(r2), "=r"(r3) : "r"(addr));
}
__device__ __forceinline__ void mma_f16(float* c, const uint32_t* a,
                                        uint32_t b0, uint32_t b1) {
    asm volatile(
        "mma.sync.aligned.m16n8k16.row.col.f32.f16.f16.f32 "
        "{%0,%1,%2,%3}, {%4,%5,%6,%7}, {%8,%9}, {%0,%1,%2,%3};"
        : "+f"(c[0]), "+f"(c[1]), "+f"(c[2]), "+f"(c[3])
        : "r"(a[0]), "r"(a[1]), "r"(a[2]), "r"(a[3]), "r"(b0), "r"(b1));
}
__device__ __forceinline__ void cp16(uint32_t dst, const void* src) {
    asm volatile("cp.async.cg.shared.global [%0], [%1], 16;" :: "r"(dst), "l"(src));
}
#define CP_COMMIT() asm volatile("cp.async.commit_group;" ::: "memory")
#define CP_WAIT1()  asm volatile("cp.async.wait_group 1;" ::: "memory")
#define CP_WAIT0()  asm volatile("cp.async.wait_group 0;" ::: "memory")

// HW tanh (MUFU.TANH, sm_75+); sigmoid built on it: 1 MUFU + 1 FMA
__device__ __forceinline__ float ftanh(float x) {
    float y;
    asm("tanh.approx.f32 %0, %1;" : "=f"(y) : "f"(x));
    return y;
}
__device__ __forceinline__ float fsig(float x) {
    return fmaf(ftanh(0.5f * x), 0.5f, 0.5f);
}

// issue one k-chunk into a stage: A + B_hi always, B_lo if NT>=2, A_lo if NT==3
template<int NT>
__device__ __forceinline__ void load_chunk(
    uint32_t st, const __half* A0, const __half* A1,
    const __half* B0, const __half* B1, int K, int kk, int tid)
{
#pragma unroll
    for (int it = 0; it < 2; it++) {
        int f = tid + (it << 8);          // 0..511
        int r = f >> 2, c = f & 3;
        uint32_t off = (uint32_t)r * TROW_B + (uint32_t)c * 16;
        size_t src = (size_t)r * K + kk + (c << 3);
        cp16(st + OFF_A   + off, A0 + src);
        cp16(st + OFF_BHI + off, B0 + src);
        if (NT >= 2) cp16(st + OFF_BLO + off, B1 + src);
        if (NT == 3) cp16(st + OFF_ALO + off, A1 + src);
    }
}

// ---------------- core GEMM: C[M,Ntot] = A @ B^T (1..3 precision terms) ----
// Block tile 128x128, warp tile 64x32 (2x4 warp grid), 2-stage k32 pipeline.
// MODE 0: Ch(half) = acc + bias (gx GEMM, NT=3)
// MODE 1: fused LSTM epilogue (reads fp16 gx w/ biases), writes g_c + next h
//         + per-(n, column) h sums into hmean_out. NT=1.
// MODE 2: C(float) = acc + bias (ehpre, NT=1) + fused BN stats.
template<int MODE, int NT>
__global__ __launch_bounds__(256, 2) void mma_gemm(
    const __half* __restrict__ Ahi, const __half* __restrict__ Alo,
    const __half* __restrict__ Bhi, const __half* __restrict__ Blo,
    float* __restrict__ C, __half* __restrict__ Ch,
    const float* __restrict__ bias,
    const __half* __restrict__ gx,
    __half* __restrict__ whi,
    float* __restrict__ hmean_out,
    int Ntot, int K)
{
    constexpr uint32_t STAGE_B = (NT == 1 ? 2 : (NT == 2 ? 3 : 4)) * TILE_B;
    extern __shared__ char smem[];
    const uint32_t sb = smem_u32(smem);
    const int tid  = threadIdx.x;
    const int wid  = tid >> 5;
    const int lane = tid & 31;
    const int row0 = blockIdx.y << 7;
    const int col0 = blockIdx.x << 7;

    const int am0 = (wid & 1) * 64;    // warp m-offset in tile
    const int bn0 = (wid >> 1) * 32;   // warp n-offset in tile

    const uint32_t lrow = lane & 15, lcol = lane >> 4;
    const int g  = lane >> 2;
    const int t2 = (lane & 3) << 1;

    const __half* A0 = Ahi + (size_t)row0 * K;
    const __half* A1 = (NT == 3) ? (Alo + (size_t)row0 * K) : nullptr;
    const __half* B0 = Bhi + (size_t)col0 * K;
    const __half* B1 = (NT >= 2) ? (Blo + (size_t)col0 * K) : nullptr;

    float acc[4][4][4];
#pragma unroll
    for (int mf = 0; mf < 4; mf++)
#pragma unroll
        for (int nf = 0; nf < 4; nf++)
#pragma unroll
            for (int e = 0; e < 4; e++) acc[mf][nf][e] = 0.f;

    const int nch = K / KCH;

    // prologue: stage 0 <- chunk 0
    load_chunk<NT>(sb, A0, A1, B0, B1, K, 0, tid);
    CP_COMMIT();

    for (int kc = 0; kc < nch; kc++) {
        if (kc + 1 < nch) {
            load_chunk<NT>(sb + (uint32_t)((kc + 1) & 1) * STAGE_B,
                           A0, A1, B0, B1, K, (kc + 1) * KCH, tid);
            CP_COMMIT();
            CP_WAIT1();
        } else {
            CP_WAIT0();
        }
        __syncthreads();

        const uint32_t st  = sb + (uint32_t)(kc & 1) * STAGE_B;
        const uint32_t sA  = st + OFF_A;
        const uint32_t sB0 = st + OFF_BHI;
        const uint32_t sB1 = st + OFF_BLO;

#pragma unroll
        for (int ks = 0; ks < 2; ks++) {
            uint32_t a[4][4], bh[2][4], bl[2][4];
            const uint32_t kb = (uint32_t)(ks * 32 + lcol * 16);
#pragma unroll
            for (int mf = 0; mf < 4; mf++) {
                uint32_t ad = sA + (uint32_t)(am0 + mf * 16 + lrow) * TROW_B + kb;
                ldsm_x4(a[mf][0], a[mf][1], a[mf][2], a[mf][3], ad);
            }
#pragma unroll
            for (int ng = 0; ng < 2; ng++) {
                uint32_t roff = (uint32_t)(bn0 + ng * 16 + lrow) * TROW_B + kb;
                ldsm_x4(bh[ng][0], bh[ng][1], bh[ng][2], bh[ng][3], sB0 + roff);
                if (NT >= 2)
                    ldsm_x4(bl[ng][0], bl[ng][1], bl[ng][2], bl[ng][3], sB1 + roff);
            }
#pragma unroll
            for (int mf = 0; mf < 4; mf++)
#pragma unroll
                for (int nf = 0; nf < 4; nf++) {
                    int ng = nf >> 1, hf = nf & 1;
                    mma_f16(acc[mf][nf], a[mf], bh[ng][hf], bh[ng][hf + 2]);
                    if (NT >= 2)
                        mma_f16(acc[mf][nf], a[mf], bl[ng][hf], bl[ng][hf + 2]);
                }
            if (NT == 3) {
#pragma unroll
                for (int mf = 0; mf < 4; mf++) {
                    uint32_t ad = st + OFF_ALO
                                + (uint32_t)(am0 + mf * 16 + lrow) * TROW_B + kb;
                    ldsm_x4(a[mf][0], a[mf][1], a[mf][2], a[mf][3], ad);
                }
#pragma unroll
                for (int mf = 0; mf < 4; mf++)
#pragma unroll
                    for (int nf = 0; nf < 4; nf++) {
                        int ng = nf >> 1, hf = nf & 1;
                        mma_f16(acc[mf][nf], a[mf], bh[ng][hf], bh[ng][hf + 2]);
                    }
            }
        }
        __syncthreads();
    }

    if (MODE == 0) {
        // ---- gx store: Ch(half) = acc + bias ----
#pragma unroll
        for (int mf = 0; mf < 4; mf++) {
            int rg = row0 + am0 + mf * 16 + g;
#pragma unroll
            for (int nf = 0; nf < 4; nf++) {
                int cg = col0 + bn0 + nf * 8 + t2;
                float b0 = bias[cg], b1 = bias[cg + 1];
                __half2 v0 = __floats2half2_rn(acc[mf][nf][0] + b0, acc[mf][nf][1] + b1);
                __half2 v1 = __floats2half2_rn(acc[mf][nf][2] + b0, acc[mf][nf][3] + b1);
                *(__half2*)(Ch + (size_t)rg * Ntot + cg) = v0;
                *(__half2*)(Ch + (size_t)(rg + 8) * Ntot + cg) = v1;
            }
        }
    } else if (MODE == 2) {
        // ---- ehpre store + BN column stats ----
        float sc_[4][2], sq_[4][2];
#pragma unroll
        for (int nf = 0; nf < 4; nf++) { sc_[nf][0] = sc_[nf][1] = 0.f;
                                         sq_[nf][0] = sq_[nf][1] = 0.f; }
#pragma unroll
        for (int mf = 0; mf < 4; mf++) {
            int rg = row0 + am0 + mf * 16 + g;
#pragma unroll
            for (int nf = 0; nf < 4; nf++) {
                int cg = col0 + bn0 + nf * 8 + t2;
                float b0 = bias[cg], b1 = bias[cg + 1];
                float v00 = acc[mf][nf][0] + b0, v01 = acc[mf][nf][1] + b1;
                float v10 = acc[mf][nf][2] + b0, v11 = acc[mf][nf][3] + b1;
                *(float2*)(C + (size_t)rg * Ntot + cg) = make_float2(v00, v01);
                *(float2*)(C + (size_t)(rg + 8) * Ntot + cg) = make_float2(v10, v11);
                sc_[nf][0] += v00 + v10; sq_[nf][0] += v00 * v00 + v10 * v10;
                sc_[nf][1] += v01 + v11; sq_[nf][1] += v01 * v01 + v11 * v11;
            }
        }
        float2* S2 = (float2*)smem;    // [128 cols][16 slots] = 16KB
        int slot = ((wid & 1) << 3) + g;
#pragma unroll
        for (int nf = 0; nf < 4; nf++) {
            int cc0 = bn0 + nf * 8 + t2;
            S2[cc0 * 16 + slot]       = make_float2(sc_[nf][0], sq_[nf][0]);
            S2[(cc0 + 1) * 16 + slot] = make_float2(sc_[nf][1], sq_[nf][1]);
        }
        __syncthreads();
        if (tid < 128) {
            float s = 0.f, q = 0.f;
#pragma unroll
            for (int k2 = 0; k2 < 16; k2++) {
                float2 v = S2[tid * 16 + k2];
                s += v.x; q += v.y;
            }
            int rb = row0 >> 7;
            g_psum[rb * EHn + col0 + tid]   = s;
            g_psumsq[rb * EHn + col0 + tid] = q;
        }
    } else {
        // ---- LSTM epilogue: stage acc tile in smem, then elementwise ----
        float* Sf = (float*)smem;   // [128][132] = 67584 B
#pragma unroll
        for (int mf = 0; mf < 4; mf++) {
            int rr = am0 + mf * 16 + g;
#pragma unroll
            for (int nf = 0; nf < 4; nf++) {
                int cc = bn0 + nf * 8 + t2;
                Sf[rr * 132 + cc]           = acc[mf][nf][0];
                Sf[rr * 132 + cc + 1]       = acc[mf][nf][1];
                Sf[(rr + 8) * 132 + cc]     = acc[mf][nf][2];
                Sf[(rr + 8) * 132 + cc + 1] = acc[mf][nf][3];
            }
        }
        __syncthreads();

        const int j0 = col0 >> 2;      // 32 gate-quadruples per tile
        float hsum = 0.f;
#pragma unroll
        for (int it = 0; it < 16; it++) {
            int item = tid + (it << 8);            // 0..4095
            int r = item >> 5, q = item & 31;
            int grow = row0 + r;
            float4 gv = *(const float4*)(Sf + r * 132 + (q << 2));
            // gx is fp16: load 4 halves (8 bytes)
            uint2 gxraw = *(const uint2*)(gx + (size_t)grow * G4H + col0 + (q << 2));
            float2 gx01 = __half22float2(*(const __half2*)&gxraw.x);
            float2 gx23 = __half22float2(*(const __half2*)&gxraw.y);
            float gi = gv.x + gx01.x;
            float gf = gv.y + gx01.y;
            float gg = gv.z + gx23.x;
            float go = gv.w + gx23.y;
            float si = fsig(gi);
            float sf = fsig(gf);
            float so = fsig(go);
            size_t idx = (size_t)grow * Hdim + j0 + q;
            float cn = sf * g_c[idx] + si * ftanh(gg);
            g_c[idx] = cn;
            float hv = so * ftanh(cn);
            hsum += hv;
            whi[idx] = __float2half_rn(hv);
        }
        // per-(n, column) h sums: this CTA's 128 rows are exactly one n
        float* Sm = (float*)(smem + 67584);   // [32 q][8 warp-slots] = 1KB
        Sm[(tid & 31) * 8 + (tid >> 5)] = hsum;
        __syncthreads();
        if (tid < 32) {
            float s = 0.f;
#pragma unroll
            for (int k2 = 0; k2 < 8; k2++) s += Sm[tid * 8 + k2];
            hmean_out[(row0 >> 7) * Hdim + j0 + tid] = s;   // raw sum; oc scales
        }
    }
}

// ---------------- splits / init -------------------------------------------
__global__ __launch_bounds__(256) void split_mat(
    const float* __restrict__ src, __half* __restrict__ hi,
    __half* __restrict__ lo, int n)
{
    int i = blockIdx.x * blockDim.x + threadIdx.x;
    if (i < n) {
        float v = src[i];
        __half h = __float2half_rn(v);
        hi[i] = h;
        if (lo) lo[i] = __float2half_rn(v - __half2float(h));
    }
}

// gate-permuted split for W [2048][K]: new_row = (r%512)*4 + r/512
__global__ __launch_bounds__(256) void split_perm(
    const float* __restrict__ src, __half* __restrict__ hi,
    __half* __restrict__ lo, int K)
{
    int i = blockIdx.x * blockDim.x + threadIdx.x;   // over 2048*K
    int r = i / K, c = i - r * K;
    int nr = ((r & 511) << 2) + (r >> 9);
    float v = src[i];
    __half h = __float2half_rn(v);
    hi[nr * K + c] = h;
    if (lo) lo[nr * K + c] = __float2half_rn(v - __half2float(h));
}

__global__ void bias_combine(const float* __restrict__ b_ih,
                             const float* __restrict__ b_hh)
{
    int i = blockIdx.x * blockDim.x + threadIdx.x;   // < 2048
    int p = ((i & 511) << 2) + (i >> 9);
    g_bias2[p] = b_ih[i] + b_hh[i];
}

__global__ void init_state(const float* __restrict__ h0, const float* __restrict__ c0)
{
    int i = blockIdx.x * blockDim.x + threadIdx.x;   // NV*Hdim grid
    g_c[i] = c0[i];
    g_h0[i] = __float2half_rn(h0[i]);
}

// ---------------- finalize: eh BN params + full ec branch ------------------
__global__ __launch_bounds__(256) void finalize_step(
    const float* __restrict__ gamma_eh, const float* __restrict__ beta_eh,
    const float* __restrict__ oneh_t,
    const float* __restrict__ W_ec, const float* __restrict__ b_ec,
    const float* __restrict__ gamma_ec, const float* __restrict__ beta_ec,
    const float* __restrict__ W_out)
{
    __shared__ float s_cnt[NCn];
    __shared__ int   s_cls[Nn];
    __shared__ float s_ec[NCn][EHn];
    __shared__ float s_contrib[NCn * ODn];

    int tid = threadIdx.x;
    {
        float s = 0.f, sq = 0.f;
        for (int b = 0; b < 128; b++) {
            s  += g_psum[b * EHn + tid];
            sq += g_psumsq[b * EHn + tid];
        }
        float m   = s * (1.f / (float)NV);
        float var = sq * (1.f / (float)NV) - m * m;
        float sc  = gamma_eh[tid] * rsqrtf(var + 1e-5f);
        g_bnscale[tid] = sc;
        g_bnshift[tid] = beta_eh[tid] - sc * m;
    }
    if (tid < NCn) {
        float cv = 0.f;
        for (int n = 0; n < Nn; n++) cv += oneh_t[n * NCn + tid];
        s_cnt[tid] = cv;
    }
    if (tid < Nn) {
        const float* r = oneh_t + tid * NCn;
        int cl = 0; float best = r[0];
#pragma unroll
        for (int k = 1; k < NCn; k++) if (r[k] > best) { best = r[k]; cl = k; }
        s_cls[tid] = cl;
    }
    __syncthreads();
    {
        int j = tid;
        float pre[NCn];
        float m = 0.f, sq = 0.f;
#pragma unroll
        for (int cl = 0; cl < NCn; cl++) {
            pre[cl] = W_ec[j * NCn + cl] + b_ec[j];
            float w = s_cnt[cl] * (1.f / (float)Nn);
            m  += w * pre[cl];
            sq += w * pre[cl] * pre[cl];
        }
        float var = sq - m * m;
        float sc  = gamma_ec[j] * rsqrtf(var + 1e-5f);
        float sh  = beta_ec[j] - sc * m;
#pragma unroll
        for (int cl = 0; cl < NCn; cl++)
            s_ec[cl][j] = fmaxf(sc * pre[cl] + sh, 0.f);
    }
    __syncthreads();
    int warp = tid >> 5, lane = tid & 31;
    for (int p = warp; p < NCn * ODn; p += 8) {
        int cl = p / ODn, od = p % ODn;
        float a = 0.f;
#pragma unroll
        for (int u = 0; u < 8; u++) {
            int j = lane + (u << 5);
            a = fmaf(s_ec[cl][j], W_out[od * (EHn + EHn) + EHn + j], a);
        }
        for (int off = 16; off; off >>= 1) a += __shfl_xor_sync(0xffffffffu, a, off);
        if (lane == 0) s_contrib[p] = a;
    }
    __syncthreads();
    if (tid < Nn) {
        int cl = s_cls[tid];
#pragma unroll
        for (int od = 0; od < ODn; od++)
            g_ncontrib[tid * ODn + od] = s_contrib[cl * ODn + od];
    }
}

// ---------------- op: bn+relu(eh) . W_out[:, :256] + ec + b_out + act ------
__global__ __launch_bounds__(256) void op_kernel(
    const float* __restrict__ W_out, const float* __restrict__ b_out,
    float* __restrict__ out, int t)
{
    int warp = threadIdx.x >> 5, lane = threadIdx.x & 31;
    int row  = (blockIdx.x << 3) + warp;
    const float* er = g_ehpre + (size_t)row * EHn;

    float a0 = 0.f, a1 = 0.f, a2 = 0.f, a3 = 0.f, a4 = 0.f;
#pragma unroll
    for (int u = 0; u < 8; u++) {
        int j = lane + (u << 5);
        float xv = fmaxf(fmaf(g_bnscale[j], er[j], g_bnshift[j]), 0.f);
        a0 = fmaf(xv, W_out[j],            a0);
        a1 = fmaf(xv, W_out[512  + j],     a1);
        a2 = fmaf(xv, W_out[1024 + j],     a2);
        a3 = fmaf(xv, W_out[1536 + j],     a3);
        a4 = fmaf(xv, W_out[2048 + j],     a4);
    }
    for (int off = 16; off; off >>= 1) {
        a0 += __shfl_xor_sync(0xffffffffu, a0, off);
        a1 += __shfl_xor_sync(0xffffffffu, a1, off);
        a2 += __shfl_xor_sync(0xffffffffu, a2, off);
        a3 += __shfl_xor_sync(0xffffffffu, a3, off);
        a4 += __shfl_xor_sync(0xffffffffu, a4, off);
    }
    if (lane < ODn) {
        int n = row >> 7, v = row & 127;
        float a = (lane == 0) ? a0 : (lane == 1) ? a1 : (lane == 2) ? a2
                : (lane == 3) ? a3 : a4;
        a += g_ncontrib[n * ODn + lane] + b_out[lane];
        if (lane == 2 || lane == 3) a = expf(a);
        else if (lane == 4)         a = tanhf(a);
        out[(((size_t)n * Tn + t) * Vn + v) * ODn + lane] = a;
    }
}

// ---------------- oc: (sum_V h / V) @ W_cls^T + b_cls ----------------------
__global__ __launch_bounds__(192) void oc_kernel(
    const float* __restrict__ hmean, const float* __restrict__ W_cls,
    const float* __restrict__ b_cls, float* __restrict__ out, int t)
{
    int n = blockIdx.x;
    int warp = threadIdx.x >> 5, lane = threadIdx.x & 31;
    if (warp < ODn) {
        float a = 0.f;
#pragma unroll
        for (int u = 0; u < 16; u++) {
            int k = lane + (u << 5);
            a = fmaf(hmean[n * Hdim + k], W_cls[warp * Hdim + k], a);
        }
        for (int off = 16; off; off >>= 1) a += __shfl_xor_sync(0xffffffffu, a, off);
        if (lane == 0)
            out[PRED_TOTAL + ((size_t)t * Nn + n) * ODn + warp] =
                a * (1.f / (float)Vn) + b_cls[warp];
    }
}

// ---------------- streams/events (created at load, before harness checkpoints)
struct StreamRes {
    cudaStream_t s2 = nullptr;
    cudaEvent_t  eG[2] = {nullptr, nullptr};
    cudaEvent_t  eH[2] = {nullptr, nullptr};
    bool ok = false;
    StreamRes() {
        if (cudaStreamCreateWithFlags(&s2, cudaStreamNonBlocking) != cudaSuccess) return;
        for (int i = 0; i < 2; i++) {
            if (cudaEventCreateWithFlags(&eG[i], cudaEventDisableTiming) != cudaSuccess) return;
            if (cudaEventCreateWithFlags(&eH[i], cudaEventDisableTiming) != cudaSuccess) return;
        }
        ok = true;
    }
};
static StreamRes g_sr;

// ---------------- host launcher --------------------------------------------
extern "C" void kernel_launch(void* const* d_in, const int* in_sizes, int n_in,
                              void* d_out, int out_size)
{
    const float* x     = (const float*)d_in[0];
    const float* h0    = (const float*)d_in[1];
    const float* c0    = (const float*)d_in[2];
    const float* oneh  = (const float*)d_in[3];
    const float* W_ih  = (const float*)d_in[4];
    const float* W_hh  = (const float*)d_in[5];
    const float* b_ih  = (const float*)d_in[6];
    const float* b_hh  = (const float*)d_in[7];
    const float* W_cls = (const float*)d_in[8];
    const float* b_cls = (const float*)d_in[9];
    const float* W_eh  = (const float*)d_in[10];
    const float* b_eh  = (const float*)d_in[11];
    const float* ga_eh = (const float*)d_in[12];
    const float* be_eh = (const float*)d_in[13];
    const float* W_ec  = (const float*)d_in[14];
    const float* b_ec  = (const float*)d_in[15];
    const float* ga_ec = (const float*)d_in[16];
    const float* be_ec = (const float*)d_in[17];
    const float* W_out = (const float*)d_in[18];
    const float* b_out = (const float*)d_in[19];
    float* out = (float*)d_out;

    cudaFuncSetAttribute(mma_gemm<0,3>, cudaFuncAttributeMaxDynamicSharedMemorySize, SMEM_M0);
    cudaFuncSetAttribute(mma_gemm<1,1>, cudaFuncAttributeMaxDynamicSharedMemorySize, SMEM_M1);
    cudaFuncSetAttribute(mma_gemm<2,1>, cudaFuncAttributeMaxDynamicSharedMemorySize, SMEM_M2);

    float *ehpre, *bias2;
    float *hmean[2];
    __half *gx;
    __half *xh, *xl, *Wihh, *Wihl, *Whhh, *Wehh;
    __half *hbuf[2];
    cudaGetSymbolAddress((void**)&gx,    g_gx);
    cudaGetSymbolAddress((void**)&ehpre, g_ehpre);
    cudaGetSymbolAddress((void**)&bias2, g_bias2);
    cudaGetSymbolAddress((void**)&xh,    g_x_hi);
    cudaGetSymbolAddress((void**)&xl,    g_x_lo);
    cudaGetSymbolAddress((void**)&Wihh,  g_Wih_hi);
    cudaGetSymbolAddress((void**)&Wihl,  g_Wih_lo);
    cudaGetSymbolAddress((void**)&Whhh,  g_Whh_hi);
    cudaGetSymbolAddress((void**)&Wehh,  g_Weh_hi);
    cudaGetSymbolAddress((void**)&hbuf[0], g_h0);
    cudaGetSymbolAddress((void**)&hbuf[1], g_h1);
    cudaGetSymbolAddress((void**)&hmean[0], g_hmean0);
    cudaGetSymbolAddress((void**)&hmean[1], g_hmean1);

    // init + operand splits (stream 0)
    init_state<<<(NV * Hdim) / 256, 256>>>(h0, c0);
    split_mat<<<(NV * Cdim) / 256, 256>>>(x, xh, xl, NV * Cdim);
    split_perm<<<(G4H * Cdim) / 256, 256>>>(W_ih, Wihh, Wihl, Cdim);
    split_perm<<<(G4H * Hdim) / 256, 256>>>(W_hh, Whhh, nullptr, Hdim);
    split_mat<<<(EHn * Hdim) / 256, 256>>>(W_eh, Wehh, nullptr, EHn * Hdim);
    bias_combine<<<G4H / 256, 256>>>(b_ih, b_hh);

    // gx = x @ Wih_perm^T + (b_ih + b_hh)_perm   (step-invariant, 3-term, fp16 out)
    mma_gemm<0,3><<<dim3(G4H / 128, NV / 128), 256, SMEM_M0>>>(
        xh, xl, Wihh, Wihl, nullptr, gx, bias2, nullptr, nullptr, nullptr,
        G4H, Cdim);

    const bool dual = g_sr.ok;
    cudaStream_t sH = dual ? g_sr.s2 : (cudaStream_t)0;

    for (int t = 0; t < Tn; t++) {
        const int rb = t & 1, wb = rb ^ 1;

        if (dual && t >= 2) cudaStreamWaitEvent(0, g_sr.eH[t & 1], 0);

        // fused: gates = gx + h @ Whh_perm^T -> LSTM update -> h,c (+ hmean)
        mma_gemm<1,1><<<dim3(G4H / 128, NV / 128), 256, SMEM_M1>>>(
            hbuf[rb], nullptr, Whhh, nullptr, nullptr, nullptr, nullptr, gx,
            hbuf[wb], hmean[wb], G4H, Hdim);

        if (dual) {
            cudaEventRecord(g_sr.eG[t & 1], 0);
            cudaStreamWaitEvent(sH, g_sr.eG[t & 1], 0);
        }

        // head chain (second stream when available)
        oc_kernel<<<Nn, 192, 0, sH>>>(hmean[wb], W_cls, b_cls, out, t);
        mma_gemm<2,1><<<dim3(EHn / 128, NV / 128), 256, SMEM_M2, sH>>>(
            hbuf[wb], nullptr, Wehh, nullptr, ehpre, nullptr, b_eh,
            nullptr, nullptr, nullptr, EHn, Hdim);
        finalize_step<<<1, 256, 0, sH>>>(ga_eh, be_eh, oneh + (size_t)t * Nn * NCn,
                                         W_ec, b_ec, ga_ec, be_ec, W_out);
        op_kernel<<<NV / 8, 256, 0, sH>>>(W_out, b_out, out, t);

        if (dual) cudaEventRecord(g_sr.eH[t & 1], sH);
    }

    if (dual) {
        cudaStreamWaitEvent(0, g_sr.eH[0], 0);
        cudaStreamWaitEvent(0, g_sr.eH[1], 0);
    }
}

// round 12
// speedup vs baseline: 2.8897x; 1.1030x over previous
#include <cuda_runtime.h>
#include <cuda_fp16.h>
#include <math.h>
#include <stdint.h>

// ---------------- problem constants ----------------
#define Nn   128
#define Vn   128
#define NV   16384          // N*V rows
#define Cdim 256
#define Hdim 512
#define G4H  2048           // 4*H
#define Tn   12
#define NCn  5
#define EHn  256
#define ODn  5
#define PRED_TOTAL (Nn*Tn*Vn*ODn)   // 983040

// SMEM tile geometry: tiles of 128 rows x 32 fp16, 80B padded rows
#define KCH      32
#define TROW_B   80
#define TILE_B   (128 * TROW_B)           // 10240 bytes
#define OFF_A    0
#define OFF_BHI  10240
#define SMEM_G   40960                    // 2 stages x 2 tiles (1-term)
#define SMEM_M1  68608                    // max(2x2 tiles, LSTM staging 67584+1024)

// ---------------- device scratch (no allocations allowed) ----------------
__device__ __half g_gx[NV * G4H];       // fp16: x @ W_ih^T + biases (gate-permuted)
__device__ __half g_c[NV * Hdim];       // fp16 cell state
__device__ __half g_ehpre[NV * EHn];    // fp16 eh pre-activation
__device__ float g_psum[128 * EHn];
__device__ float g_psumsq[128 * EHn];
__device__ float g_bnscale[EHn];
__device__ float g_bnshift[EHn];
__device__ float g_ncontrib[Nn * NCn];
__device__ float g_bias2[G4H];          // permuted b_ih + b_hh
__device__ float g_hmean0[Nn * Hdim];   // per-n column sums of h (double buffered)
__device__ float g_hmean1[Nn * Hdim];

// fp16 operands; h is single fp16 (double buffered)
__device__ __half g_h0[NV * Hdim];
__device__ __half g_h1[NV * Hdim];
__device__ __half g_x[NV * Cdim];
__device__ __half g_Wih[G4H * Cdim];      // gate-permuted rows
__device__ __half g_Whh[G4H * Hdim];      // gate-permuted rows
__device__ __half g_Weh[EHn * Hdim];

// ---------------- mma.sync / ldmatrix / cp.async helpers -------------------
__device__ __forceinline__ uint32_t smem_u32(const void* p) {
    uint32_t a;
    asm("{ .reg .u64 t; cvta.to.shared.u64 t, %1; cvt.u32.u64 %0, t; }" : "=r"(a) : "l"(p));
    return a;
}
__device__ __forceinline__ void ldsm_x4(uint32_t& r0, uint32_t& r1, uint32_t& r2,
                                        uint32_t& r3, uint32_t addr) {
    asm volatile("ldmatrix.sync.aligned.m8n8.x4.shared.b16 {%0,%1,%2,%3}, [%4];"
                 : "=r"(r0), "=r"(r1), "=r"(r2), "=r"(r3) : "r"(addr));
}
__device__ __forceinline__ void mma_f16(float* c, const uint32_t* a,
                                        uint32_t b0, uint32_t b1) {
    asm volatile(
        "mma.sync.aligned.m16n8k16.row.col.f32.f16.f16.f32 "
        "{%0,%1,%2,%3}, {%4,%5,%6,%7}, {%8,%9}, {%0,%1,%2,%3};"
        : "+f"(c[0]), "+f"(c[1]), "+f"(c[2]), "+f"(c[3])
        : "r"(a[0]), "r"(a[1]), "r"(a[2]), "r"(a[3]), "r"(b0), "r"(b1));
}
__device__ __forceinline__ void cp16(uint32_t dst, const void* src) {
    asm volatile("cp.async.cg.shared.global [%0], [%1], 16;" :: "r"(dst), "l"(src));
}
#define CP_COMMIT() asm volatile("cp.async.commit_group;" ::: "memory")
#define CP_WAIT1()  asm volatile("cp.async.wait_group 1;" ::: "memory")
#define CP_WAIT0()  asm volatile("cp.async.wait_group 0;" ::: "memory")

// HW tanh (MUFU.TANH, sm_75+); sigmoid built on it: 1 MUFU + 1 FMA
__device__ __forceinline__ float ftanh(float x) {
    float y;
    asm("tanh.approx.f32 %0, %1;" : "=f"(y) : "f"(x));
    return y;
}
__device__ __forceinline__ float fsig(float x) {
    return fmaf(ftanh(0.5f * x), 0.5f, 0.5f);
}

// issue one k-chunk (A + B) into a stage
__device__ __forceinline__ void load_chunk(
    uint32_t st, const __half* A0, const __half* B0, int K, int kk, int tid)
{
#pragma unroll
    for (int it = 0; it < 2; it++) {
        int f = tid + (it << 8);          // 0..511
        int r = f >> 2, c = f & 3;
        uint32_t off = (uint32_t)r * TROW_B + (uint32_t)c * 16;
        size_t src = (size_t)r * K + kk + (c << 3);
        cp16(st + OFF_A   + off, A0 + src);
        cp16(st + OFF_BHI + off, B0 + src);
    }
}

// ---------------- core GEMM: C[M,Ntot] = A @ B^T (single fp16 term) --------
// Block tile 128x128, warp tile 64x32 (2x4 warp grid), 2-stage k32 pipeline.
// MODE 0: Ch(half) = acc + bias (gx GEMM)
// MODE 1: fused LSTM epilogue (reads fp16 gx w/ biases), writes fp16 c + next h
//         + per-(n, column) h sums into hmean_out.
// MODE 2: Ch(half) = acc + bias (ehpre) + fused BN stats (fp32).
template<int MODE>
__global__ __launch_bounds__(256, 2) void mma_gemm(
    const __half* __restrict__ Ahi,
    const __half* __restrict__ Bhi,
    __half* __restrict__ Ch,
    const float* __restrict__ bias,
    const __half* __restrict__ gx,
    __half* __restrict__ whi,
    float* __restrict__ hmean_out,
    int Ntot, int K)
{
    constexpr uint32_t STAGE_B = 2 * TILE_B;
    extern __shared__ char smem[];
    const uint32_t sb = smem_u32(smem);
    const int tid  = threadIdx.x;
    const int wid  = tid >> 5;
    const int lane = tid & 31;
    const int row0 = blockIdx.y << 7;
    const int col0 = blockIdx.x << 7;

    const int am0 = (wid & 1) * 64;    // warp m-offset in tile
    const int bn0 = (wid >> 1) * 32;   // warp n-offset in tile

    const uint32_t lrow = lane & 15, lcol = lane >> 4;
    const int g  = lane >> 2;
    const int t2 = (lane & 3) << 1;

    const __half* A0 = Ahi + (size_t)row0 * K;
    const __half* B0 = Bhi + (size_t)col0 * K;

    float acc[4][4][4];
#pragma unroll
    for (int mf = 0; mf < 4; mf++)
#pragma unroll
        for (int nf = 0; nf < 4; nf++)
#pragma unroll
            for (int e = 0; e < 4; e++) acc[mf][nf][e] = 0.f;

    const int nch = K / KCH;

    // prologue: stage 0 <- chunk 0
    load_chunk(sb, A0, B0, K, 0, tid);
    CP_COMMIT();

    for (int kc = 0; kc < nch; kc++) {
        if (kc + 1 < nch) {
            load_chunk(sb + (uint32_t)((kc + 1) & 1) * STAGE_B,
                       A0, B0, K, (kc + 1) * KCH, tid);
            CP_COMMIT();
            CP_WAIT1();
        } else {
            CP_WAIT0();
        }
        __syncthreads();

        const uint32_t st  = sb + (uint32_t)(kc & 1) * STAGE_B;
        const uint32_t sA  = st + OFF_A;
        const uint32_t sB0 = st + OFF_BHI;

#pragma unroll
        for (int ks = 0; ks < 2; ks++) {
            uint32_t a[4][4], bh[2][4];
            const uint32_t kb = (uint32_t)(ks * 32 + lcol * 16);
#pragma unroll
            for (int mf = 0; mf < 4; mf++) {
                uint32_t ad = sA + (uint32_t)(am0 + mf * 16 + lrow) * TROW_B + kb;
                ldsm_x4(a[mf][0], a[mf][1], a[mf][2], a[mf][3], ad);
            }
#pragma unroll
            for (int ng = 0; ng < 2; ng++) {
                uint32_t roff = (uint32_t)(bn0 + ng * 16 + lrow) * TROW_B + kb;
                ldsm_x4(bh[ng][0], bh[ng][1], bh[ng][2], bh[ng][3], sB0 + roff);
            }
#pragma unroll
            for (int mf = 0; mf < 4; mf++)
#pragma unroll
                for (int nf = 0; nf < 4; nf++) {
                    int ng = nf >> 1, hf = nf & 1;
                    mma_f16(acc[mf][nf], a[mf], bh[ng][hf], bh[ng][hf + 2]);
                }
        }
        __syncthreads();
    }

    if (MODE != 1) {
        // ---- fp16 store: Ch = acc + bias; MODE 2 also collects BN stats ----
        float sc_[4][2], sq_[4][2];
        if (MODE == 2) {
#pragma unroll
            for (int nf = 0; nf < 4; nf++) { sc_[nf][0] = sc_[nf][1] = 0.f;
                                             sq_[nf][0] = sq_[nf][1] = 0.f; }
        }
#pragma unroll
        for (int mf = 0; mf < 4; mf++) {
            int rg = row0 + am0 + mf * 16 + g;
#pragma unroll
            for (int nf = 0; nf < 4; nf++) {
                int cg = col0 + bn0 + nf * 8 + t2;
                float b0 = bias[cg], b1 = bias[cg + 1];
                float v00 = acc[mf][nf][0] + b0, v01 = acc[mf][nf][1] + b1;
                float v10 = acc[mf][nf][2] + b0, v11 = acc[mf][nf][3] + b1;
                *(__half2*)(Ch + (size_t)rg * Ntot + cg) = __floats2half2_rn(v00, v01);
                *(__half2*)(Ch + (size_t)(rg + 8) * Ntot + cg) = __floats2half2_rn(v10, v11);
                if (MODE == 2) {
                    sc_[nf][0] += v00 + v10; sq_[nf][0] += v00 * v00 + v10 * v10;
                    sc_[nf][1] += v01 + v11; sq_[nf][1] += v01 * v01 + v11 * v11;
                }
            }
        }
        if (MODE == 2) {
            float2* S2 = (float2*)smem;    // [128 cols][16 slots] = 16KB
            int slot = ((wid & 1) << 3) + g;
#pragma unroll
            for (int nf = 0; nf < 4; nf++) {
                int cc0 = bn0 + nf * 8 + t2;
                S2[cc0 * 16 + slot]       = make_float2(sc_[nf][0], sq_[nf][0]);
                S2[(cc0 + 1) * 16 + slot] = make_float2(sc_[nf][1], sq_[nf][1]);
            }
            __syncthreads();
            if (tid < 128) {
                float s = 0.f, q = 0.f;
#pragma unroll
                for (int k2 = 0; k2 < 16; k2++) {
                    float2 v = S2[tid * 16 + k2];
                    s += v.x; q += v.y;
                }
                int rb = row0 >> 7;
                g_psum[rb * EHn + col0 + tid]   = s;
                g_psumsq[rb * EHn + col0 + tid] = q;
            }
        }
    } else {
        // ---- LSTM epilogue: stage acc tile in smem, then elementwise ----
        float* Sf = (float*)smem;   // [128][132] = 67584 B
#pragma unroll
        for (int mf = 0; mf < 4; mf++) {
            int rr = am0 + mf * 16 + g;
#pragma unroll
            for (int nf = 0; nf < 4; nf++) {
                int cc = bn0 + nf * 8 + t2;
                Sf[rr * 132 + cc]           = acc[mf][nf][0];
                Sf[rr * 132 + cc + 1]       = acc[mf][nf][1];
                Sf[(rr + 8) * 132 + cc]     = acc[mf][nf][2];
                Sf[(rr + 8) * 132 + cc + 1] = acc[mf][nf][3];
            }
        }
        __syncthreads();

        const int j0 = col0 >> 2;      // 32 gate-quadruples per tile
        float hsum = 0.f;
#pragma unroll
        for (int it = 0; it < 16; it++) {
            int item = tid + (it << 8);            // 0..4095
            int r = item >> 5, q = item & 31;
            int grow = row0 + r;
            float4 gv = *(const float4*)(Sf + r * 132 + (q << 2));
            uint2 gxraw = *(const uint2*)(gx + (size_t)grow * G4H + col0 + (q << 2));
            float2 gx01 = __half22float2(*(const __half2*)&gxraw.x);
            float2 gx23 = __half22float2(*(const __half2*)&gxraw.y);
            float gi = gv.x + gx01.x;
            float gf = gv.y + gx01.y;
            float gg = gv.z + gx23.x;
            float go = gv.w + gx23.y;
            float si = fsig(gi);
            float sf = fsig(gf);
            float so = fsig(go);
            size_t idx = (size_t)grow * Hdim + j0 + q;
            float cn = sf * __half2float(g_c[idx]) + si * ftanh(gg);
            g_c[idx] = __float2half_rn(cn);
            float hv = so * ftanh(cn);
            hsum += hv;
            whi[idx] = __float2half_rn(hv);
        }
        // per-(n, column) h sums: this CTA's 128 rows are exactly one n
        float* Sm = (float*)(smem + 67584);   // [32 q][8 warp-slots] = 1KB
        Sm[(tid & 31) * 8 + (tid >> 5)] = hsum;
        __syncthreads();
        if (tid < 32) {
            float s = 0.f;
#pragma unroll
            for (int k2 = 0; k2 < 8; k2++) s += Sm[tid * 8 + k2];
            hmean_out[(row0 >> 7) * Hdim + j0 + tid] = s;   // raw sum; oc scales
        }
    }
}

// ---------------- casts / init --------------------------------------------
__global__ __launch_bounds__(256) void cast_mat(
    const float* __restrict__ src, __half* __restrict__ dst, int n)
{
    int i = blockIdx.x * blockDim.x + threadIdx.x;
    if (i < n) dst[i] = __float2half_rn(src[i]);
}

// gate-permuted cast for W [2048][K]: new_row = (r%512)*4 + r/512
__global__ __launch_bounds__(256) void cast_perm(
    const float* __restrict__ src, __half* __restrict__ dst, int K)
{
    int i = blockIdx.x * blockDim.x + threadIdx.x;   // over 2048*K
    int r = i / K, c = i - r * K;
    int nr = ((r & 511) << 2) + (r >> 9);
    dst[nr * K + c] = __float2half_rn(src[i]);
}

__global__ void bias_combine(const float* __restrict__ b_ih,
                             const float* __restrict__ b_hh)
{
    int i = blockIdx.x * blockDim.x + threadIdx.x;   // < 2048
    int p = ((i & 511) << 2) + (i >> 9);
    g_bias2[p] = b_ih[i] + b_hh[i];
}

__global__ void init_state(const float* __restrict__ h0, const float* __restrict__ c0)
{
    int i = blockIdx.x * blockDim.x + threadIdx.x;   // NV*Hdim grid
    g_c[i]  = __float2half_rn(c0[i]);
    g_h0[i] = __float2half_rn(h0[i]);
}

// ---------------- finalize (block 0) + oc (blocks 1..Nn) -------------------
__global__ __launch_bounds__(256) void finalize_oc(
    const float* __restrict__ gamma_eh, const float* __restrict__ beta_eh,
    const float* __restrict__ oneh_t,
    const float* __restrict__ W_ec, const float* __restrict__ b_ec,
    const float* __restrict__ gamma_ec, const float* __restrict__ beta_ec,
    const float* __restrict__ W_out,
    const float* __restrict__ hmean, const float* __restrict__ W_cls,
    const float* __restrict__ b_cls, float* __restrict__ out, int t)
{
    int tid = threadIdx.x;
    if (blockIdx.x > 0) {
        // ---- oc: (sum_V h / V) @ W_cls^T + b_cls ----
        int n = blockIdx.x - 1;
        int warp = tid >> 5, lane = tid & 31;
        if (warp < ODn) {
            float a = 0.f;
#pragma unroll
            for (int u = 0; u < 16; u++) {
                int k = lane + (u << 5);
                a = fmaf(hmean[n * Hdim + k], W_cls[warp * Hdim + k], a);
            }
            for (int off = 16; off; off >>= 1) a += __shfl_xor_sync(0xffffffffu, a, off);
            if (lane == 0)
                out[PRED_TOTAL + ((size_t)t * Nn + n) * ODn + warp] =
                    a * (1.f / (float)Vn) + b_cls[warp];
        }
        return;
    }

    __shared__ float s_cnt[NCn];
    __shared__ int   s_cls[Nn];
    __shared__ float s_ec[NCn][EHn];
    __shared__ float s_contrib[NCn * ODn];

    {
        float s = 0.f, sq = 0.f;
        for (int b = 0; b < 128; b++) {
            s  += g_psum[b * EHn + tid];
            sq += g_psumsq[b * EHn + tid];
        }
        float m   = s * (1.f / (float)NV);
        float var = sq * (1.f / (float)NV) - m * m;
        float sc  = gamma_eh[tid] * rsqrtf(var + 1e-5f);
        g_bnscale[tid] = sc;
        g_bnshift[tid] = beta_eh[tid] - sc * m;
    }
    if (tid < NCn) {
        float cv = 0.f;
        for (int n = 0; n < Nn; n++) cv += oneh_t[n * NCn + tid];
        s_cnt[tid] = cv;
    }
    if (tid < Nn) {
        const float* r = oneh_t + tid * NCn;
        int cl = 0; float best = r[0];
#pragma unroll
        for (int k = 1; k < NCn; k++) if (r[k] > best) { best = r[k]; cl = k; }
        s_cls[tid] = cl;
    }
    __syncthreads();
    {
        int j = tid;
        float pre[NCn];
        float m = 0.f, sq = 0.f;
#pragma unroll
        for (int cl = 0; cl < NCn; cl++) {
            pre[cl] = W_ec[j * NCn + cl] + b_ec[j];
            float w = s_cnt[cl] * (1.f / (float)Nn);
            m  += w * pre[cl];
            sq += w * pre[cl] * pre[cl];
        }
        float var = sq - m * m;
        float sc  = gamma_ec[j] * rsqrtf(var + 1e-5f);
        float sh  = beta_ec[j] - sc * m;
#pragma unroll
        for (int cl = 0; cl < NCn; cl++)
            s_ec[cl][j] = fmaxf(sc * pre[cl] + sh, 0.f);
    }
    __syncthreads();
    int warp = tid >> 5, lane = tid & 31;
    for (int p = warp; p < NCn * ODn; p += 8) {
        int cl = p / ODn, od = p % ODn;
        float a = 0.f;
#pragma unroll
        for (int u = 0; u < 8; u++) {
            int j = lane + (u << 5);
            a = fmaf(s_ec[cl][j], W_out[od * (EHn + EHn) + EHn + j], a);
        }
        for (int off = 16; off; off >>= 1) a += __shfl_xor_sync(0xffffffffu, a, off);
        if (lane == 0) s_contrib[p] = a;
    }
    __syncthreads();
    if (tid < Nn) {
        int cl = s_cls[tid];
#pragma unroll
        for (int od = 0; od < ODn; od++)
            g_ncontrib[tid * ODn + od] = s_contrib[cl * ODn + od];
    }
}

// ---------------- op: bn+relu(eh) . W_out[:, :256] + ec + b_out + act ------
__global__ __launch_bounds__(256) void op_kernel(
    const float* __restrict__ W_out, const float* __restrict__ b_out,
    float* __restrict__ out, int t)
{
    int warp = threadIdx.x >> 5, lane = threadIdx.x & 31;
    int row  = (blockIdx.x << 3) + warp;
    const __half* er = g_ehpre + (size_t)row * EHn;

    float a0 = 0.f, a1 = 0.f, a2 = 0.f, a3 = 0.f, a4 = 0.f;
#pragma unroll
    for (int u = 0; u < 8; u++) {
        int j = lane + (u << 5);
        float xv = fmaxf(fmaf(g_bnscale[j], __half2float(er[j]), g_bnshift[j]), 0.f);
        a0 = fmaf(xv, W_out[j],            a0);
        a1 = fmaf(xv, W_out[512  + j],     a1);
        a2 = fmaf(xv, W_out[1024 + j],     a2);
        a3 = fmaf(xv, W_out[1536 + j],     a3);
        a4 = fmaf(xv, W_out[2048 + j],     a4);
    }
    for (int off = 16; off; off >>= 1) {
        a0 += __shfl_xor_sync(0xffffffffu, a0, off);
        a1 += __shfl_xor_sync(0xffffffffu, a1, off);
        a2 += __shfl_xor_sync(0xffffffffu, a2, off);
        a3 += __shfl_xor_sync(0xffffffffu, a3, off);
        a4 += __shfl_xor_sync(0xffffffffu, a4, off);
    }
    if (lane < ODn) {
        int n = row >> 7, v = row & 127;
        float a = (lane == 0) ? a0 : (lane == 1) ? a1 : (lane == 2) ? a2
                : (lane == 3) ? a3 : a4;
        a += g_ncontrib[n * ODn + lane] + b_out[lane];
        if (lane == 2 || lane == 3) a = expf(a);
        else if (lane == 4)         a = tanhf(a);
        out[(((size_t)n * Tn + t) * Vn + v) * ODn + lane] = a;
    }
}

// ---------------- streams/events (created at load, before harness checkpoints)
struct StreamRes {
    cudaStream_t s2 = nullptr;
    cudaEvent_t  eG[2] = {nullptr, nullptr};
    cudaEvent_t  eH[2] = {nullptr, nullptr};
    bool ok = false;
    StreamRes() {
        if (cudaStreamCreateWithFlags(&s2, cudaStreamNonBlocking) != cudaSuccess) return;
        for (int i = 0; i < 2; i++) {
            if (cudaEventCreateWithFlags(&eG[i], cudaEventDisableTiming) != cudaSuccess) return;
            if (cudaEventCreateWithFlags(&eH[i], cudaEventDisableTiming) != cudaSuccess) return;
        }
        ok = true;
    }
};
static StreamRes g_sr;

// ---------------- host launcher --------------------------------------------
extern "C" void kernel_launch(void* const* d_in, const int* in_sizes, int n_in,
                              void* d_out, int out_size)
{
    const float* x     = (const float*)d_in[0];
    const float* h0    = (const float*)d_in[1];
    const float* c0    = (const float*)d_in[2];
    const float* oneh  = (const float*)d_in[3];
    const float* W_ih  = (const float*)d_in[4];
    const float* W_hh  = (const float*)d_in[5];
    const float* b_ih  = (const float*)d_in[6];
    const float* b_hh  = (const float*)d_in[7];
    const float* W_cls = (const float*)d_in[8];
    const float* b_cls = (const float*)d_in[9];
    const float* W_eh  = (const float*)d_in[10];
    const float* b_eh  = (const float*)d_in[11];
    const float* ga_eh = (const float*)d_in[12];
    const float* be_eh = (const float*)d_in[13];
    const float* W_ec  = (const float*)d_in[14];
    const float* b_ec  = (const float*)d_in[15];
    const float* ga_ec = (const float*)d_in[16];
    const float* be_ec = (const float*)d_in[17];
    const float* W_out = (const float*)d_in[18];
    const float* b_out = (const float*)d_in[19];
    float* out = (float*)d_out;

    cudaFuncSetAttribute(mma_gemm<0>, cudaFuncAttributeMaxDynamicSharedMemorySize, SMEM_G);
    cudaFuncSetAttribute(mma_gemm<1>, cudaFuncAttributeMaxDynamicSharedMemorySize, SMEM_M1);
    cudaFuncSetAttribute(mma_gemm<2>, cudaFuncAttributeMaxDynamicSharedMemorySize, SMEM_G);

    float *bias2;
    float *hmean[2];
    __half *gx, *ehpre;
    __half *xh, *Wih, *Whh, *Weh;
    __half *hbuf[2];
    cudaGetSymbolAddress((void**)&gx,    g_gx);
    cudaGetSymbolAddress((void**)&ehpre, g_ehpre);
    cudaGetSymbolAddress((void**)&bias2, g_bias2);
    cudaGetSymbolAddress((void**)&xh,    g_x);
    cudaGetSymbolAddress((void**)&Wih,   g_Wih);
    cudaGetSymbolAddress((void**)&Whh,   g_Whh);
    cudaGetSymbolAddress((void**)&Weh,   g_Weh);
    cudaGetSymbolAddress((void**)&hbuf[0], g_h0);
    cudaGetSymbolAddress((void**)&hbuf[1], g_h1);
    cudaGetSymbolAddress((void**)&hmean[0], g_hmean0);
    cudaGetSymbolAddress((void**)&hmean[1], g_hmean1);

    // init + operand casts (stream 0)
    init_state<<<(NV * Hdim) / 256, 256>>>(h0, c0);
    cast_mat<<<(NV * Cdim) / 256, 256>>>(x, xh, NV * Cdim);
    cast_perm<<<(G4H * Cdim) / 256, 256>>>(W_ih, Wih, Cdim);
    cast_perm<<<(G4H * Hdim) / 256, 256>>>(W_hh, Whh, Hdim);
    cast_mat<<<(EHn * Hdim) / 256, 256>>>(W_eh, Weh, EHn * Hdim);
    bias_combine<<<G4H / 256, 256>>>(b_ih, b_hh);

    // gx = x @ Wih_perm^T + (b_ih + b_hh)_perm   (step-invariant, fp16 out)
    mma_gemm<0><<<dim3(G4H / 128, NV / 128), 256, SMEM_G>>>(
        xh, Wih, gx, bias2, nullptr, nullptr, nullptr, G4H, Cdim);

    const bool dual = g_sr.ok;
    cudaStream_t sH = dual ? g_sr.s2 : (cudaStream_t)0;

    for (int t = 0; t < Tn; t++) {
        const int rb = t & 1, wb = rb ^ 1;

        if (dual && t >= 2) cudaStreamWaitEvent(0, g_sr.eH[t & 1], 0);

        // fused: gates = gx + h @ Whh_perm^T -> LSTM update -> h,c (+ hmean)
        mma_gemm<1><<<dim3(G4H / 128, NV / 128), 256, SMEM_M1>>>(
            hbuf[rb], Whh, nullptr, nullptr, gx, hbuf[wb], hmean[wb],
            G4H, Hdim);

        if (dual) {
            cudaEventRecord(g_sr.eG[t & 1], 0);
            cudaStreamWaitEvent(sH, g_sr.eG[t & 1], 0);
        }

        // head chain (second stream when available)
        mma_gemm<2><<<dim3(EHn / 128, NV / 128), 256, SMEM_G, sH>>>(
            hbuf[wb], Weh, ehpre, b_eh, nullptr, nullptr, nullptr,
            EHn, Hdim);
        finalize_oc<<<1 + Nn, 256, 0, sH>>>(
            ga_eh, be_eh, oneh + (size_t)t * Nn * NCn,
            W_ec, b_ec, ga_ec, be_ec, W_out,
            hmean[wb], W_cls, b_cls, out, t);
        op_kernel<<<NV / 8, 256, 0, sH>>>(W_out, b_out, out, t);

        if (dual) cudaEventRecord(g_sr.eH[t & 1], sH);
    }

    if (dual) {
        cudaStreamWaitEvent(0, g_sr.eH[0], 0);
        cudaStreamWaitEvent(0, g_sr.eH[1], 0);
    }
}

// round 13
// speedup vs baseline: 3.3577x; 1.1620x over previous
#include <cuda_runtime.h>
#include <cuda_fp16.h>
#include <math.h>
#include <stdint.h>

// ---------------- problem constants ----------------
#define Nn   128
#define Vn   128
#define NV   16384          // N*V rows
#define Cdim 256
#define Hdim 512
#define G4H  2048           // 4*H
#define Tn   12
#define NCn  5
#define EHn  256
#define ODn  5
#define PRED_TOTAL (Nn*Tn*Vn*ODn)   // 983040

// SMEM tile geometry: tiles of 128 rows x 64 fp16, 144B padded rows
#define KCH      64
#define TROW_B   144
#define TILE_B   (128 * TROW_B)           // 18432 bytes
#define OFF_A    0
#define OFF_B    18432
#define STAGE_B  36864
#define SMEM_ALL 73728                    // 2 stages (>= LSTM staging 68608)

// ---------------- device scratch (no allocations allowed) ----------------
__device__ __half g_gx[NV * G4H];       // fp16: x @ W_ih^T + biases (gate-permuted)
__device__ __half g_c[NV * Hdim];       // fp16 cell state
__device__ __half g_ehpre[NV * EHn];    // fp16 eh pre-activation
__device__ float g_psum[128 * EHn];
__device__ float g_psumsq[128 * EHn];
__device__ float g_bnscale[EHn];
__device__ float g_bnshift[EHn];
__device__ float g_ncontrib[Nn * NCn];
__device__ float g_bias2[G4H];          // permuted b_ih + b_hh
__device__ float g_hmean0[Nn * Hdim];   // per-n column sums of h (double buffered)
__device__ float g_hmean1[Nn * Hdim];

// fp16 operands; h is single fp16 (double buffered)
__device__ __half g_h0[NV * Hdim];
__device__ __half g_h1[NV * Hdim];
__device__ __half g_x[NV * Cdim];
__device__ __half g_Wih[G4H * Cdim];      // gate-permuted rows
__device__ __half g_Whh[G4H * Hdim];      // gate-permuted rows
__device__ __half g_Weh[EHn * Hdim];

// ---------------- mma.sync / ldmatrix / cp.async helpers -------------------
__device__ __forceinline__ uint32_t smem_u32(const void* p) {
    uint32_t a;
    asm("{ .reg .u64 t; cvta.to.shared.u64 t, %1; cvt.u32.u64 %0, t; }" : "=r"(a) : "l"(p));
    return a;
}
__device__ __forceinline__ void ldsm_x4(uint32_t& r0, uint32_t& r1, uint32_t& r2,
                                        uint32_t& r3, uint32_t addr) {
    asm volatile("ldmatrix.sync.aligned.m8n8.x4.shared.b16 {%0,%1,%2,%3}, [%4];"
                 : "=r"(r0), "=r"(r1), "=r"(r2), "=r"(r3) : "r"(addr));
}
__device__ __forceinline__ void mma_f16(float* c, const uint32_t* a,
                                        uint32_t b0, uint32_t b1) {
    asm volatile(
        "mma.sync.aligned.m16n8k16.row.col.f32.f16.f16.f32 "
        "{%0,%1,%2,%3}, {%4,%5,%6,%7}, {%8,%9}, {%0,%1,%2,%3};"
        : "+f"(c[0]), "+f"(c[1]), "+f"(c[2]), "+f"(c[3])
        : "r"(a[0]), "r"(a[1]), "r"(a[2]), "r"(a[3]), "r"(b0), "r"(b1));
}
__device__ __forceinline__ void cp16(uint32_t dst, const void* src) {
    asm volatile("cp.async.cg.shared.global [%0], [%1], 16;" :: "r"(dst), "l"(src));
}
#define CP_COMMIT() asm volatile("cp.async.commit_group;" ::: "memory")
#define CP_WAIT1()  asm volatile("cp.async.wait_group 1;" ::: "memory")
#define CP_WAIT0()  asm volatile("cp.async.wait_group 0;" ::: "memory")

// HW tanh (MUFU.TANH), scalar f32 and packed f16x2
__device__ __forceinline__ float ftanh(float x) {
    float y;
    asm("tanh.approx.f32 %0, %1;" : "=f"(y) : "f"(x));
    return y;
}
__device__ __forceinline__ uint32_t tanh2(uint32_t x) {
    uint32_t y;
    asm("tanh.approx.f16x2 %0, %1;" : "=r"(y) : "r"(x));
    return y;
}
__device__ __forceinline__ uint32_t pack2(float a, float b) {
    __half2 h = __floats2half2_rn(a, b);
    return *(uint32_t*)&h;
}
__device__ __forceinline__ float2 unpack2(uint32_t x) {
    return __half22float2(*(__half2*)&x);
}

// issue one k-chunk (A + B tiles, 128 rows x 64 fp16 each) into a stage
__device__ __forceinline__ void load_chunk(
    uint32_t st, const __half* A0, const __half* B0, int K, int kk, int tid)
{
#pragma unroll
    for (int it = 0; it < 4; it++) {
        int f = tid + (it << 8);          // 0..1023
        int r = f >> 3, c = f & 7;
        uint32_t off = (uint32_t)r * TROW_B + (uint32_t)c * 16;
        size_t src = (size_t)r * K + kk + (c << 3);
        cp16(st + OFF_A + off, A0 + src);
        cp16(st + OFF_B + off, B0 + src);
    }
}

// ---------------- core GEMM: C[M,Ntot] = A @ B^T (single fp16 term) --------
// Block tile 128x128, warp tile 64x32 (2x4 warp grid), 2-stage k64 pipeline.
// MODE 0: Ch(half) = acc + bias (gx GEMM)
// MODE 1: fused LSTM epilogue (reads fp16 gx w/ biases), writes fp16 c + next h
//         + per-(n, column) h sums into hmean_out.
// MODE 2: Ch(half) = acc + bias (ehpre) + fused BN stats (fp32).
template<int MODE>
__global__ __launch_bounds__(256, 2) void mma_gemm(
    const __half* __restrict__ Ahi,
    const __half* __restrict__ Bhi,
    __half* __restrict__ Ch,
    const float* __restrict__ bias,
    const __half* __restrict__ gx,
    __half* __restrict__ whi,
    float* __restrict__ hmean_out,
    int Ntot, int K)
{
    extern __shared__ char smem[];
    const uint32_t sb = smem_u32(smem);
    const int tid  = threadIdx.x;
    const int wid  = tid >> 5;
    const int lane = tid & 31;
    const int row0 = blockIdx.y << 7;
    const int col0 = blockIdx.x << 7;

    const int am0 = (wid & 1) * 64;    // warp m-offset in tile
    const int bn0 = (wid >> 1) * 32;   // warp n-offset in tile

    const uint32_t lrow = lane & 15, lcol = lane >> 4;
    const int g  = lane >> 2;
    const int t2 = (lane & 3) << 1;

    const __half* A0 = Ahi + (size_t)row0 * K;
    const __half* B0 = Bhi + (size_t)col0 * K;

    float acc[4][4][4];
#pragma unroll
    for (int mf = 0; mf < 4; mf++)
#pragma unroll
        for (int nf = 0; nf < 4; nf++)
#pragma unroll
            for (int e = 0; e < 4; e++) acc[mf][nf][e] = 0.f;

    const int nch = K / KCH;

    // prologue: stage 0 <- chunk 0
    load_chunk(sb, A0, B0, K, 0, tid);
    CP_COMMIT();

    for (int kc = 0; kc < nch; kc++) {
        if (kc + 1 < nch) {
            load_chunk(sb + (uint32_t)((kc + 1) & 1) * STAGE_B,
                       A0, B0, K, (kc + 1) * KCH, tid);
            CP_COMMIT();
            CP_WAIT1();
        } else {
            CP_WAIT0();
        }
        __syncthreads();

        const uint32_t st = sb + (uint32_t)(kc & 1) * STAGE_B;
        const uint32_t sA = st + OFF_A;
        const uint32_t sB = st + OFF_B;

#pragma unroll
        for (int ks = 0; ks < 4; ks++) {
            uint32_t a[4][4], bh[2][4];
            const uint32_t kb = (uint32_t)(ks * 32 + lcol * 16);
#pragma unroll
            for (int mf = 0; mf < 4; mf++) {
                uint32_t ad = sA + (uint32_t)(am0 + mf * 16 + lrow) * TROW_B + kb;
                ldsm_x4(a[mf][0], a[mf][1], a[mf][2], a[mf][3], ad);
            }
#pragma unroll
            for (int ng = 0; ng < 2; ng++) {
                uint32_t roff = (uint32_t)(bn0 + ng * 16 + lrow) * TROW_B + kb;
                ldsm_x4(bh[ng][0], bh[ng][1], bh[ng][2], bh[ng][3], sB + roff);
            }
#pragma unroll
            for (int mf = 0; mf < 4; mf++)
#pragma unroll
                for (int nf = 0; nf < 4; nf++) {
                    int ng = nf >> 1, hf = nf & 1;
                    mma_f16(acc[mf][nf], a[mf], bh[ng][hf], bh[ng][hf + 2]);
                }
        }
        __syncthreads();
    }

    if (MODE != 1) {
        // ---- fp16 store: Ch = acc + bias; MODE 2 also collects BN stats ----
        float sc_[4][2], sq_[4][2];
        if (MODE == 2) {
#pragma unroll
            for (int nf = 0; nf < 4; nf++) { sc_[nf][0] = sc_[nf][1] = 0.f;
                                             sq_[nf][0] = sq_[nf][1] = 0.f; }
        }
#pragma unroll
        for (int mf = 0; mf < 4; mf++) {
            int rg = row0 + am0 + mf * 16 + g;
#pragma unroll
            for (int nf = 0; nf < 4; nf++) {
                int cg = col0 + bn0 + nf * 8 + t2;
                float b0 = bias[cg], b1 = bias[cg + 1];
                float v00 = acc[mf][nf][0] + b0, v01 = acc[mf][nf][1] + b1;
                float v10 = acc[mf][nf][2] + b0, v11 = acc[mf][nf][3] + b1;
                *(__half2*)(Ch + (size_t)rg * Ntot + cg) = __floats2half2_rn(v00, v01);
                *(__half2*)(Ch + (size_t)(rg + 8) * Ntot + cg) = __floats2half2_rn(v10, v11);
                if (MODE == 2) {
                    sc_[nf][0] += v00 + v10; sq_[nf][0] += v00 * v00 + v10 * v10;
                    sc_[nf][1] += v01 + v11; sq_[nf][1] += v01 * v01 + v11 * v11;
                }
            }
        }
        if (MODE == 2) {
            float2* S2 = (float2*)smem;    // [128 cols][16 slots] = 16KB
            int slot = ((wid & 1) << 3) + g;
#pragma unroll
            for (int nf = 0; nf < 4; nf++) {
                int cc0 = bn0 + nf * 8 + t2;
                S2[cc0 * 16 + slot]       = make_float2(sc_[nf][0], sq_[nf][0]);
                S2[(cc0 + 1) * 16 + slot] = make_float2(sc_[nf][1], sq_[nf][1]);
            }
            __syncthreads();
            if (tid < 128) {
                float s = 0.f, q = 0.f;
#pragma unroll
                for (int k2 = 0; k2 < 16; k2++) {
                    float2 v = S2[tid * 16 + k2];
                    s += v.x; q += v.y;
                }
                int rb = row0 >> 7;
                g_psum[rb * EHn + col0 + tid]   = s;
                g_psumsq[rb * EHn + col0 + tid] = q;
            }
        }
    } else {
        // ---- LSTM epilogue: stage acc tile in smem, then elementwise ----
        float* Sf = (float*)smem;   // [128][132] = 67584 B
#pragma unroll
        for (int mf = 0; mf < 4; mf++) {
            int rr = am0 + mf * 16 + g;
#pragma unroll
            for (int nf = 0; nf < 4; nf++) {
                int cc = bn0 + nf * 8 + t2;
                Sf[rr * 132 + cc]           = acc[mf][nf][0];
                Sf[rr * 132 + cc + 1]       = acc[mf][nf][1];
                Sf[(rr + 8) * 132 + cc]     = acc[mf][nf][2];
                Sf[(rr + 8) * 132 + cc + 1] = acc[mf][nf][3];
            }
        }
        __syncthreads();

        const int j0 = col0 >> 2;      // 32 gate-quadruples per tile
        const int q  = tid & 31;
        const int rb = tid >> 5;       // 0..7
        float hsum = 0.f;
#pragma unroll
        for (int p = 0; p < 8; p++) {
            int rA = rb + (p << 4);    // rows rA and rA+8, same column q
            int rB = rA + 8;
            int growA = row0 + rA, growB = row0 + rB;
            float4 gvA = *(const float4*)(Sf + rA * 132 + (q << 2));
            float4 gvB = *(const float4*)(Sf + rB * 132 + (q << 2));
            uint2 gxA = *(const uint2*)(gx + (size_t)growA * G4H + col0 + (q << 2));
            uint2 gxB = *(const uint2*)(gx + (size_t)growB * G4H + col0 + (q << 2));
            float2 gA01 = unpack2(gxA.x), gA23 = unpack2(gxA.y);
            float2 gB01 = unpack2(gxB.x), gB23 = unpack2(gxB.y);
            float giA = gvA.x + gA01.x, gfA = gvA.y + gA01.y;
            float ggA = gvA.z + gA23.x, goA = gvA.w + gA23.y;
            float giB = gvB.x + gB01.x, gfB = gvB.y + gB01.y;
            float ggB = gvB.z + gB23.x, goB = gvB.w + gB23.y;

            // packed transcendentals: pairs (A,B) per gate
            float2 ti = unpack2(tanh2(pack2(0.5f * giA, 0.5f * giB)));
            float2 tf = unpack2(tanh2(pack2(0.5f * gfA, 0.5f * gfB)));
            float2 to = unpack2(tanh2(pack2(0.5f * goA, 0.5f * goB)));
            float2 tg = unpack2(tanh2(pack2(ggA, ggB)));
            float siA = fmaf(ti.x, 0.5f, 0.5f), siB = fmaf(ti.y, 0.5f, 0.5f);
            float sfA = fmaf(tf.x, 0.5f, 0.5f), sfB = fmaf(tf.y, 0.5f, 0.5f);
            float soA = fmaf(to.x, 0.5f, 0.5f), soB = fmaf(to.y, 0.5f, 0.5f);

            size_t idxA = (size_t)growA * Hdim + j0 + q;
            size_t idxB = (size_t)growB * Hdim + j0 + q;
            float cnA = sfA * __half2float(g_c[idxA]) + siA * tg.x;
            float cnB = sfB * __half2float(g_c[idxB]) + siB * tg.y;
            g_c[idxA] = __float2half_rn(cnA);
            g_c[idxB] = __float2half_rn(cnB);
            float2 tc = unpack2(tanh2(pack2(cnA, cnB)));
            float hvA = soA * tc.x, hvB = soB * tc.y;
            hsum += hvA + hvB;
            whi[idxA] = __float2half_rn(hvA);
            whi[idxB] = __float2half_rn(hvB);
        }
        // per-(n, column) h sums: this CTA's 128 rows are exactly one n
        float* Sm = (float*)(smem + 67584);   // [32 q][8 warp-slots] = 1KB
        Sm[q * 8 + rb] = hsum;
        __syncthreads();
        if (tid < 32) {
            float s = 0.f;
#pragma unroll
            for (int k2 = 0; k2 < 8; k2++) s += Sm[tid * 8 + k2];
            hmean_out[(row0 >> 7) * Hdim + j0 + tid] = s;   // raw sum; oc scales
        }
    }
}

// ---------------- casts / init --------------------------------------------
__global__ __launch_bounds__(256) void cast_mat(
    const float* __restrict__ src, __half* __restrict__ dst, int n)
{
    int i = blockIdx.x * blockDim.x + threadIdx.x;
    if (i < n) dst[i] = __float2half_rn(src[i]);
}

// gate-permuted cast for W [2048][K]: new_row = (r%512)*4 + r/512
__global__ __launch_bounds__(256) void cast_perm(
    const float* __restrict__ src, __half* __restrict__ dst, int K)
{
    int i = blockIdx.x * blockDim.x + threadIdx.x;   // over 2048*K
    int r = i / K, c = i - r * K;
    int nr = ((r & 511) << 2) + (r >> 9);
    dst[nr * K + c] = __float2half_rn(src[i]);
}

__global__ void bias_combine(const float* __restrict__ b_ih,
                             const float* __restrict__ b_hh)
{
    int i = blockIdx.x * blockDim.x + threadIdx.x;   // < 2048
    int p = ((i & 511) << 2) + (i >> 9);
    g_bias2[p] = b_ih[i] + b_hh[i];
}

__global__ void init_state(const float* __restrict__ h0, const float* __restrict__ c0)
{
    int i = blockIdx.x * blockDim.x + threadIdx.x;   // NV*Hdim grid
    g_c[i]  = __float2half_rn(c0[i]);
    g_h0[i] = __float2half_rn(h0[i]);
}

// ---------------- finalize (block 0) + oc (blocks 1..Nn) -------------------
__global__ __launch_bounds__(256) void finalize_oc(
    const float* __restrict__ gamma_eh, const float* __restrict__ beta_eh,
    const float* __restrict__ oneh_t,
    const float* __restrict__ W_ec, const float* __restrict__ b_ec,
    const float* __restrict__ gamma_ec, const float* __restrict__ beta_ec,
    const float* __restrict__ W_out,
    const float* __restrict__ hmean, const float* __restrict__ W_cls,
    const float* __restrict__ b_cls, float* __restrict__ out, int t)
{
    int tid = threadIdx.x;
    if (blockIdx.x > 0) {
        // ---- oc: (sum_V h / V) @ W_cls^T + b_cls ----
        int n = blockIdx.x - 1;
        int warp = tid >> 5, lane = tid & 31;
        if (warp < ODn) {
            float a = 0.f;
#pragma unroll
            for (int u = 0; u < 16; u++) {
                int k = lane + (u << 5);
                a = fmaf(hmean[n * Hdim + k], W_cls[warp * Hdim + k], a);
            }
            for (int off = 16; off; off >>= 1) a += __shfl_xor_sync(0xffffffffu, a, off);
            if (lane == 0)
                out[PRED_TOTAL + ((size_t)t * Nn + n) * ODn + warp] =
                    a * (1.f / (float)Vn) + b_cls[warp];
        }
        return;
    }

    __shared__ float s_cnt[NCn];
    __shared__ int   s_cls[Nn];
    __shared__ float s_ec[NCn][EHn];
    __shared__ float s_contrib[NCn * ODn];

    {
        float s = 0.f, sq = 0.f;
        for (int b = 0; b < 128; b++) {
            s  += g_psum[b * EHn + tid];
            sq += g_psumsq[b * EHn + tid];
        }
        float m   = s * (1.f / (float)NV);
        float var = sq * (1.f / (float)NV) - m * m;
        float sc  = gamma_eh[tid] * rsqrtf(var + 1e-5f);
        g_bnscale[tid] = sc;
        g_bnshift[tid] = beta_eh[tid] - sc * m;
    }
    if (tid < NCn) {
        float cv = 0.f;
        for (int n = 0; n < Nn; n++) cv += oneh_t[n * NCn + tid];
        s_cnt[tid] = cv;
    }
    if (tid < Nn) {
        const float* r = oneh_t + tid * NCn;
        int cl = 0; float best = r[0];
#pragma unroll
        for (int k = 1; k < NCn; k++) if (r[k] > best) { best = r[k]; cl = k; }
        s_cls[tid] = cl;
    }
    __syncthreads();
    {
        int j = tid;
        float pre[NCn];
        float m = 0.f, sq = 0.f;
#pragma unroll
        for (int cl = 0; cl < NCn; cl++) {
            pre[cl] = W_ec[j * NCn + cl] + b_ec[j];
            float w = s_cnt[cl] * (1.f / (float)Nn);
            m  += w * pre[cl];
            sq += w * pre[cl] * pre[cl];
        }
        float var = sq - m * m;
        float sc  = gamma_ec[j] * rsqrtf(var + 1e-5f);
        float sh  = beta_ec[j] - sc * m;
#pragma unroll
        for (int cl = 0; cl < NCn; cl++)
            s_ec[cl][j] = fmaxf(sc * pre[cl] + sh, 0.f);
    }
    __syncthreads();
    int warp = tid >> 5, lane = tid & 31;
    for (int p = warp; p < NCn * ODn; p += 8) {
        int cl = p / ODn, od = p % ODn;
        float a = 0.f;
#pragma unroll
        for (int u = 0; u < 8; u++) {
            int j = lane + (u << 5);
            a = fmaf(s_ec[cl][j], W_out[od * (EHn + EHn) + EHn + j], a);
        }
        for (int off = 16; off; off >>= 1) a += __shfl_xor_sync(0xffffffffu, a, off);
        if (lane == 0) s_contrib[p] = a;
    }
    __syncthreads();
    if (tid < Nn) {
        int cl = s_cls[tid];
#pragma unroll
        for (int od = 0; od < ODn; od++)
            g_ncontrib[tid * ODn + od] = s_contrib[cl * ODn + od];
    }
}

// ---------------- op: bn+relu(eh) . W_out[:, :256] + ec + b_out + act ------
__global__ __launch_bounds__(256) void op_kernel(
    const float* __restrict__ W_out, const float* __restrict__ b_out,
    float* __restrict__ out, int t)
{
    int warp = threadIdx.x >> 5, lane = threadIdx.x & 31;
    int row  = (blockIdx.x << 3) + warp;
    const __half* er = g_ehpre + (size_t)row * EHn;

    float a0 = 0.f, a1 = 0.f, a2 = 0.f, a3 = 0.f, a4 = 0.f;
#pragma unroll
    for (int u = 0; u < 8; u++) {
        int j = lane + (u << 5);
        float xv = fmaxf(fmaf(g_bnscale[j], __half2float(er[j]), g_bnshift[j]), 0.f);
        a0 = fmaf(xv, W_out[j],            a0);
        a1 = fmaf(xv, W_out[512  + j],     a1);
        a2 = fmaf(xv, W_out[1024 + j],     a2);
        a3 = fmaf(xv, W_out[1536 + j],     a3);
        a4 = fmaf(xv, W_out[2048 + j],     a4);
    }
    for (int off = 16; off; off >>= 1) {
        a0 += __shfl_xor_sync(0xffffffffu, a0, off);
        a1 += __shfl_xor_sync(0xffffffffu, a1, off);
        a2 += __shfl_xor_sync(0xffffffffu, a2, off);
        a3 += __shfl_xor_sync(0xffffffffu, a3, off);
        a4 += __shfl_xor_sync(0xffffffffu, a4, off);
    }
    if (lane < ODn) {
        int n = row >> 7, v = row & 127;
        float a = (lane == 0) ? a0 : (lane == 1) ? a1 : (lane == 2) ? a2
                : (lane == 3) ? a3 : a4;
        a += g_ncontrib[n * ODn + lane] + b_out[lane];
        if (lane == 2 || lane == 3) a = expf(a);
        else if (lane == 4)         a = tanhf(a);
        out[(((size_t)n * Tn + t) * Vn + v) * ODn + lane] = a;
    }
}

// ---------------- streams/events (created at load, before harness checkpoints)
struct StreamRes {
    cudaStream_t s2 = nullptr;
    cudaEvent_t  eG[2] = {nullptr, nullptr};
    cudaEvent_t  eH[2] = {nullptr, nullptr};
    bool ok = false;
    StreamRes() {
        if (cudaStreamCreateWithFlags(&s2, cudaStreamNonBlocking) != cudaSuccess) return;
        for (int i = 0; i < 2; i++) {
            if (cudaEventCreateWithFlags(&eG[i], cudaEventDisableTiming) != cudaSuccess) return;
            if (cudaEventCreateWithFlags(&eH[i], cudaEventDisableTiming) != cudaSuccess) return;
        }
        ok = true;
    }
};
static StreamRes g_sr;

// ---------------- host launcher --------------------------------------------
extern "C" void kernel_launch(void* const* d_in, const int* in_sizes, int n_in,
                              void* d_out, int out_size)
{
    const float* x     = (const float*)d_in[0];
    const float* h0    = (const float*)d_in[1];
    const float* c0    = (const float*)d_in[2];
    const float* oneh  = (const float*)d_in[3];
    const float* W_ih  = (const float*)d_in[4];
    const float* W_hh  = (const float*)d_in[5];
    const float* b_ih  = (const float*)d_in[6];
    const float* b_hh  = (const float*)d_in[7];
    const float* W_cls = (const float*)d_in[8];
    const float* b_cls = (const float*)d_in[9];
    const float* W_eh  = (const float*)d_in[10];
    const float* b_eh  = (const float*)d_in[11];
    const float* ga_eh = (const float*)d_in[12];
    const float* be_eh = (const float*)d_in[13];
    const float* W_ec  = (const float*)d_in[14];
    const float* b_ec  = (const float*)d_in[15];
    const float* ga_ec = (const float*)d_in[16];
    const float* be_ec = (const float*)d_in[17];
    const float* W_out = (const float*)d_in[18];
    const float* b_out = (const float*)d_in[19];
    float* out = (float*)d_out;

    cudaFuncSetAttribute(mma_gemm<0>, cudaFuncAttributeMaxDynamicSharedMemorySize, SMEM_ALL);
    cudaFuncSetAttribute(mma_gemm<1>, cudaFuncAttributeMaxDynamicSharedMemorySize, SMEM_ALL);
    cudaFuncSetAttribute(mma_gemm<2>, cudaFuncAttributeMaxDynamicSharedMemorySize, SMEM_ALL);

    float *bias2;
    float *hmean[2];
    __half *gx, *ehpre;
    __half *xh, *Wih, *Whh, *Weh;
    __half *hbuf[2];
    cudaGetSymbolAddress((void**)&gx,    g_gx);
    cudaGetSymbolAddress((void**)&ehpre, g_ehpre);
    cudaGetSymbolAddress((void**)&bias2, g_bias2);
    cudaGetSymbolAddress((void**)&xh,    g_x);
    cudaGetSymbolAddress((void**)&Wih,   g_Wih);
    cudaGetSymbolAddress((void**)&Whh,   g_Whh);
    cudaGetSymbolAddress((void**)&Weh,   g_Weh);
    cudaGetSymbolAddress((void**)&hbuf[0], g_h0);
    cudaGetSymbolAddress((void**)&hbuf[1], g_h1);
    cudaGetSymbolAddress((void**)&hmean[0], g_hmean0);
    cudaGetSymbolAddress((void**)&hmean[1], g_hmean1);

    // init + operand casts (stream 0)
    init_state<<<(NV * Hdim) / 256, 256>>>(h0, c0);
    cast_mat<<<(NV * Cdim) / 256, 256>>>(x, xh, NV * Cdim);
    cast_perm<<<(G4H * Cdim) / 256, 256>>>(W_ih, Wih, Cdim);
    cast_perm<<<(G4H * Hdim) / 256, 256>>>(W_hh, Whh, Hdim);
    cast_mat<<<(EHn * Hdim) / 256, 256>>>(W_eh, Weh, EHn * Hdim);
    bias_combine<<<G4H / 256, 256>>>(b_ih, b_hh);

    // gx = x @ Wih_perm^T + (b_ih + b_hh)_perm   (step-invariant, fp16 out)
    mma_gemm<0><<<dim3(G4H / 128, NV / 128), 256, SMEM_ALL>>>(
        xh, Wih, gx, bias2, nullptr, nullptr, nullptr, G4H, Cdim);

    const bool dual = g_sr.ok;
    cudaStream_t sH = dual ? g_sr.s2 : (cudaStream_t)0;

    for (int t = 0; t < Tn; t++) {
        const int rb = t & 1, wb = rb ^ 1;

        if (dual && t >= 2) cudaStreamWaitEvent(0, g_sr.eH[t & 1], 0);

        // fused: gates = gx + h @ Whh_perm^T -> LSTM update -> h,c (+ hmean)
        mma_gemm<1><<<dim3(G4H / 128, NV / 128), 256, SMEM_ALL>>>(
            hbuf[rb], Whh, nullptr, nullptr, gx, hbuf[wb], hmean[wb],
            G4H, Hdim);

        if (dual) {
            cudaEventRecord(g_sr.eG[t & 1], 0);
            cudaStreamWaitEvent(sH, g_sr.eG[t & 1], 0);
        }

        // head chain (second stream when available)
        mma_gemm<2><<<dim3(EHn / 128, NV / 128), 256, SMEM_ALL, sH>>>(
            hbuf[wb], Weh, ehpre, b_eh, nullptr, nullptr, nullptr,
            EHn, Hdim);
        finalize_oc<<<1 + Nn, 256, 0, sH>>>(
            ga_eh, be_eh, oneh + (size_t)t * Nn * NCn,
            W_ec, b_ec, ga_ec, be_ec, W_out,
            hmean[wb], W_cls, b_cls, out, t);
        op_kernel<<<NV / 8, 256, 0, sH>>>(W_out, b_out, out, t);

        if (dual) cudaEventRecord(g_sr.eH[t & 1], sH);
    }

    if (dual) {
        cudaStreamWaitEvent(0, g_sr.eH[0], 0);
        cudaStreamWaitEvent(0, g_sr.eH[1], 0);
    }
}